// round 2
// baseline (speedup 1.0000x reference)
#include <cuda_runtime.h>
#include <math.h>

#define BSZ   64
#define SEQ   197
#define CDIM  768
#define NH    12
#define HD    64
#define KEEP  160
#define SCALEF 0.125f   /* 64^-0.5 */

#define BH   (BSZ*NH)     /* 768 */
#define TOK  (BSZ*SEQ)    /* 12608 */

/* scratch (no allocations allowed -> __device__ globals) */
__device__ float g_q[BH*SEQ*HD];
__device__ float g_k[BH*SEQ*HD];
__device__ float g_v[BH*SEQ*HD];
__device__ float g_sc[BH*SEQ*SEQ];   /* raw scaled scores [B,H,N,N] */
__device__ float g_ctx[TOK*CDIM];    /* attention output, [B,N,H*D] */

/* ------------------------------------------------------------------ */
/* K1: qkv = x @ qkv_w^T, scattered into q/k/v [B,H,N,D]              */
/* M=12608 (197 tiles of 64), Nout=2304 (36 tiles of 64), K=768       */
/* ------------------------------------------------------------------ */
__global__ void qkv_gemm_kernel(const float* __restrict__ x,
                                const float* __restrict__ w)
{
    __shared__ float As[16][64];
    __shared__ float Bs[16][64];

    const int m0 = blockIdx.y * 64;
    const int r0 = blockIdx.x * 64;
    const int t  = threadIdx.x;            /* 0..255 */
    const int li = t >> 2;                 /* 0..63  */
    const int lk = (t & 3) * 4;            /* 0,4,8,12 */
    const int ty = t >> 4, tx = t & 15;

    float acc[4][4];
#pragma unroll
    for (int i = 0; i < 4; i++)
#pragma unroll
        for (int j = 0; j < 4; j++) acc[i][j] = 0.f;

    for (int kb = 0; kb < CDIM; kb += 16) {
        float4 av = *reinterpret_cast<const float4*>(&x[(m0 + li) * CDIM + kb + lk]);
        float4 bv = *reinterpret_cast<const float4*>(&w[(r0 + li) * CDIM + kb + lk]);
        As[lk + 0][li] = av.x; As[lk + 1][li] = av.y;
        As[lk + 2][li] = av.z; As[lk + 3][li] = av.w;
        Bs[lk + 0][li] = bv.x; Bs[lk + 1][li] = bv.y;
        Bs[lk + 2][li] = bv.z; Bs[lk + 3][li] = bv.w;
        __syncthreads();
#pragma unroll
        for (int k = 0; k < 16; k++) {
            float a[4], b[4];
#pragma unroll
            for (int i = 0; i < 4; i++) a[i] = As[k][ty * 4 + i];
#pragma unroll
            for (int j = 0; j < 4; j++) b[j] = Bs[k][tx * 4 + j];
#pragma unroll
            for (int i = 0; i < 4; i++)
#pragma unroll
                for (int j = 0; j < 4; j++) acc[i][j] += a[i] * b[j];
        }
        __syncthreads();
    }

    /* scatter: r = s*768 + h*64 + d ; 64-wide tile never crosses s/h */
    const int s  = r0 / CDIM;
    const int hh = (r0 % CDIM) / HD;
    float* dst = (s == 0) ? g_q : (s == 1) ? g_k : g_v;

#pragma unroll
    for (int i = 0; i < 4; i++) {
        const int m = m0 + ty * 4 + i;
        const int b = m / SEQ, n = m % SEQ;
        float* drow = dst + ((size_t)(b * NH + hh) * SEQ + n) * HD;
#pragma unroll
        for (int j = 0; j < 4; j++) {
            const int d = tx * 4 + j;
            drow[d] = acc[i][j];
        }
    }
}

/* ------------------------------------------------------------------ */
/* K2: scores[b,h] = scale * q[b,h] @ k[b,h]^T   (197x197, K=64)      */
/* ------------------------------------------------------------------ */
__global__ void score_gemm_kernel()
{
    __shared__ float As[16][64];
    __shared__ float Bs[16][64];

    const int bh = blockIdx.z;
    const float* q  = g_q + (size_t)bh * SEQ * HD;
    const float* kk = g_k + (size_t)bh * SEQ * HD;
    float* sc = g_sc + (size_t)bh * SEQ * SEQ;

    const int i0 = blockIdx.y * 64;
    const int j0 = blockIdx.x * 64;
    const int t  = threadIdx.x;
    const int li = t >> 2;
    const int lk = (t & 3) * 4;
    const int ty = t >> 4, tx = t & 15;

    float acc[4][4];
#pragma unroll
    for (int i = 0; i < 4; i++)
#pragma unroll
        for (int j = 0; j < 4; j++) acc[i][j] = 0.f;

    for (int kb = 0; kb < HD; kb += 16) {
        float4 av = make_float4(0.f, 0.f, 0.f, 0.f);
        float4 bv = make_float4(0.f, 0.f, 0.f, 0.f);
        if (i0 + li < SEQ) av = *reinterpret_cast<const float4*>(&q [(i0 + li) * HD + kb + lk]);
        if (j0 + li < SEQ) bv = *reinterpret_cast<const float4*>(&kk[(j0 + li) * HD + kb + lk]);
        As[lk + 0][li] = av.x; As[lk + 1][li] = av.y;
        As[lk + 2][li] = av.z; As[lk + 3][li] = av.w;
        Bs[lk + 0][li] = bv.x; Bs[lk + 1][li] = bv.y;
        Bs[lk + 2][li] = bv.z; Bs[lk + 3][li] = bv.w;
        __syncthreads();
#pragma unroll
        for (int k = 0; k < 16; k++) {
            float a[4], b[4];
#pragma unroll
            for (int i = 0; i < 4; i++) a[i] = As[k][ty * 4 + i];
#pragma unroll
            for (int j = 0; j < 4; j++) b[j] = Bs[k][tx * 4 + j];
#pragma unroll
            for (int i = 0; i < 4; i++)
#pragma unroll
                for (int j = 0; j < 4; j++) acc[i][j] += a[i] * b[j];
        }
        __syncthreads();
    }

#pragma unroll
    for (int i = 0; i < 4; i++) {
        const int ii = i0 + ty * 4 + i;
        if (ii >= SEQ) continue;
#pragma unroll
        for (int j = 0; j < 4; j++) {
            const int jj = j0 + tx * 4 + j;
            if (jj < SEQ) sc[ii * SEQ + jj] = acc[i][j] * SCALEF;
        }
    }
}

/* ------------------------------------------------------------------ */
/* K3: weight[b,m] = sum_h |sc[b,h,0,m]|; exact rank-based top-160,   */
/* indices emitted ascending (== sort(top_k indices))                 */
/* ------------------------------------------------------------------ */
__global__ void topk_kernel(float* __restrict__ out_keep, int write_keep)
{
    __shared__ float wt[SEQ];
    __shared__ unsigned char keep[SEQ];
    const int b = blockIdx.x;
    const int t = threadIdx.x;

    if (t < SEQ) {
        float s = 0.f;
        for (int h = 0; h < NH; h++)
            s += fabsf(g_sc[((size_t)(b * NH + h) * SEQ + 0) * SEQ + t]);
        wt[t] = s;
    }
    __syncthreads();
    if (t < SEQ) {
        const float wi = wt[t];
        int cnt = 0;
        for (int j = 0; j < SEQ; j++) {
            const float wj = wt[j];
            cnt += (wj > wi) || (wj == wi && j < t);   /* top_k tiebreak: lower index first */
        }
        keep[t] = (cnt < KEEP) ? 1 : 0;
    }
    __syncthreads();
    if (write_keep && t < SEQ && keep[t]) {
        int pos = 0;
        for (int j = 0; j < t; j++) pos += keep[j];
        out_keep[b * KEEP + pos] = (float)t;
    }
}

/* ------------------------------------------------------------------ */
/* K4: per (b,h): softmax(scores) @ v -> ctx[b,n, h*64+d]             */
/* v tile resident in smem (50.4 KB)                                  */
/* ------------------------------------------------------------------ */
extern __shared__ float s_av[];
__global__ void av_kernel()
{
    const int bh = blockIdx.x;
    const int b = bh / NH, h = bh % NH;
    float* sv  = s_av;                 /* SEQ*HD */
    float* p   = s_av + SEQ * HD;      /* 200    */
    float* red = p + 200;              /* 256    */

    const float* v = g_v + (size_t)bh * SEQ * HD;
    const int t = threadIdx.x;

    const float4* v4  = reinterpret_cast<const float4*>(v);
    float4*       sv4 = reinterpret_cast<float4*>(sv);
    for (int idx = t; idx < SEQ * HD / 4; idx += 256) sv4[idx] = v4[idx];
    __syncthreads();

    const float* scb = g_sc + (size_t)bh * SEQ * SEQ;
    float* ctx = g_ctx + (size_t)(b * SEQ) * CDIM + h * HD;

    const int part = t >> 6;   /* 0..3 */
    const int d    = t & 63;

    for (int n = 0; n < SEQ; n++) {
        const float* row = scb + n * SEQ;
        const float sval = (t < SEQ) ? row[t] : -1e30f;

        red[t] = sval; __syncthreads();
#pragma unroll
        for (int off = 128; off > 0; off >>= 1) {
            if (t < off) red[t] = fmaxf(red[t], red[t + off]);
            __syncthreads();
        }
        const float mx = red[0];
        __syncthreads();

        const float e = (t < SEQ) ? __expf(sval - mx) : 0.f;
        red[t] = e; __syncthreads();
#pragma unroll
        for (int off = 128; off > 0; off >>= 1) {
            if (t < off) red[t] += red[t + off];
            __syncthreads();
        }
        const float inv = 1.f / red[0];
        __syncthreads();
        if (t < SEQ) p[t] = e * inv;
        __syncthreads();

        float acc = 0.f;
        for (int m = part; m < SEQ; m += 4) acc += p[m] * sv[m * HD + d];
        red[t] = acc; __syncthreads();
        if (part == 0)
            ctx[n * CDIM + d] = red[d] + red[64 + d] + red[128 + d] + red[192 + d];
        __syncthreads();
    }
}

/* ------------------------------------------------------------------ */
/* K5: out = ctx @ proj_w^T + proj_b                                  */
/* ------------------------------------------------------------------ */
__global__ void proj_gemm_kernel(const float* __restrict__ w,
                                 const float* __restrict__ bias,
                                 float* __restrict__ out)
{
    __shared__ float As[16][64];
    __shared__ float Bs[16][64];

    const int m0 = blockIdx.y * 64;
    const int c0 = blockIdx.x * 64;
    const int t  = threadIdx.x;
    const int li = t >> 2;
    const int lk = (t & 3) * 4;
    const int ty = t >> 4, tx = t & 15;

    float acc[4][4];
#pragma unroll
    for (int i = 0; i < 4; i++)
#pragma unroll
        for (int j = 0; j < 4; j++) acc[i][j] = 0.f;

    for (int kb = 0; kb < CDIM; kb += 16) {
        float4 av = *reinterpret_cast<const float4*>(&g_ctx[(size_t)(m0 + li) * CDIM + kb + lk]);
        float4 bv = *reinterpret_cast<const float4*>(&w[(c0 + li) * CDIM + kb + lk]);
        As[lk + 0][li] = av.x; As[lk + 1][li] = av.y;
        As[lk + 2][li] = av.z; As[lk + 3][li] = av.w;
        Bs[lk + 0][li] = bv.x; Bs[lk + 1][li] = bv.y;
        Bs[lk + 2][li] = bv.z; Bs[lk + 3][li] = bv.w;
        __syncthreads();
#pragma unroll
        for (int k = 0; k < 16; k++) {
            float a[4], b[4];
#pragma unroll
            for (int i = 0; i < 4; i++) a[i] = As[k][ty * 4 + i];
#pragma unroll
            for (int j = 0; j < 4; j++) b[j] = Bs[k][tx * 4 + j];
#pragma unroll
            for (int i = 0; i < 4; i++)
#pragma unroll
                for (int j = 0; j < 4; j++) acc[i][j] += a[i] * b[j];
        }
        __syncthreads();
    }

#pragma unroll
    for (int i = 0; i < 4; i++) {
        const int m = m0 + ty * 4 + i;
#pragma unroll
        for (int j = 0; j < 4; j++) {
            const int c = c0 + tx * 4 + j;
            out[(size_t)m * CDIM + c] = acc[i][j] + bias[c];
        }
    }
}

/* ------------------------------------------------------------------ */
extern "C" void kernel_launch(void* const* d_in, const int* in_sizes, int n_in,
                              void* d_out, int out_size)
{
    const float* x      = (const float*)d_in[0];
    const float* qkv_w  = (const float*)d_in[1];
    const float* proj_w = (const float*)d_in[2];
    const float* proj_b = (const float*)d_in[3];
    float* out = (float*)d_out;

    const int av_smem = (SEQ * HD + 200 + 256) * (int)sizeof(float); /* ~52.3 KB */
    cudaFuncSetAttribute(av_kernel, cudaFuncAttributeMaxDynamicSharedMemorySize, av_smem);

    qkv_gemm_kernel<<<dim3(36, 197), 256>>>(x, qkv_w);
    score_gemm_kernel<<<dim3(4, 4, BH), 256>>>();

    const int write_keep = (out_size >= TOK * CDIM + BSZ * KEEP) ? 1 : 0;
    topk_kernel<<<BSZ, 256>>>(out + (size_t)TOK * CDIM, write_keep);

    av_kernel<<<BH, 256, av_smem>>>();
    proj_gemm_kernel<<<dim3(12, 197), 256>>>(proj_w, proj_b, out);
}

// round 3
// speedup vs baseline: 1.3018x; 1.3018x over previous
#include <cuda_runtime.h>
#include <math.h>

#define BSZ   64
#define SEQ   197
#define CDIM  768
#define NH    12
#define HD    64
#define KEEP  160
#define SCALEF 0.125f   /* 64^-0.5 */

#define BH   (BSZ*NH)     /* 768 */
#define TOK  (BSZ*SEQ)    /* 12608 */

#define AV_ROWS 64
#define SPITCH  200       /* padded P row stride */

/* scratch (no allocations allowed -> __device__ globals) */
__device__ float g_q[BH*SEQ*HD];
__device__ float g_k[BH*SEQ*HD];
__device__ float g_v[BH*SEQ*HD];
__device__ float g_sc[BH*SEQ*SEQ];   /* raw scaled scores [B,H,N,N] */
__device__ float g_ctx[TOK*CDIM];    /* attention output, [B,N,H*D] */

/* ------------------------------------------------------------------ */
/* K1: qkv = x @ qkv_w^T, scattered into q/k/v [B,H,N,D]              */
/* ------------------------------------------------------------------ */
__global__ void qkv_gemm_kernel(const float* __restrict__ x,
                                const float* __restrict__ w)
{
    __shared__ float As[16][64];
    __shared__ float Bs[16][64];

    const int m0 = blockIdx.y * 64;
    const int r0 = blockIdx.x * 64;
    const int t  = threadIdx.x;            /* 0..255 */
    const int li = t >> 2;                 /* 0..63  */
    const int lk = (t & 3) * 4;            /* 0,4,8,12 */
    const int ty = t >> 4, tx = t & 15;

    float acc[4][4];
#pragma unroll
    for (int i = 0; i < 4; i++)
#pragma unroll
        for (int j = 0; j < 4; j++) acc[i][j] = 0.f;

    for (int kb = 0; kb < CDIM; kb += 16) {
        float4 av = *reinterpret_cast<const float4*>(&x[(m0 + li) * CDIM + kb + lk]);
        float4 bv = *reinterpret_cast<const float4*>(&w[(r0 + li) * CDIM + kb + lk]);
        As[lk + 0][li] = av.x; As[lk + 1][li] = av.y;
        As[lk + 2][li] = av.z; As[lk + 3][li] = av.w;
        Bs[lk + 0][li] = bv.x; Bs[lk + 1][li] = bv.y;
        Bs[lk + 2][li] = bv.z; Bs[lk + 3][li] = bv.w;
        __syncthreads();
#pragma unroll
        for (int k = 0; k < 16; k++) {
            float a[4], b[4];
#pragma unroll
            for (int i = 0; i < 4; i++) a[i] = As[k][ty * 4 + i];
#pragma unroll
            for (int j = 0; j < 4; j++) b[j] = Bs[k][tx * 4 + j];
#pragma unroll
            for (int i = 0; i < 4; i++)
#pragma unroll
                for (int j = 0; j < 4; j++) acc[i][j] += a[i] * b[j];
        }
        __syncthreads();
    }

    /* scatter: r = s*768 + h*64 + d ; 64-wide tile never crosses s/h */
    const int s  = r0 / CDIM;
    const int hh = (r0 % CDIM) / HD;
    float* dst = (s == 0) ? g_q : (s == 1) ? g_k : g_v;

#pragma unroll
    for (int i = 0; i < 4; i++) {
        const int m = m0 + ty * 4 + i;
        const int b = m / SEQ, n = m % SEQ;
        float* drow = dst + ((size_t)(b * NH + hh) * SEQ + n) * HD;
#pragma unroll
        for (int j = 0; j < 4; j++) {
            const int d = tx * 4 + j;
            drow[d] = acc[i][j];
        }
    }
}

/* ------------------------------------------------------------------ */
/* K2: scores[b,h] = scale * q[b,h] @ k[b,h]^T   (197x197, K=64)      */
/* ------------------------------------------------------------------ */
__global__ void score_gemm_kernel()
{
    __shared__ float As[16][64];
    __shared__ float Bs[16][64];

    const int bh = blockIdx.z;
    const float* q  = g_q + (size_t)bh * SEQ * HD;
    const float* kk = g_k + (size_t)bh * SEQ * HD;
    float* sc = g_sc + (size_t)bh * SEQ * SEQ;

    const int i0 = blockIdx.y * 64;
    const int j0 = blockIdx.x * 64;
    const int t  = threadIdx.x;
    const int li = t >> 2;
    const int lk = (t & 3) * 4;
    const int ty = t >> 4, tx = t & 15;

    float acc[4][4];
#pragma unroll
    for (int i = 0; i < 4; i++)
#pragma unroll
        for (int j = 0; j < 4; j++) acc[i][j] = 0.f;

    for (int kb = 0; kb < HD; kb += 16) {
        float4 av = make_float4(0.f, 0.f, 0.f, 0.f);
        float4 bv = make_float4(0.f, 0.f, 0.f, 0.f);
        if (i0 + li < SEQ) av = *reinterpret_cast<const float4*>(&q [(i0 + li) * HD + kb + lk]);
        if (j0 + li < SEQ) bv = *reinterpret_cast<const float4*>(&kk[(j0 + li) * HD + kb + lk]);
        As[lk + 0][li] = av.x; As[lk + 1][li] = av.y;
        As[lk + 2][li] = av.z; As[lk + 3][li] = av.w;
        Bs[lk + 0][li] = bv.x; Bs[lk + 1][li] = bv.y;
        Bs[lk + 2][li] = bv.z; Bs[lk + 3][li] = bv.w;
        __syncthreads();
#pragma unroll
        for (int k = 0; k < 16; k++) {
            float a[4], b[4];
#pragma unroll
            for (int i = 0; i < 4; i++) a[i] = As[k][ty * 4 + i];
#pragma unroll
            for (int j = 0; j < 4; j++) b[j] = Bs[k][tx * 4 + j];
#pragma unroll
            for (int i = 0; i < 4; i++)
#pragma unroll
                for (int j = 0; j < 4; j++) acc[i][j] += a[i] * b[j];
        }
        __syncthreads();
    }

#pragma unroll
    for (int i = 0; i < 4; i++) {
        const int ii = i0 + ty * 4 + i;
        if (ii >= SEQ) continue;
#pragma unroll
        for (int j = 0; j < 4; j++) {
            const int jj = j0 + tx * 4 + j;
            if (jj < SEQ) sc[ii * SEQ + jj] = acc[i][j] * SCALEF;
        }
    }
}

/* ------------------------------------------------------------------ */
/* K3: weight[b,m] = sum_h |sc[b,h,0,m]|; exact rank-based top-160    */
/* ------------------------------------------------------------------ */
__global__ void topk_kernel(float* __restrict__ out_keep, int write_keep)
{
    __shared__ float wt[SEQ];
    __shared__ unsigned char keep[SEQ];
    const int b = blockIdx.x;
    const int t = threadIdx.x;

    if (t < SEQ) {
        float s = 0.f;
        for (int h = 0; h < NH; h++)
            s += fabsf(g_sc[((size_t)(b * NH + h) * SEQ + 0) * SEQ + t]);
        wt[t] = s;
    }
    __syncthreads();
    if (t < SEQ) {
        const float wi = wt[t];
        int cnt = 0;
        for (int j = 0; j < SEQ; j++) {
            const float wj = wt[j];
            cnt += (wj > wi) || (wj == wi && j < t);
        }
        keep[t] = (cnt < KEEP) ? 1 : 0;
    }
    __syncthreads();
    if (write_keep && t < SEQ && keep[t]) {
        int pos = 0;
        for (int j = 0; j < t; j++) pos += keep[j];
        out_keep[b * KEEP + pos] = (float)t;
    }
}

/* ------------------------------------------------------------------ */
/* K4 (NEW): per (b,h, 64-row tile): warp-shuffle softmax -> P in smem */
/* then register-tiled P(64x197) @ V(197x64)                          */
/* ------------------------------------------------------------------ */
__global__ __launch_bounds__(256, 2) void av_kernel2()
{
    extern __shared__ float sm[];
    float* sV = sm;                 /* SEQ*HD    = 12608 floats */
    float* sS = sm + SEQ * HD;      /* 64*SPITCH = 12800 floats */

    const int bh   = blockIdx.x;
    const int b    = bh / NH, h = bh % NH;
    const int row0 = blockIdx.y * AV_ROWS;
    const int t    = threadIdx.x;
    const int lane = t & 31;
    const int w    = t >> 5;        /* 8 warps */

    /* stage V */
    const float4* v4  = reinterpret_cast<const float4*>(g_v + (size_t)bh * SEQ * HD);
    float4*       sV4 = reinterpret_cast<float4*>(sV);
    for (int i = t; i < SEQ * HD / 4; i += 256) sV4[i] = v4[i];

    /* softmax: warp w handles rows w*8 .. w*8+7 of this tile */
    const float* scb = g_sc + (size_t)bh * SEQ * SEQ;
#pragma unroll
    for (int r8 = 0; r8 < 8; r8++) {
        const int sr = w * 8 + r8;          /* row within tile */
        const int r  = row0 + sr;           /* global n        */
        if (r < SEQ) {
            const float* row = scb + (size_t)r * SEQ;
            float vals[7];
            float mx = -1e30f;
#pragma unroll
            for (int i = 0; i < 7; i++) {
                const int m = lane + i * 32;
                vals[i] = (m < SEQ) ? row[m] : -1e30f;
                mx = fmaxf(mx, vals[i]);
            }
#pragma unroll
            for (int off = 16; off > 0; off >>= 1)
                mx = fmaxf(mx, __shfl_xor_sync(0xffffffffu, mx, off));
            float s = 0.f;
#pragma unroll
            for (int i = 0; i < 7; i++) {
                const int m = lane + i * 32;
                const float e = (m < SEQ) ? __expf(vals[i] - mx) : 0.f;
                vals[i] = e;
                s += e;
            }
#pragma unroll
            for (int off = 16; off > 0; off >>= 1)
                s += __shfl_xor_sync(0xffffffffu, s, off);
            const float inv = 1.f / s;
#pragma unroll
            for (int i = 0; i < 7; i++) {
                const int m = lane + i * 32;
                if (m < SEQ) sS[sr * SPITCH + m] = vals[i] * inv;
            }
        } else {
            /* pad rows: zero so PV reads are benign */
#pragma unroll
            for (int i = 0; i < 7; i++) {
                const int m = lane + i * 32;
                if (m < SEQ) sS[sr * SPITCH + m] = 0.f;
            }
        }
    }
    __syncthreads();

    /* PV: 16x16 thread grid, each thread 4 rows x 4 cols */
    const int tx = t & 15, ty = t >> 4;
    float acc[4][4];
#pragma unroll
    for (int i = 0; i < 4; i++)
#pragma unroll
        for (int j = 0; j < 4; j++) acc[i][j] = 0.f;

#pragma unroll 4
    for (int m = 0; m < SEQ; m++) {
        const float4 vv = *reinterpret_cast<const float4*>(&sV[m * HD + tx * 4]);
        float p[4];
#pragma unroll
        for (int i = 0; i < 4; i++) p[i] = sS[(ty * 4 + i) * SPITCH + m];
#pragma unroll
        for (int i = 0; i < 4; i++) {
            acc[i][0] += p[i] * vv.x;
            acc[i][1] += p[i] * vv.y;
            acc[i][2] += p[i] * vv.z;
            acc[i][3] += p[i] * vv.w;
        }
    }

    float* ctx = g_ctx + (size_t)(b * SEQ) * CDIM + h * HD;
#pragma unroll
    for (int i = 0; i < 4; i++) {
        const int r = row0 + ty * 4 + i;
        if (r < SEQ) {
            float4 o = make_float4(acc[i][0], acc[i][1], acc[i][2], acc[i][3]);
            *reinterpret_cast<float4*>(&ctx[(size_t)r * CDIM + tx * 4]) = o;
        }
    }
}

/* ------------------------------------------------------------------ */
/* K5: out = ctx @ proj_w^T + proj_b                                  */
/* ------------------------------------------------------------------ */
__global__ void proj_gemm_kernel(const float* __restrict__ w,
                                 const float* __restrict__ bias,
                                 float* __restrict__ out)
{
    __shared__ float As[16][64];
    __shared__ float Bs[16][64];

    const int m0 = blockIdx.y * 64;
    const int c0 = blockIdx.x * 64;
    const int t  = threadIdx.x;
    const int li = t >> 2;
    const int lk = (t & 3) * 4;
    const int ty = t >> 4, tx = t & 15;

    float acc[4][4];
#pragma unroll
    for (int i = 0; i < 4; i++)
#pragma unroll
        for (int j = 0; j < 4; j++) acc[i][j] = 0.f;

    for (int kb = 0; kb < CDIM; kb += 16) {
        float4 av = *reinterpret_cast<const float4*>(&g_ctx[(size_t)(m0 + li) * CDIM + kb + lk]);
        float4 bv = *reinterpret_cast<const float4*>(&w[(c0 + li) * CDIM + kb + lk]);
        As[lk + 0][li] = av.x; As[lk + 1][li] = av.y;
        As[lk + 2][li] = av.z; As[lk + 3][li] = av.w;
        Bs[lk + 0][li] = bv.x; Bs[lk + 1][li] = bv.y;
        Bs[lk + 2][li] = bv.z; Bs[lk + 3][li] = bv.w;
        __syncthreads();
#pragma unroll
        for (int k = 0; k < 16; k++) {
            float a[4], b[4];
#pragma unroll
            for (int i = 0; i < 4; i++) a[i] = As[k][ty * 4 + i];
#pragma unroll
            for (int j = 0; j < 4; j++) b[j] = Bs[k][tx * 4 + j];
#pragma unroll
            for (int i = 0; i < 4; i++)
#pragma unroll
                for (int j = 0; j < 4; j++) acc[i][j] += a[i] * b[j];
        }
        __syncthreads();
    }

#pragma unroll
    for (int i = 0; i < 4; i++) {
        const int m = m0 + ty * 4 + i;
#pragma unroll
        for (int j = 0; j < 4; j++) {
            const int c = c0 + tx * 4 + j;
            out[(size_t)m * CDIM + c] = acc[i][j] + bias[c];
        }
    }
}

/* ------------------------------------------------------------------ */
extern "C" void kernel_launch(void* const* d_in, const int* in_sizes, int n_in,
                              void* d_out, int out_size)
{
    const float* x      = (const float*)d_in[0];
    const float* qkv_w  = (const float*)d_in[1];
    const float* proj_w = (const float*)d_in[2];
    const float* proj_b = (const float*)d_in[3];
    float* out = (float*)d_out;

    const int av_smem = (SEQ * HD + AV_ROWS * SPITCH) * (int)sizeof(float); /* ~99.3 KB */
    cudaFuncSetAttribute(av_kernel2, cudaFuncAttributeMaxDynamicSharedMemorySize, av_smem);

    qkv_gemm_kernel<<<dim3(36, 197), 256>>>(x, qkv_w);
    score_gemm_kernel<<<dim3(4, 4, BH), 256>>>();

    const int write_keep = (out_size >= TOK * CDIM + BSZ * KEEP) ? 1 : 0;
    topk_kernel<<<BSZ, 256>>>(out + (size_t)TOK * CDIM, write_keep);

    av_kernel2<<<dim3(BH, 4), 256, av_smem>>>();
    proj_gemm_kernel<<<dim3(12, 197), 256>>>(proj_w, proj_b, out);
}

// round 5
// speedup vs baseline: 1.8436x; 1.4162x over previous
#include <cuda_runtime.h>
#include <cuda_bf16.h>
#include <math.h>
#include <stdint.h>

#define BSZ   64
#define SEQ   197
#define CDIM  768
#define NH    12
#define HD    64
#define KEEP  160
#define SCALEF 0.125f

#define BH   (BSZ*NH)
#define TOK  (BSZ*SEQ)

#define AV_ROWS 64
#define SPITCH  200

/* ---------------- scratch (device globals; no allocs allowed) ------ */
__device__ float g_q[BH*SEQ*HD];
__device__ float g_k[BH*SEQ*HD];
__device__ float g_v[BH*SEQ*HD];
__device__ float g_sc[BH*SEQ*SEQ];
__device__ float g_ctx[TOK*CDIM];

__device__ __nv_bfloat16 g_xh[TOK*CDIM],  g_xl[TOK*CDIM];
__device__ __nv_bfloat16 g_wqh[3*CDIM*CDIM], g_wql[3*CDIM*CDIM];
__device__ __nv_bfloat16 g_wph[CDIM*CDIM],   g_wpl[CDIM*CDIM];
__device__ __nv_bfloat16 g_cth[TOK*CDIM], g_ctl[TOK*CDIM];

/* ---------------- split fp32 -> bf16 hi/lo ------------------------- */
__global__ void split_kernel(const float* __restrict__ src, int which, int n)
{
    int i = blockIdx.x * 256 + threadIdx.x;
    if (i >= n) return;
    __nv_bfloat16 *hi, *lo;
    const float* s = src;
    if      (which == 0) { hi = g_xh;  lo = g_xl;  }
    else if (which == 1) { hi = g_wqh; lo = g_wql; }
    else if (which == 2) { hi = g_wph; lo = g_wpl; }
    else                 { hi = g_cth; lo = g_ctl; s = g_ctx; }
    float v = s[i];
    __nv_bfloat16 h = __float2bfloat16(v);
    hi[i] = h;
    lo[i] = __float2bfloat16(v - __bfloat162float(h));
}

/* ---------------- HMMA split-bf16 GEMM: out = A @ B^T -------------- */
/* mma.sync.aligned.m16n8k16 bf16 (portable ISA -> compiles at
   compute_103; tcgen05 is rejected by this toolchain's PTX target).   */
#define MT 128
#define NT 128
#define KPAN 32
#define SPAD 40   /* bf16 row stride: 80B, 16B-aligned, conflict-free */

__device__ __forceinline__ void mma16816(float* c, const uint32_t* a,
                                         uint32_t b0, uint32_t b1)
{
    asm volatile(
        "mma.sync.aligned.m16n8k16.row.col.f32.bf16.bf16.f32 "
        "{%0,%1,%2,%3}, {%4,%5,%6,%7}, {%8,%9}, {%0,%1,%2,%3};"
        : "+f"(c[0]), "+f"(c[1]), "+f"(c[2]), "+f"(c[3])
        : "r"(a[0]), "r"(a[1]), "r"(a[2]), "r"(a[3]), "r"(b0), "r"(b1));
}

__device__ __forceinline__ void stage_tile(__nv_bfloat16* s,
        const __nv_bfloat16* __restrict__ g, int row0, int rowmax, int kb, int t)
{
#pragma unroll
    for (int i = 0; i < 2; i++) {
        const int idx = t + i * 256;
        const int row = idx >> 2;
        const int c8  = (idx & 3) * 8;
        int gr = row0 + row; if (gr > rowmax) gr = rowmax;
        uint4 v = *reinterpret_cast<const uint4*>(g + (size_t)gr * CDIM + kb + c8);
        *reinterpret_cast<uint4*>(s + row * SPAD + c8) = v;
    }
}

__global__ __launch_bounds__(256, 2) void hmma_gemm(int mode,
        const float* __restrict__ bias, float* __restrict__ outp)
{
    __shared__ __align__(16) __nv_bfloat16 sAh[128*SPAD];
    __shared__ __align__(16) __nv_bfloat16 sAl[128*SPAD];
    __shared__ __align__(16) __nv_bfloat16 sBh[128*SPAD];
    __shared__ __align__(16) __nv_bfloat16 sBl[128*SPAD];

    const int t    = threadIdx.x;
    const int wid  = t >> 5, lane = t & 31;
    const int gq   = lane >> 2, tig = lane & 3;
    const int wm   = (wid & 3) * 32;
    const int wn   = (wid >> 2) * 64;
    const int m0   = blockIdx.y * MT;
    const int n0   = blockIdx.x * NT;

    const __nv_bfloat16 *Ah, *Al, *Bh, *Bl;
    if (mode == 0) { Ah = g_xh;  Al = g_xl;  Bh = g_wqh; Bl = g_wql; }
    else           { Ah = g_cth; Al = g_ctl; Bh = g_wph; Bl = g_wpl; }

    float acc[2][8][4];
#pragma unroll
    for (int mi = 0; mi < 2; mi++)
#pragma unroll
        for (int ni = 0; ni < 8; ni++)
#pragma unroll
            for (int r = 0; r < 4; r++) acc[mi][ni][r] = 0.f;

    for (int p = 0; p < CDIM / KPAN; p++) {
        const int kb = p * KPAN;
        stage_tile(sAh, Ah, m0, TOK - 1, kb, t);
        stage_tile(sAl, Al, m0, TOK - 1, kb, t);
        stage_tile(sBh, Bh, n0, 1 << 30, kb, t);   /* B dims exact */
        stage_tile(sBl, Bl, n0, 1 << 30, kb, t);
        __syncthreads();

#pragma unroll
        for (int ks = 0; ks < 2; ks++) {
            const int ko = ks * 16;
            uint32_t ah[2][4], al[2][4];
#pragma unroll
            for (int mi = 0; mi < 2; mi++) {
                const int r = wm + mi * 16 + gq;
                ah[mi][0] = *reinterpret_cast<const uint32_t*>(&sAh[(r    ) * SPAD + ko     + 2*tig]);
                ah[mi][1] = *reinterpret_cast<const uint32_t*>(&sAh[(r + 8) * SPAD + ko     + 2*tig]);
                ah[mi][2] = *reinterpret_cast<const uint32_t*>(&sAh[(r    ) * SPAD + ko + 8 + 2*tig]);
                ah[mi][3] = *reinterpret_cast<const uint32_t*>(&sAh[(r + 8) * SPAD + ko + 8 + 2*tig]);
                al[mi][0] = *reinterpret_cast<const uint32_t*>(&sAl[(r    ) * SPAD + ko     + 2*tig]);
                al[mi][1] = *reinterpret_cast<const uint32_t*>(&sAl[(r + 8) * SPAD + ko     + 2*tig]);
                al[mi][2] = *reinterpret_cast<const uint32_t*>(&sAl[(r    ) * SPAD + ko + 8 + 2*tig]);
                al[mi][3] = *reinterpret_cast<const uint32_t*>(&sAl[(r + 8) * SPAD + ko + 8 + 2*tig]);
            }
#pragma unroll
            for (int ni = 0; ni < 8; ni++) {
                const int c = wn + ni * 8 + gq;
                const uint32_t bh0 = *reinterpret_cast<const uint32_t*>(&sBh[c * SPAD + ko     + 2*tig]);
                const uint32_t bh1 = *reinterpret_cast<const uint32_t*>(&sBh[c * SPAD + ko + 8 + 2*tig]);
                const uint32_t bl0 = *reinterpret_cast<const uint32_t*>(&sBl[c * SPAD + ko     + 2*tig]);
                const uint32_t bl1 = *reinterpret_cast<const uint32_t*>(&sBl[c * SPAD + ko + 8 + 2*tig]);
#pragma unroll
                for (int mi = 0; mi < 2; mi++) {
                    mma16816(acc[mi][ni], ah[mi], bh0, bh1);
                    mma16816(acc[mi][ni], ah[mi], bl0, bl1);
                    mma16816(acc[mi][ni], al[mi], bh0, bh1);
                }
            }
        }
        __syncthreads();
    }

    /* epilogue: thread holds rows {gq, gq+8} x cols {2*tig, 2*tig+1} per tile */
#pragma unroll
    for (int mi = 0; mi < 2; mi++) {
#pragma unroll
        for (int h2 = 0; h2 < 2; h2++) {
            const int m = m0 + wm + mi * 16 + gq + h2 * 8;
            if (m >= TOK) continue;
#pragma unroll
            for (int ni = 0; ni < 8; ni++) {
                const int col = n0 + wn + ni * 8 + 2 * tig;
                const float v0 = acc[mi][ni][h2 * 2 + 0];
                const float v1 = acc[mi][ni][h2 * 2 + 1];
                if (mode == 1) {
                    float2 o = make_float2(v0 + bias[col], v1 + bias[col + 1]);
                    *reinterpret_cast<float2*>(&outp[(size_t)m * CDIM + col]) = o;
                } else {
                    const int s  = col / CDIM;
                    const int rm = col % CDIM;
                    const int h  = rm / HD, dd = rm % HD;
                    float* dst = (s == 0) ? g_q : (s == 1) ? g_k : g_v;
                    const int bidx = m / SEQ, n = m % SEQ;
                    float2 o = make_float2(v0, v1);
                    *reinterpret_cast<float2*>(
                        &dst[((size_t)(bidx * NH + h) * SEQ + n) * HD + dd]) = o;
                }
            }
        }
    }
}

/* ---------------- exact fp32 top-k via u = Wk^T (Wq x_cls) --------- */
__global__ __launch_bounds__(256) void topk_fused(const float* __restrict__ x,
                                                  const float* __restrict__ w,
                                                  float* __restrict__ out_keep,
                                                  int write_keep)
{
    __shared__ float xc[CDIM];
    __shared__ float qc[CDIM];
    __shared__ float u[NH * CDIM];
    __shared__ float wt[SEQ];
    __shared__ unsigned char keep[SEQ];

    const int b = blockIdx.x, t = threadIdx.x;

    for (int i = t; i < CDIM; i += 256) xc[i] = x[(size_t)(b * SEQ) * CDIM + i];
    __syncthreads();
    for (int j = t; j < CDIM; j += 256) {
        const float* wr = w + (size_t)j * CDIM;
        float s = 0.f;
        for (int c = 0; c < CDIM; c++) s += wr[c] * xc[c];
        qc[j] = s;
    }
    __syncthreads();
    for (int idx = t; idx < NH * CDIM; idx += 256) {
        const int h = idx / CDIM, c = idx % CDIM;
        const float* wk = w + (size_t)(CDIM + h * HD) * CDIM + c;
        const float* q  = qc + h * HD;
        float s = 0.f;
#pragma unroll 8
        for (int d = 0; d < HD; d++) s += wk[(size_t)d * CDIM] * q[d];
        u[idx] = s;
    }
    __syncthreads();
    if (t < SEQ) {
        const float* xr = x + (size_t)(b * SEQ + t) * CDIM;
        float acc[NH];
#pragma unroll
        for (int h = 0; h < NH; h++) acc[h] = 0.f;
        for (int c = 0; c < CDIM; c++) {
            const float xv = xr[c];
#pragma unroll
            for (int h = 0; h < NH; h++) acc[h] += u[h * CDIM + c] * xv;
        }
        float s = 0.f;
#pragma unroll
        for (int h = 0; h < NH; h++) s += fabsf(acc[h]);
        wt[t] = s;
    }
    __syncthreads();
    if (t < SEQ) {
        const float wi = wt[t];
        int cnt = 0;
        for (int j = 0; j < SEQ; j++) {
            const float wj = wt[j];
            cnt += (wj > wi) || (wj == wi && j < t);
        }
        keep[t] = (cnt < KEEP) ? 1 : 0;
    }
    __syncthreads();
    if (write_keep && t < SEQ && keep[t]) {
        int pos = 0;
        for (int j = 0; j < t; j++) pos += keep[j];
        out_keep[b * KEEP + pos] = (float)t;
    }
}

/* ---------------- K2: scores (fp32 SIMT) --------------------------- */
__global__ void score_gemm_kernel()
{
    __shared__ float As[16][64];
    __shared__ float Bs[16][64];

    const int bh = blockIdx.z;
    const float* q  = g_q + (size_t)bh * SEQ * HD;
    const float* kk = g_k + (size_t)bh * SEQ * HD;
    float* sc = g_sc + (size_t)bh * SEQ * SEQ;

    const int i0 = blockIdx.y * 64;
    const int j0 = blockIdx.x * 64;
    const int t  = threadIdx.x;
    const int li = t >> 2;
    const int lk = (t & 3) * 4;
    const int ty = t >> 4, tx = t & 15;

    float acc[4][4];
#pragma unroll
    for (int i = 0; i < 4; i++)
#pragma unroll
        for (int j = 0; j < 4; j++) acc[i][j] = 0.f;

    for (int kb = 0; kb < HD; kb += 16) {
        float4 av = make_float4(0.f, 0.f, 0.f, 0.f);
        float4 bv = make_float4(0.f, 0.f, 0.f, 0.f);
        if (i0 + li < SEQ) av = *reinterpret_cast<const float4*>(&q [(i0 + li) * HD + kb + lk]);
        if (j0 + li < SEQ) bv = *reinterpret_cast<const float4*>(&kk[(j0 + li) * HD + kb + lk]);
        As[lk + 0][li] = av.x; As[lk + 1][li] = av.y;
        As[lk + 2][li] = av.z; As[lk + 3][li] = av.w;
        Bs[lk + 0][li] = bv.x; Bs[lk + 1][li] = bv.y;
        Bs[lk + 2][li] = bv.z; Bs[lk + 3][li] = bv.w;
        __syncthreads();
#pragma unroll
        for (int k = 0; k < 16; k++) {
            float a[4], b[4];
#pragma unroll
            for (int i = 0; i < 4; i++) a[i] = As[k][ty * 4 + i];
#pragma unroll
            for (int j = 0; j < 4; j++) b[j] = Bs[k][tx * 4 + j];
#pragma unroll
            for (int i = 0; i < 4; i++)
#pragma unroll
                for (int j = 0; j < 4; j++) acc[i][j] += a[i] * b[j];
        }
        __syncthreads();
    }

#pragma unroll
    for (int i = 0; i < 4; i++) {
        const int ii = i0 + ty * 4 + i;
        if (ii >= SEQ) continue;
#pragma unroll
        for (int j = 0; j < 4; j++) {
            const int jj = j0 + tx * 4 + j;
            if (jj < SEQ) sc[ii * SEQ + jj] = acc[i][j] * SCALEF;
        }
    }
}

/* ---------------- K4: softmax + AV --------------------------------- */
__global__ __launch_bounds__(256, 2) void av_kernel2()
{
    extern __shared__ float smf[];
    float* sV = smf;
    float* sS = smf + SEQ * HD;

    const int bh   = blockIdx.x;
    const int b    = bh / NH, h = bh % NH;
    const int row0 = blockIdx.y * AV_ROWS;
    const int t    = threadIdx.x;
    const int lane = t & 31;
    const int w    = t >> 5;

    const float4* v4  = reinterpret_cast<const float4*>(g_v + (size_t)bh * SEQ * HD);
    float4*       sV4 = reinterpret_cast<float4*>(sV);
    for (int i = t; i < SEQ * HD / 4; i += 256) sV4[i] = v4[i];

    const float* scb = g_sc + (size_t)bh * SEQ * SEQ;
#pragma unroll
    for (int r8 = 0; r8 < 8; r8++) {
        const int sr = w * 8 + r8;
        const int r  = row0 + sr;
        if (r < SEQ) {
            const float* row = scb + (size_t)r * SEQ;
            float vals[7];
            float mx = -1e30f;
#pragma unroll
            for (int i = 0; i < 7; i++) {
                const int m = lane + i * 32;
                vals[i] = (m < SEQ) ? row[m] : -1e30f;
                mx = fmaxf(mx, vals[i]);
            }
#pragma unroll
            for (int off = 16; off > 0; off >>= 1)
                mx = fmaxf(mx, __shfl_xor_sync(0xffffffffu, mx, off));
            float s = 0.f;
#pragma unroll
            for (int i = 0; i < 7; i++) {
                const int m = lane + i * 32;
                const float e = (m < SEQ) ? __expf(vals[i] - mx) : 0.f;
                vals[i] = e;
                s += e;
            }
#pragma unroll
            for (int off = 16; off > 0; off >>= 1)
                s += __shfl_xor_sync(0xffffffffu, s, off);
            const float inv = 1.f / s;
#pragma unroll
            for (int i = 0; i < 7; i++) {
                const int m = lane + i * 32;
                if (m < SEQ) sS[sr * SPITCH + m] = vals[i] * inv;
            }
        } else {
#pragma unroll
            for (int i = 0; i < 7; i++) {
                const int m = lane + i * 32;
                if (m < SEQ) sS[sr * SPITCH + m] = 0.f;
            }
        }
    }
    __syncthreads();

    const int tx = t & 15, ty = t >> 4;
    float acc[4][4];
#pragma unroll
    for (int i = 0; i < 4; i++)
#pragma unroll
        for (int j = 0; j < 4; j++) acc[i][j] = 0.f;

#pragma unroll 4
    for (int m = 0; m < SEQ; m++) {
        const float4 vv = *reinterpret_cast<const float4*>(&sV[m * HD + tx * 4]);
        float p[4];
#pragma unroll
        for (int i = 0; i < 4; i++) p[i] = sS[(ty * 4 + i) * SPITCH + m];
#pragma unroll
        for (int i = 0; i < 4; i++) {
            acc[i][0] += p[i] * vv.x;
            acc[i][1] += p[i] * vv.y;
            acc[i][2] += p[i] * vv.z;
            acc[i][3] += p[i] * vv.w;
        }
    }

    float* ctx = g_ctx + (size_t)(b * SEQ) * CDIM + h * HD;
#pragma unroll
    for (int i = 0; i < 4; i++) {
        const int r = row0 + ty * 4 + i;
        if (r < SEQ) {
            float4 o = make_float4(acc[i][0], acc[i][1], acc[i][2], acc[i][3]);
            *reinterpret_cast<float4*>(&ctx[(size_t)r * CDIM + tx * 4]) = o;
        }
    }
}

/* ------------------------------------------------------------------ */
extern "C" void kernel_launch(void* const* d_in, const int* in_sizes, int n_in,
                              void* d_out, int out_size)
{
    const float* x      = (const float*)d_in[0];
    const float* qkv_w  = (const float*)d_in[1];
    const float* proj_w = (const float*)d_in[2];
    const float* proj_b = (const float*)d_in[3];
    float* out = (float*)d_out;

    const int av_smem = (SEQ * HD + AV_ROWS * SPITCH) * (int)sizeof(float);
    cudaFuncSetAttribute(av_kernel2, cudaFuncAttributeMaxDynamicSharedMemorySize, av_smem);

    /* splits */
    split_kernel<<<(TOK*CDIM + 255)/256, 256>>>(x, 0, TOK*CDIM);
    split_kernel<<<(3*CDIM*CDIM + 255)/256, 256>>>(qkv_w, 1, 3*CDIM*CDIM);
    split_kernel<<<(CDIM*CDIM + 255)/256, 256>>>(proj_w, 2, CDIM*CDIM);

    /* exact fp32 top-k (independent of bf16 path) */
    const int write_keep = (out_size >= TOK * CDIM + BSZ * KEEP) ? 1 : 0;
    topk_fused<<<BSZ, 256>>>(x, qkv_w, out + (size_t)TOK * CDIM, write_keep);

    /* QKV via HMMA split-bf16 */
    hmma_gemm<<<dim3(3*CDIM/NT, (TOK + MT - 1)/MT), 256>>>(0, nullptr, nullptr);

    score_gemm_kernel<<<dim3(4, 4, BH), 256>>>();
    av_kernel2<<<dim3(BH, 4), 256, av_smem>>>();

    /* proj via HMMA split-bf16 */
    split_kernel<<<(TOK*CDIM + 255)/256, 256>>>(nullptr, 3, TOK*CDIM);
    hmma_gemm<<<dim3(CDIM/NT, (TOK + MT - 1)/MT), 256>>>(1, proj_b, out);
}

// round 6
// speedup vs baseline: 2.6127x; 1.4172x over previous
#include <cuda_runtime.h>
#include <cuda_bf16.h>
#include <math.h>
#include <stdint.h>

#define BSZ   64
#define SEQ   197
#define CDIM  768
#define NH    12
#define HD    64
#define KEEP  160
#define SCALEF 0.125f

#define BH   (BSZ*NH)
#define TOK  (BSZ*SEQ)

#define AV_ROWS 64
#define SPITCH  200

/* ---------------- scratch (device globals; no allocs allowed) ------ */
__device__ float g_q[BH*SEQ*HD];
__device__ float g_k[BH*SEQ*HD];
__device__ float g_v[BH*SEQ*HD];
__device__ float g_sc[BH*SEQ*SEQ];
__device__ float g_ctx[TOK*CDIM];

__device__ __nv_bfloat16 g_xh[TOK*CDIM],  g_xl[TOK*CDIM];
__device__ __nv_bfloat16 g_wqh[3*CDIM*CDIM], g_wql[3*CDIM*CDIM];
__device__ __nv_bfloat16 g_wph[CDIM*CDIM],   g_wpl[CDIM*CDIM];
__device__ __nv_bfloat16 g_cth[TOK*CDIM], g_ctl[TOK*CDIM];

/* top-k staging */
__device__ float g_qc[BSZ*CDIM];       /* q_cls per batch            */
__device__ float g_u [BSZ*NH*CDIM];    /* u[b,h,c]                   */
__device__ float g_wt[BSZ*SEQ];        /* abs-sum weights            */

/* ---------------- split fp32 -> bf16 hi/lo ------------------------- */
__global__ void split_kernel(const float* __restrict__ src, int which, int n)
{
    int i = blockIdx.x * 256 + threadIdx.x;
    if (i >= n) return;
    __nv_bfloat16 *hi, *lo;
    const float* s = src;
    if      (which == 0) { hi = g_xh;  lo = g_xl;  }
    else if (which == 1) { hi = g_wqh; lo = g_wql; }
    else if (which == 2) { hi = g_wph; lo = g_wpl; }
    else                 { hi = g_cth; lo = g_ctl; s = g_ctx; }
    float v = s[i];
    __nv_bfloat16 h = __float2bfloat16(v);
    hi[i] = h;
    lo[i] = __float2bfloat16(v - __bfloat162float(h));
}

/* ---------------- HMMA split-bf16 GEMM: out = A @ B^T -------------- */
#define MT 128
#define NT 128
#define KPAN 32
#define SPAD 40

__device__ __forceinline__ void mma16816(float* c, const uint32_t* a,
                                         uint32_t b0, uint32_t b1)
{
    asm volatile(
        "mma.sync.aligned.m16n8k16.row.col.f32.bf16.bf16.f32 "
        "{%0,%1,%2,%3}, {%4,%5,%6,%7}, {%8,%9}, {%0,%1,%2,%3};"
        : "+f"(c[0]), "+f"(c[1]), "+f"(c[2]), "+f"(c[3])
        : "r"(a[0]), "r"(a[1]), "r"(a[2]), "r"(a[3]), "r"(b0), "r"(b1));
}

__device__ __forceinline__ void stage_tile(__nv_bfloat16* s,
        const __nv_bfloat16* __restrict__ g, int row0, int rowmax, int kb, int t)
{
#pragma unroll
    for (int i = 0; i < 2; i++) {
        const int idx = t + i * 256;
        const int row = idx >> 2;
        const int c8  = (idx & 3) * 8;
        int gr = row0 + row; if (gr > rowmax) gr = rowmax;
        uint4 v = *reinterpret_cast<const uint4*>(g + (size_t)gr * CDIM + kb + c8);
        *reinterpret_cast<uint4*>(s + row * SPAD + c8) = v;
    }
}

__global__ __launch_bounds__(256, 2) void hmma_gemm(int mode,
        const float* __restrict__ bias, float* __restrict__ outp)
{
    __shared__ __align__(16) __nv_bfloat16 sAh[128*SPAD];
    __shared__ __align__(16) __nv_bfloat16 sAl[128*SPAD];
    __shared__ __align__(16) __nv_bfloat16 sBh[128*SPAD];
    __shared__ __align__(16) __nv_bfloat16 sBl[128*SPAD];

    const int t    = threadIdx.x;
    const int wid  = t >> 5, lane = t & 31;
    const int gq   = lane >> 2, tig = lane & 3;
    const int wm   = (wid & 3) * 32;
    const int wn   = (wid >> 2) * 64;
    const int m0   = blockIdx.y * MT;
    const int n0   = blockIdx.x * NT;

    const __nv_bfloat16 *Ah, *Al, *Bh, *Bl;
    if (mode == 0) { Ah = g_xh;  Al = g_xl;  Bh = g_wqh; Bl = g_wql; }
    else           { Ah = g_cth; Al = g_ctl; Bh = g_wph; Bl = g_wpl; }

    float acc[2][8][4];
#pragma unroll
    for (int mi = 0; mi < 2; mi++)
#pragma unroll
        for (int ni = 0; ni < 8; ni++)
#pragma unroll
            for (int r = 0; r < 4; r++) acc[mi][ni][r] = 0.f;

    for (int p = 0; p < CDIM / KPAN; p++) {
        const int kb = p * KPAN;
        stage_tile(sAh, Ah, m0, TOK - 1, kb, t);
        stage_tile(sAl, Al, m0, TOK - 1, kb, t);
        stage_tile(sBh, Bh, n0, 1 << 30, kb, t);
        stage_tile(sBl, Bl, n0, 1 << 30, kb, t);
        __syncthreads();

#pragma unroll
        for (int ks = 0; ks < 2; ks++) {
            const int ko = ks * 16;
            uint32_t ah[2][4], al[2][4];
#pragma unroll
            for (int mi = 0; mi < 2; mi++) {
                const int r = wm + mi * 16 + gq;
                ah[mi][0] = *reinterpret_cast<const uint32_t*>(&sAh[(r    ) * SPAD + ko     + 2*tig]);
                ah[mi][1] = *reinterpret_cast<const uint32_t*>(&sAh[(r + 8) * SPAD + ko     + 2*tig]);
                ah[mi][2] = *reinterpret_cast<const uint32_t*>(&sAh[(r    ) * SPAD + ko + 8 + 2*tig]);
                ah[mi][3] = *reinterpret_cast<const uint32_t*>(&sAh[(r + 8) * SPAD + ko + 8 + 2*tig]);
                al[mi][0] = *reinterpret_cast<const uint32_t*>(&sAl[(r    ) * SPAD + ko     + 2*tig]);
                al[mi][1] = *reinterpret_cast<const uint32_t*>(&sAl[(r + 8) * SPAD + ko     + 2*tig]);
                al[mi][2] = *reinterpret_cast<const uint32_t*>(&sAl[(r    ) * SPAD + ko + 8 + 2*tig]);
                al[mi][3] = *reinterpret_cast<const uint32_t*>(&sAl[(r + 8) * SPAD + ko + 8 + 2*tig]);
            }
#pragma unroll
            for (int ni = 0; ni < 8; ni++) {
                const int c = wn + ni * 8 + gq;
                const uint32_t bh0 = *reinterpret_cast<const uint32_t*>(&sBh[c * SPAD + ko     + 2*tig]);
                const uint32_t bh1 = *reinterpret_cast<const uint32_t*>(&sBh[c * SPAD + ko + 8 + 2*tig]);
                const uint32_t bl0 = *reinterpret_cast<const uint32_t*>(&sBl[c * SPAD + ko     + 2*tig]);
                const uint32_t bl1 = *reinterpret_cast<const uint32_t*>(&sBl[c * SPAD + ko + 8 + 2*tig]);
#pragma unroll
                for (int mi = 0; mi < 2; mi++) {
                    mma16816(acc[mi][ni], ah[mi], bh0, bh1);
                    mma16816(acc[mi][ni], ah[mi], bl0, bl1);
                    mma16816(acc[mi][ni], al[mi], bh0, bh1);
                }
            }
        }
        __syncthreads();
    }

#pragma unroll
    for (int mi = 0; mi < 2; mi++) {
#pragma unroll
        for (int h2 = 0; h2 < 2; h2++) {
            const int m = m0 + wm + mi * 16 + gq + h2 * 8;
            if (m >= TOK) continue;
#pragma unroll
            for (int ni = 0; ni < 8; ni++) {
                const int col = n0 + wn + ni * 8 + 2 * tig;
                const float v0 = acc[mi][ni][h2 * 2 + 0];
                const float v1 = acc[mi][ni][h2 * 2 + 1];
                if (mode == 1) {
                    float2 o = make_float2(v0 + bias[col], v1 + bias[col + 1]);
                    *reinterpret_cast<float2*>(&outp[(size_t)m * CDIM + col]) = o;
                } else {
                    const int s  = col / CDIM;
                    const int rm = col % CDIM;
                    const int h  = rm / HD, dd = rm % HD;
                    float* dst = (s == 0) ? g_q : (s == 1) ? g_k : g_v;
                    const int bidx = m / SEQ, n = m % SEQ;
                    float2 o = make_float2(v0, v1);
                    *reinterpret_cast<float2*>(
                        &dst[((size_t)(bidx * NH + h) * SEQ + n) * HD + dd]) = o;
                }
            }
        }
    }
}

/* ---------------- top-k stage A: Qc = x_cls @ Wq^T ----------------- */
__global__ __launch_bounds__(256) void topk_qc(const float* __restrict__ x,
                                               const float* __restrict__ w)
{
    __shared__ float xc[CDIM];
    const int b  = blockIdx.x;
    const int jt = blockIdx.y;       /* 0..11 -> 64 j's each */
    const int t  = threadIdx.x;
    const int lane = t & 31, wrp = t >> 5;

    for (int i = t; i < CDIM; i += 256) xc[i] = x[(size_t)(b * SEQ) * CDIM + i];
    __syncthreads();

#pragma unroll
    for (int jj = 0; jj < 8; jj++) {
        const int j = jt * 64 + wrp * 8 + jj;
        const float* wr = w + (size_t)j * CDIM;
        float s = 0.f;
#pragma unroll
        for (int c4 = 0; c4 < 6; c4++) {
            const int c = (c4 * 32 + lane) * 4;
            const float4 wv = *reinterpret_cast<const float4*>(&wr[c]);
            s += wv.x * xc[c] + wv.y * xc[c+1] + wv.z * xc[c+2] + wv.w * xc[c+3];
        }
#pragma unroll
        for (int off = 16; off > 0; off >>= 1)
            s += __shfl_xor_sync(0xffffffffu, s, off);
        if (lane == 0) g_qc[b * CDIM + j] = s;
    }
}

/* ---------------- top-k stage B: u[b,h,c] -------------------------- */
__global__ __launch_bounds__(256) void topk_u(const float* __restrict__ w)
{
    __shared__ float qh[HD];
    const int b = blockIdx.x, h = blockIdx.y;
    const int t = threadIdx.x;
    if (t < HD) qh[t] = g_qc[b * CDIM + h * HD + t];
    __syncthreads();

    const float* wk = w + (size_t)(CDIM + h * HD) * CDIM;
#pragma unroll
    for (int cc = 0; cc < 3; cc++) {
        const int c = cc * 256 + t;
        float s = 0.f;
#pragma unroll 16
        for (int d = 0; d < HD; d++) s += wk[(size_t)d * CDIM + c] * qh[d];
        g_u[((size_t)b * NH + h) * CDIM + c] = s;
    }
}

/* ---------------- top-k stage C: wt[b,m] --------------------------- */
__global__ __launch_bounds__(256) void topk_wt(const float* __restrict__ x)
{
    const int b = blockIdx.x;
    const int t = threadIdx.x;
    const int lane = t & 31, wrp = t >> 5;
    const int m = blockIdx.y * 8 + wrp;
    if (m >= SEQ) return;

    /* x row into registers (24 floats per lane) */
    const float* xr = x + (size_t)(b * SEQ + m) * CDIM;
    float4 xv[6];
#pragma unroll
    for (int c4 = 0; c4 < 6; c4++)
        xv[c4] = *reinterpret_cast<const float4*>(&xr[(c4 * 32 + lane) * 4]);

    const float* ub = g_u + (size_t)b * NH * CDIM;
    float tot = 0.f;
#pragma unroll
    for (int h = 0; h < NH; h++) {
        const float* ur = ub + h * CDIM;
        float s = 0.f;
#pragma unroll
        for (int c4 = 0; c4 < 6; c4++) {
            const int c = (c4 * 32 + lane) * 4;
            const float4 uv = *reinterpret_cast<const float4*>(&ur[c]);
            s += uv.x * xv[c4].x + uv.y * xv[c4].y + uv.z * xv[c4].z + uv.w * xv[c4].w;
        }
#pragma unroll
        for (int off = 16; off > 0; off >>= 1)
            s += __shfl_xor_sync(0xffffffffu, s, off);
        tot += fabsf(s);
    }
    if (lane == 0) g_wt[b * SEQ + m] = tot;
}

/* ---------------- top-k stage D: rank + emit ----------------------- */
__global__ __launch_bounds__(256) void topk_emit(float* __restrict__ out_keep,
                                                 int write_keep)
{
    __shared__ float wt[SEQ];
    __shared__ unsigned char keep[SEQ];
    const int b = blockIdx.x, t = threadIdx.x;

    if (t < SEQ) wt[t] = g_wt[b * SEQ + t];
    __syncthreads();
    if (t < SEQ) {
        const float wi = wt[t];
        int cnt = 0;
        for (int j = 0; j < SEQ; j++) {
            const float wj = wt[j];
            cnt += (wj > wi) || (wj == wi && j < t);
        }
        keep[t] = (cnt < KEEP) ? 1 : 0;
    }
    __syncthreads();
    if (write_keep && t < SEQ && keep[t]) {
        int pos = 0;
        for (int j = 0; j < t; j++) pos += keep[j];
        out_keep[b * KEEP + pos] = (float)t;
    }
}

/* ---------------- K2: scores (fp32 SIMT) --------------------------- */
__global__ void score_gemm_kernel()
{
    __shared__ float As[16][64];
    __shared__ float Bs[16][64];

    const int bh = blockIdx.z;
    const float* q  = g_q + (size_t)bh * SEQ * HD;
    const float* kk = g_k + (size_t)bh * SEQ * HD;
    float* sc = g_sc + (size_t)bh * SEQ * SEQ;

    const int i0 = blockIdx.y * 64;
    const int j0 = blockIdx.x * 64;
    const int t  = threadIdx.x;
    const int li = t >> 2;
    const int lk = (t & 3) * 4;
    const int ty = t >> 4, tx = t & 15;

    float acc[4][4];
#pragma unroll
    for (int i = 0; i < 4; i++)
#pragma unroll
        for (int j = 0; j < 4; j++) acc[i][j] = 0.f;

    for (int kb = 0; kb < HD; kb += 16) {
        float4 av = make_float4(0.f, 0.f, 0.f, 0.f);
        float4 bv = make_float4(0.f, 0.f, 0.f, 0.f);
        if (i0 + li < SEQ) av = *reinterpret_cast<const float4*>(&q [(i0 + li) * HD + kb + lk]);
        if (j0 + li < SEQ) bv = *reinterpret_cast<const float4*>(&kk[(j0 + li) * HD + kb + lk]);
        As[lk + 0][li] = av.x; As[lk + 1][li] = av.y;
        As[lk + 2][li] = av.z; As[lk + 3][li] = av.w;
        Bs[lk + 0][li] = bv.x; Bs[lk + 1][li] = bv.y;
        Bs[lk + 2][li] = bv.z; Bs[lk + 3][li] = bv.w;
        __syncthreads();
#pragma unroll
        for (int k = 0; k < 16; k++) {
            float a[4], b[4];
#pragma unroll
            for (int i = 0; i < 4; i++) a[i] = As[k][ty * 4 + i];
#pragma unroll
            for (int j = 0; j < 4; j++) b[j] = Bs[k][tx * 4 + j];
#pragma unroll
            for (int i = 0; i < 4; i++)
#pragma unroll
                for (int j = 0; j < 4; j++) acc[i][j] += a[i] * b[j];
        }
        __syncthreads();
    }

#pragma unroll
    for (int i = 0; i < 4; i++) {
        const int ii = i0 + ty * 4 + i;
        if (ii >= SEQ) continue;
#pragma unroll
        for (int j = 0; j < 4; j++) {
            const int jj = j0 + tx * 4 + j;
            if (jj < SEQ) sc[ii * SEQ + jj] = acc[i][j] * SCALEF;
        }
    }
}

/* ---------------- K4: softmax + AV --------------------------------- */
__global__ __launch_bounds__(256, 2) void av_kernel2()
{
    extern __shared__ float smf[];
    float* sV = smf;
    float* sS = smf + SEQ * HD;

    const int bh   = blockIdx.x;
    const int b    = bh / NH, h = bh % NH;
    const int row0 = blockIdx.y * AV_ROWS;
    const int t    = threadIdx.x;
    const int lane = t & 31;
    const int w    = t >> 5;

    const float4* v4  = reinterpret_cast<const float4*>(g_v + (size_t)bh * SEQ * HD);
    float4*       sV4 = reinterpret_cast<float4*>(sV);
    for (int i = t; i < SEQ * HD / 4; i += 256) sV4[i] = v4[i];

    const float* scb = g_sc + (size_t)bh * SEQ * SEQ;
#pragma unroll
    for (int r8 = 0; r8 < 8; r8++) {
        const int sr = w * 8 + r8;
        const int r  = row0 + sr;
        if (r < SEQ) {
            const float* row = scb + (size_t)r * SEQ;
            float vals[7];
            float mx = -1e30f;
#pragma unroll
            for (int i = 0; i < 7; i++) {
                const int m = lane + i * 32;
                vals[i] = (m < SEQ) ? row[m] : -1e30f;
                mx = fmaxf(mx, vals[i]);
            }
#pragma unroll
            for (int off = 16; off > 0; off >>= 1)
                mx = fmaxf(mx, __shfl_xor_sync(0xffffffffu, mx, off));
            float s = 0.f;
#pragma unroll
            for (int i = 0; i < 7; i++) {
                const int m = lane + i * 32;
                const float e = (m < SEQ) ? __expf(vals[i] - mx) : 0.f;
                vals[i] = e;
                s += e;
            }
#pragma unroll
            for (int off = 16; off > 0; off >>= 1)
                s += __shfl_xor_sync(0xffffffffu, s, off);
            const float inv = 1.f / s;
#pragma unroll
            for (int i = 0; i < 7; i++) {
                const int m = lane + i * 32;
                if (m < SEQ) sS[sr * SPITCH + m] = vals[i] * inv;
            }
        } else {
#pragma unroll
            for (int i = 0; i < 7; i++) {
                const int m = lane + i * 32;
                if (m < SEQ) sS[sr * SPITCH + m] = 0.f;
            }
        }
    }
    __syncthreads();

    const int tx = t & 15, ty = t >> 4;
    float acc[4][4];
#pragma unroll
    for (int i = 0; i < 4; i++)
#pragma unroll
        for (int j = 0; j < 4; j++) acc[i][j] = 0.f;

#pragma unroll 4
    for (int m = 0; m < SEQ; m++) {
        const float4 vv = *reinterpret_cast<const float4*>(&sV[m * HD + tx * 4]);
        float p[4];
#pragma unroll
        for (int i = 0; i < 4; i++) p[i] = sS[(ty * 4 + i) * SPITCH + m];
#pragma unroll
        for (int i = 0; i < 4; i++) {
            acc[i][0] += p[i] * vv.x;
            acc[i][1] += p[i] * vv.y;
            acc[i][2] += p[i] * vv.z;
            acc[i][3] += p[i] * vv.w;
        }
    }

    float* ctx = g_ctx + (size_t)(b * SEQ) * CDIM + h * HD;
#pragma unroll
    for (int i = 0; i < 4; i++) {
        const int r = row0 + ty * 4 + i;
        if (r < SEQ) {
            float4 o = make_float4(acc[i][0], acc[i][1], acc[i][2], acc[i][3]);
            *reinterpret_cast<float4*>(&ctx[(size_t)r * CDIM + tx * 4]) = o;
        }
    }
}

/* ------------------------------------------------------------------ */
extern "C" void kernel_launch(void* const* d_in, const int* in_sizes, int n_in,
                              void* d_out, int out_size)
{
    const float* x      = (const float*)d_in[0];
    const float* qkv_w  = (const float*)d_in[1];
    const float* proj_w = (const float*)d_in[2];
    const float* proj_b = (const float*)d_in[3];
    float* out = (float*)d_out;

    const int av_smem = (SEQ * HD + AV_ROWS * SPITCH) * (int)sizeof(float);
    cudaFuncSetAttribute(av_kernel2, cudaFuncAttributeMaxDynamicSharedMemorySize, av_smem);

    /* splits */
    split_kernel<<<(TOK*CDIM + 255)/256, 256>>>(x, 0, TOK*CDIM);
    split_kernel<<<(3*CDIM*CDIM + 255)/256, 256>>>(qkv_w, 1, 3*CDIM*CDIM);
    split_kernel<<<(CDIM*CDIM + 255)/256, 256>>>(proj_w, 2, CDIM*CDIM);

    /* exact fp32 top-k, staged for parallelism */
    const int write_keep = (out_size >= TOK * CDIM + BSZ * KEEP) ? 1 : 0;
    topk_qc  <<<dim3(BSZ, 12), 256>>>(x, qkv_w);
    topk_u   <<<dim3(BSZ, NH), 256>>>(qkv_w);
    topk_wt  <<<dim3(BSZ, (SEQ + 7) / 8), 256>>>(x);
    topk_emit<<<BSZ, 256>>>(out + (size_t)TOK * CDIM, write_keep);

    /* QKV via HMMA split-bf16 */
    hmma_gemm<<<dim3(3*CDIM/NT, (TOK + MT - 1)/MT), 256>>>(0, nullptr, nullptr);

    score_gemm_kernel<<<dim3(4, 4, BH), 256>>>();
    av_kernel2<<<dim3(BH, 4), 256, av_smem>>>();

    /* proj via HMMA split-bf16 */
    split_kernel<<<(TOK*CDIM + 255)/256, 256>>>(nullptr, 3, TOK*CDIM);
    hmma_gemm<<<dim3(CDIM/NT, (TOK + MT - 1)/MT), 256>>>(1, proj_b, out);
}

// round 7
// speedup vs baseline: 2.9821x; 1.1414x over previous
#include <cuda_runtime.h>
#include <cuda_bf16.h>
#include <math.h>
#include <stdint.h>

#define BSZ   64
#define SEQ   197
#define CDIM  768
#define NH    12
#define HD    64
#define KEEP  160
#define SCALEF 0.125f

#define BH   (BSZ*NH)
#define TOK  (BSZ*SEQ)

#define AV_ROWS 64
#define SPITCH  200

/* ---------------- scratch (device globals; no allocs allowed) ------ */
__device__ float g_v[BH*SEQ*HD];
__device__ float g_sc[BH*SEQ*SEQ];

__device__ __nv_bfloat16 g_qh[BH*SEQ*HD], g_ql[BH*SEQ*HD];
__device__ __nv_bfloat16 g_kh[BH*SEQ*HD], g_kl[BH*SEQ*HD];

__device__ __nv_bfloat16 g_xh[TOK*CDIM],  g_xl[TOK*CDIM];
__device__ __nv_bfloat16 g_wqh[3*CDIM*CDIM], g_wql[3*CDIM*CDIM];
__device__ __nv_bfloat16 g_wph[CDIM*CDIM],   g_wpl[CDIM*CDIM];
__device__ __nv_bfloat16 g_cth[TOK*CDIM], g_ctl[TOK*CDIM];

/* top-k staging */
__device__ float g_qc[BSZ*CDIM];
__device__ float g_u [BSZ*NH*CDIM];
__device__ float g_wt[BSZ*SEQ];

/* ---------------- helpers ------------------------------------------ */
__device__ __forceinline__ uint32_t pack_hi_lo(float v0, float v1, uint32_t* lo)
{
    __nv_bfloat16 h0 = __float2bfloat16(v0);
    __nv_bfloat16 h1 = __float2bfloat16(v1);
    __nv_bfloat16 l0 = __float2bfloat16(v0 - __bfloat162float(h0));
    __nv_bfloat16 l1 = __float2bfloat16(v1 - __bfloat162float(h1));
    uint32_t hi = ((uint32_t)__bfloat16_as_ushort(h1) << 16) | __bfloat16_as_ushort(h0);
    *lo         = ((uint32_t)__bfloat16_as_ushort(l1) << 16) | __bfloat16_as_ushort(l0);
    return hi;
}

/* ---------------- split fp32 -> bf16 hi/lo ------------------------- */
__global__ void split_kernel(const float* __restrict__ src, int which, int n)
{
    int i = blockIdx.x * 256 + threadIdx.x;
    if (i >= n) return;
    __nv_bfloat16 *hi, *lo;
    if      (which == 0) { hi = g_xh;  lo = g_xl;  }
    else if (which == 1) { hi = g_wqh; lo = g_wql; }
    else                 { hi = g_wph; lo = g_wpl; }
    float v = src[i];
    __nv_bfloat16 h = __float2bfloat16(v);
    hi[i] = h;
    lo[i] = __float2bfloat16(v - __bfloat162float(h));
}

/* ---------------- HMMA primitives ---------------------------------- */
#define MT 128
#define NT 128
#define KPAN 32
#define SPAD 40

__device__ __forceinline__ void mma16816(float* c, const uint32_t* a,
                                         uint32_t b0, uint32_t b1)
{
    asm volatile(
        "mma.sync.aligned.m16n8k16.row.col.f32.bf16.bf16.f32 "
        "{%0,%1,%2,%3}, {%4,%5,%6,%7}, {%8,%9}, {%0,%1,%2,%3};"
        : "+f"(c[0]), "+f"(c[1]), "+f"(c[2]), "+f"(c[3])
        : "r"(a[0]), "r"(a[1]), "r"(a[2]), "r"(a[3]), "r"(b0), "r"(b1));
}

__device__ __forceinline__ void stage_tile(__nv_bfloat16* s,
        const __nv_bfloat16* __restrict__ g, int row0, int rowmax, int kb, int t)
{
#pragma unroll
    for (int i = 0; i < 2; i++) {
        const int idx = t + i * 256;
        const int row = idx >> 2;
        const int c8  = (idx & 3) * 8;
        int gr = row0 + row; if (gr > rowmax) gr = rowmax;
        uint4 v = *reinterpret_cast<const uint4*>(g + (size_t)gr * CDIM + kb + c8);
        *reinterpret_cast<uint4*>(s + row * SPAD + c8) = v;
    }
}

/* stage from a [rows, HD] slice (stride 64) with row clamp */
__device__ __forceinline__ void stage_tile64(__nv_bfloat16* s,
        const __nv_bfloat16* __restrict__ g, int row0, int rowmax, int kb, int t)
{
#pragma unroll
    for (int i = 0; i < 2; i++) {
        const int idx = t + i * 256;
        const int row = idx >> 2;
        const int c8  = (idx & 3) * 8;
        int gr = row0 + row; if (gr > rowmax) gr = rowmax;
        uint4 v = *reinterpret_cast<const uint4*>(g + (size_t)gr * HD + kb + c8);
        *reinterpret_cast<uint4*>(s + row * SPAD + c8) = v;
    }
}

/* ---------------- K1/K5: big GEMMs (A @ B^T) ----------------------- */
__global__ __launch_bounds__(256, 2) void hmma_gemm(int mode,
        const float* __restrict__ bias, float* __restrict__ outp)
{
    __shared__ __align__(16) __nv_bfloat16 sAh[128*SPAD];
    __shared__ __align__(16) __nv_bfloat16 sAl[128*SPAD];
    __shared__ __align__(16) __nv_bfloat16 sBh[128*SPAD];
    __shared__ __align__(16) __nv_bfloat16 sBl[128*SPAD];

    const int t    = threadIdx.x;
    const int wid  = t >> 5, lane = t & 31;
    const int gq   = lane >> 2, tig = lane & 3;
    const int wm   = (wid & 3) * 32;
    const int wn   = (wid >> 2) * 64;
    const int m0   = blockIdx.y * MT;
    const int n0   = blockIdx.x * NT;

    const __nv_bfloat16 *Ah, *Al, *Bh, *Bl;
    if (mode == 0) { Ah = g_xh;  Al = g_xl;  Bh = g_wqh; Bl = g_wql; }
    else           { Ah = g_cth; Al = g_ctl; Bh = g_wph; Bl = g_wpl; }

    float acc[2][8][4];
#pragma unroll
    for (int mi = 0; mi < 2; mi++)
#pragma unroll
        for (int ni = 0; ni < 8; ni++)
#pragma unroll
            for (int r = 0; r < 4; r++) acc[mi][ni][r] = 0.f;

    for (int p = 0; p < CDIM / KPAN; p++) {
        const int kb = p * KPAN;
        stage_tile(sAh, Ah, m0, TOK - 1, kb, t);
        stage_tile(sAl, Al, m0, TOK - 1, kb, t);
        stage_tile(sBh, Bh, n0, 1 << 30, kb, t);
        stage_tile(sBl, Bl, n0, 1 << 30, kb, t);
        __syncthreads();

#pragma unroll
        for (int ks = 0; ks < 2; ks++) {
            const int ko = ks * 16;
            uint32_t ah[2][4], al[2][4];
#pragma unroll
            for (int mi = 0; mi < 2; mi++) {
                const int r = wm + mi * 16 + gq;
                ah[mi][0] = *reinterpret_cast<const uint32_t*>(&sAh[(r    ) * SPAD + ko     + 2*tig]);
                ah[mi][1] = *reinterpret_cast<const uint32_t*>(&sAh[(r + 8) * SPAD + ko     + 2*tig]);
                ah[mi][2] = *reinterpret_cast<const uint32_t*>(&sAh[(r    ) * SPAD + ko + 8 + 2*tig]);
                ah[mi][3] = *reinterpret_cast<const uint32_t*>(&sAh[(r + 8) * SPAD + ko + 8 + 2*tig]);
                al[mi][0] = *reinterpret_cast<const uint32_t*>(&sAl[(r    ) * SPAD + ko     + 2*tig]);
                al[mi][1] = *reinterpret_cast<const uint32_t*>(&sAl[(r + 8) * SPAD + ko     + 2*tig]);
                al[mi][2] = *reinterpret_cast<const uint32_t*>(&sAl[(r    ) * SPAD + ko + 8 + 2*tig]);
                al[mi][3] = *reinterpret_cast<const uint32_t*>(&sAl[(r + 8) * SPAD + ko + 8 + 2*tig]);
            }
#pragma unroll
            for (int ni = 0; ni < 8; ni++) {
                const int c = wn + ni * 8 + gq;
                const uint32_t bh0 = *reinterpret_cast<const uint32_t*>(&sBh[c * SPAD + ko     + 2*tig]);
                const uint32_t bh1 = *reinterpret_cast<const uint32_t*>(&sBh[c * SPAD + ko + 8 + 2*tig]);
                const uint32_t bl0 = *reinterpret_cast<const uint32_t*>(&sBl[c * SPAD + ko     + 2*tig]);
                const uint32_t bl1 = *reinterpret_cast<const uint32_t*>(&sBl[c * SPAD + ko + 8 + 2*tig]);
#pragma unroll
                for (int mi = 0; mi < 2; mi++) {
                    mma16816(acc[mi][ni], ah[mi], bh0, bh1);
                    mma16816(acc[mi][ni], ah[mi], bl0, bl1);
                    mma16816(acc[mi][ni], al[mi], bh0, bh1);
                }
            }
        }
        __syncthreads();
    }

#pragma unroll
    for (int mi = 0; mi < 2; mi++) {
#pragma unroll
        for (int h2 = 0; h2 < 2; h2++) {
            const int m = m0 + wm + mi * 16 + gq + h2 * 8;
            if (m >= TOK) continue;
#pragma unroll
            for (int ni = 0; ni < 8; ni++) {
                const int col = n0 + wn + ni * 8 + 2 * tig;
                const float v0 = acc[mi][ni][h2 * 2 + 0];
                const float v1 = acc[mi][ni][h2 * 2 + 1];
                if (mode == 1) {
                    float2 o = make_float2(v0 + bias[col], v1 + bias[col + 1]);
                    *reinterpret_cast<float2*>(&outp[(size_t)m * CDIM + col]) = o;
                } else {
                    const int s  = col / CDIM;
                    const int rm = col % CDIM;
                    const int h  = rm / HD, dd = rm % HD;
                    const int bidx = m / SEQ, n = m % SEQ;
                    const size_t off = ((size_t)(bidx * NH + h) * SEQ + n) * HD + dd;
                    if (s == 2) {
                        *reinterpret_cast<float2*>(&g_v[off]) = make_float2(v0, v1);
                    } else {
                        uint32_t lo, hi = pack_hi_lo(v0, v1, &lo);
                        __nv_bfloat16 *dh = (s == 0) ? g_qh : g_kh;
                        __nv_bfloat16 *dl = (s == 0) ? g_ql : g_kl;
                        *reinterpret_cast<uint32_t*>(&dh[off]) = hi;
                        *reinterpret_cast<uint32_t*>(&dl[off]) = lo;
                    }
                }
            }
        }
    }
}

/* ---------------- K2: scores via HMMA split-bf16 ------------------- */
__global__ __launch_bounds__(256, 2) void score_hmma()
{
    __shared__ __align__(16) __nv_bfloat16 sAh[128*SPAD];
    __shared__ __align__(16) __nv_bfloat16 sAl[128*SPAD];
    __shared__ __align__(16) __nv_bfloat16 sBh[128*SPAD];
    __shared__ __align__(16) __nv_bfloat16 sBl[128*SPAD];

    const int t    = threadIdx.x;
    const int wid  = t >> 5, lane = t & 31;
    const int gq   = lane >> 2, tig = lane & 3;
    const int wm   = (wid & 3) * 32;
    const int wn   = (wid >> 2) * 64;
    const int bh   = blockIdx.z;
    const int i0   = blockIdx.y * MT;
    const int j0   = blockIdx.x * NT;

    const size_t base = (size_t)bh * SEQ * HD;
    const __nv_bfloat16 *Qh = g_qh + base, *Ql = g_ql + base;
    const __nv_bfloat16 *Kh = g_kh + base, *Kl = g_kl + base;

    float acc[2][8][4];
#pragma unroll
    for (int mi = 0; mi < 2; mi++)
#pragma unroll
        for (int ni = 0; ni < 8; ni++)
#pragma unroll
            for (int r = 0; r < 4; r++) acc[mi][ni][r] = 0.f;

#pragma unroll
    for (int p = 0; p < HD / KPAN; p++) {
        const int kb = p * KPAN;
        stage_tile64(sAh, Qh, i0, SEQ - 1, kb, t);
        stage_tile64(sAl, Ql, i0, SEQ - 1, kb, t);
        stage_tile64(sBh, Kh, j0, SEQ - 1, kb, t);
        stage_tile64(sBl, Kl, j0, SEQ - 1, kb, t);
        __syncthreads();

#pragma unroll
        for (int ks = 0; ks < 2; ks++) {
            const int ko = ks * 16;
            uint32_t ah[2][4], al[2][4];
#pragma unroll
            for (int mi = 0; mi < 2; mi++) {
                const int r = wm + mi * 16 + gq;
                ah[mi][0] = *reinterpret_cast<const uint32_t*>(&sAh[(r    ) * SPAD + ko     + 2*tig]);
                ah[mi][1] = *reinterpret_cast<const uint32_t*>(&sAh[(r + 8) * SPAD + ko     + 2*tig]);
                ah[mi][2] = *reinterpret_cast<const uint32_t*>(&sAh[(r    ) * SPAD + ko + 8 + 2*tig]);
                ah[mi][3] = *reinterpret_cast<const uint32_t*>(&sAh[(r + 8) * SPAD + ko + 8 + 2*tig]);
                al[mi][0] = *reinterpret_cast<const uint32_t*>(&sAl[(r    ) * SPAD + ko     + 2*tig]);
                al[mi][1] = *reinterpret_cast<const uint32_t*>(&sAl[(r + 8) * SPAD + ko     + 2*tig]);
                al[mi][2] = *reinterpret_cast<const uint32_t*>(&sAl[(r    ) * SPAD + ko + 8 + 2*tig]);
                al[mi][3] = *reinterpret_cast<const uint32_t*>(&sAl[(r + 8) * SPAD + ko + 8 + 2*tig]);
            }
#pragma unroll
            for (int ni = 0; ni < 8; ni++) {
                const int c = wn + ni * 8 + gq;
                const uint32_t bh0 = *reinterpret_cast<const uint32_t*>(&sBh[c * SPAD + ko     + 2*tig]);
                const uint32_t bh1 = *reinterpret_cast<const uint32_t*>(&sBh[c * SPAD + ko + 8 + 2*tig]);
                const uint32_t bl0 = *reinterpret_cast<const uint32_t*>(&sBl[c * SPAD + ko     + 2*tig]);
                const uint32_t bl1 = *reinterpret_cast<const uint32_t*>(&sBl[c * SPAD + ko + 8 + 2*tig]);
#pragma unroll
                for (int mi = 0; mi < 2; mi++) {
                    mma16816(acc[mi][ni], ah[mi], bh0, bh1);
                    mma16816(acc[mi][ni], ah[mi], bl0, bl1);
                    mma16816(acc[mi][ni], al[mi], bh0, bh1);
                }
            }
        }
        __syncthreads();
    }

    float* sc = g_sc + (size_t)bh * SEQ * SEQ;
#pragma unroll
    for (int mi = 0; mi < 2; mi++) {
#pragma unroll
        for (int h2 = 0; h2 < 2; h2++) {
            const int ii = i0 + wm + mi * 16 + gq + h2 * 8;
            if (ii >= SEQ) continue;
#pragma unroll
            for (int ni = 0; ni < 8; ni++) {
                const int jj = j0 + wn + ni * 8 + 2 * tig;
                if (jj < SEQ)     sc[(size_t)ii * SEQ + jj]     = acc[mi][ni][h2*2+0] * SCALEF;
                if (jj + 1 < SEQ) sc[(size_t)ii * SEQ + jj + 1] = acc[mi][ni][h2*2+1] * SCALEF;
            }
        }
    }
}

/* ---------------- top-k stages (exact fp32) ------------------------ */
__global__ __launch_bounds__(256) void topk_qc(const float* __restrict__ x,
                                               const float* __restrict__ w)
{
    __shared__ float xc[CDIM];
    const int b  = blockIdx.x;
    const int jt = blockIdx.y;
    const int t  = threadIdx.x;
    const int lane = t & 31, wrp = t >> 5;

    for (int i = t; i < CDIM; i += 256) xc[i] = x[(size_t)(b * SEQ) * CDIM + i];
    __syncthreads();

#pragma unroll
    for (int jj = 0; jj < 8; jj++) {
        const int j = jt * 64 + wrp * 8 + jj;
        const float* wr = w + (size_t)j * CDIM;
        float s = 0.f;
#pragma unroll
        for (int c4 = 0; c4 < 6; c4++) {
            const int c = (c4 * 32 + lane) * 4;
            const float4 wv = *reinterpret_cast<const float4*>(&wr[c]);
            s += wv.x * xc[c] + wv.y * xc[c+1] + wv.z * xc[c+2] + wv.w * xc[c+3];
        }
#pragma unroll
        for (int off = 16; off > 0; off >>= 1)
            s += __shfl_xor_sync(0xffffffffu, s, off);
        if (lane == 0) g_qc[b * CDIM + j] = s;
    }
}

__global__ __launch_bounds__(256) void topk_u(const float* __restrict__ w)
{
    __shared__ float qh[HD];
    const int b = blockIdx.x, h = blockIdx.y;
    const int t = threadIdx.x;
    if (t < HD) qh[t] = g_qc[b * CDIM + h * HD + t];
    __syncthreads();

    const float* wk = w + (size_t)(CDIM + h * HD) * CDIM;
#pragma unroll
    for (int cc = 0; cc < 3; cc++) {
        const int c = cc * 256 + t;
        float s = 0.f;
#pragma unroll 16
        for (int d = 0; d < HD; d++) s += wk[(size_t)d * CDIM + c] * qh[d];
        g_u[((size_t)b * NH + h) * CDIM + c] = s;
    }
}

__global__ __launch_bounds__(256) void topk_wt(const float* __restrict__ x)
{
    const int b = blockIdx.x;
    const int t = threadIdx.x;
    const int lane = t & 31, wrp = t >> 5;
    const int m = blockIdx.y * 8 + wrp;
    if (m >= SEQ) return;

    const float* xr = x + (size_t)(b * SEQ + m) * CDIM;
    float4 xv[6];
#pragma unroll
    for (int c4 = 0; c4 < 6; c4++)
        xv[c4] = *reinterpret_cast<const float4*>(&xr[(c4 * 32 + lane) * 4]);

    const float* ub = g_u + (size_t)b * NH * CDIM;
    float tot = 0.f;
#pragma unroll
    for (int h = 0; h < NH; h++) {
        const float* ur = ub + h * CDIM;
        float s = 0.f;
#pragma unroll
        for (int c4 = 0; c4 < 6; c4++) {
            const int c = (c4 * 32 + lane) * 4;
            const float4 uv = *reinterpret_cast<const float4*>(&ur[c]);
            s += uv.x * xv[c4].x + uv.y * xv[c4].y + uv.z * xv[c4].z + uv.w * xv[c4].w;
        }
#pragma unroll
        for (int off = 16; off > 0; off >>= 1)
            s += __shfl_xor_sync(0xffffffffu, s, off);
        tot += fabsf(s);
    }
    if (lane == 0) g_wt[b * SEQ + m] = tot;
}

__global__ __launch_bounds__(256) void topk_emit(float* __restrict__ out_keep,
                                                 int write_keep)
{
    __shared__ float wt[SEQ];
    __shared__ unsigned char keep[SEQ];
    const int b = blockIdx.x, t = threadIdx.x;

    if (t < SEQ) wt[t] = g_wt[b * SEQ + t];
    __syncthreads();
    if (t < SEQ) {
        const float wi = wt[t];
        int cnt = 0;
        for (int j = 0; j < SEQ; j++) {
            const float wj = wt[j];
            cnt += (wj > wi) || (wj == wi && j < t);
        }
        keep[t] = (cnt < KEEP) ? 1 : 0;
    }
    __syncthreads();
    if (write_keep && t < SEQ && keep[t]) {
        int pos = 0;
        for (int j = 0; j < t; j++) pos += keep[j];
        out_keep[b * KEEP + pos] = (float)t;
    }
}

/* ---------------- K4: softmax + AV, ctx emitted as bf16 hi/lo ------ */
__global__ __launch_bounds__(256, 2) void av_kernel2()
{
    extern __shared__ float smf[];
    float* sV = smf;
    float* sS = smf + SEQ * HD;

    const int bh   = blockIdx.x;
    const int b    = bh / NH, h = bh % NH;
    const int row0 = blockIdx.y * AV_ROWS;
    const int t    = threadIdx.x;
    const int lane = t & 31;
    const int w    = t >> 5;

    const float4* v4  = reinterpret_cast<const float4*>(g_v + (size_t)bh * SEQ * HD);
    float4*       sV4 = reinterpret_cast<float4*>(sV);
    for (int i = t; i < SEQ * HD / 4; i += 256) sV4[i] = v4[i];

    const float* scb = g_sc + (size_t)bh * SEQ * SEQ;
#pragma unroll
    for (int r8 = 0; r8 < 8; r8++) {
        const int sr = w * 8 + r8;
        const int r  = row0 + sr;
        if (r < SEQ) {
            const float* row = scb + (size_t)r * SEQ;
            float vals[7];
            float mx = -1e30f;
#pragma unroll
            for (int i = 0; i < 7; i++) {
                const int m = lane + i * 32;
                vals[i] = (m < SEQ) ? row[m] : -1e30f;
                mx = fmaxf(mx, vals[i]);
            }
#pragma unroll
            for (int off = 16; off > 0; off >>= 1)
                mx = fmaxf(mx, __shfl_xor_sync(0xffffffffu, mx, off));
            float s = 0.f;
#pragma unroll
            for (int i = 0; i < 7; i++) {
                const int m = lane + i * 32;
                const float e = (m < SEQ) ? __expf(vals[i] - mx) : 0.f;
                vals[i] = e;
                s += e;
            }
#pragma unroll
            for (int off = 16; off > 0; off >>= 1)
                s += __shfl_xor_sync(0xffffffffu, s, off);
            const float inv = 1.f / s;
#pragma unroll
            for (int i = 0; i < 7; i++) {
                const int m = lane + i * 32;
                if (m < SEQ) sS[sr * SPITCH + m] = vals[i] * inv;
            }
        } else {
#pragma unroll
            for (int i = 0; i < 7; i++) {
                const int m = lane + i * 32;
                if (m < SEQ) sS[sr * SPITCH + m] = 0.f;
            }
        }
    }
    __syncthreads();

    const int tx = t & 15, ty = t >> 4;
    float acc[4][4];
#pragma unroll
    for (int i = 0; i < 4; i++)
#pragma unroll
        for (int j = 0; j < 4; j++) acc[i][j] = 0.f;

#pragma unroll 4
    for (int m = 0; m < SEQ; m++) {
        const float4 vv = *reinterpret_cast<const float4*>(&sV[m * HD + tx * 4]);
        float p[4];
#pragma unroll
        for (int i = 0; i < 4; i++) p[i] = sS[(ty * 4 + i) * SPITCH + m];
#pragma unroll
        for (int i = 0; i < 4; i++) {
            acc[i][0] += p[i] * vv.x;
            acc[i][1] += p[i] * vv.y;
            acc[i][2] += p[i] * vv.z;
            acc[i][3] += p[i] * vv.w;
        }
    }

    /* emit ctx directly as bf16 hi/lo (proj GEMM input format) */
#pragma unroll
    for (int i = 0; i < 4; i++) {
        const int r = row0 + ty * 4 + i;
        if (r < SEQ) {
            const size_t off = (size_t)(b * SEQ + r) * CDIM + h * HD + tx * 4;
            uint32_t lo0, hi0 = pack_hi_lo(acc[i][0], acc[i][1], &lo0);
            uint32_t lo1, hi1 = pack_hi_lo(acc[i][2], acc[i][3], &lo1);
            *reinterpret_cast<uint2*>(&g_cth[off]) = make_uint2(hi0, hi1);
            *reinterpret_cast<uint2*>(&g_ctl[off]) = make_uint2(lo0, lo1);
        }
    }
}

/* ------------------------------------------------------------------ */
extern "C" void kernel_launch(void* const* d_in, const int* in_sizes, int n_in,
                              void* d_out, int out_size)
{
    const float* x      = (const float*)d_in[0];
    const float* qkv_w  = (const float*)d_in[1];
    const float* proj_w = (const float*)d_in[2];
    const float* proj_b = (const float*)d_in[3];
    float* out = (float*)d_out;

    const int av_smem = (SEQ * HD + AV_ROWS * SPITCH) * (int)sizeof(float);
    cudaFuncSetAttribute(av_kernel2, cudaFuncAttributeMaxDynamicSharedMemorySize, av_smem);

    /* splits */
    split_kernel<<<(TOK*CDIM + 255)/256, 256>>>(x, 0, TOK*CDIM);
    split_kernel<<<(3*CDIM*CDIM + 255)/256, 256>>>(qkv_w, 1, 3*CDIM*CDIM);
    split_kernel<<<(CDIM*CDIM + 255)/256, 256>>>(proj_w, 2, CDIM*CDIM);

    /* exact fp32 top-k (decoupled from bf16 path) */
    const int write_keep = (out_size >= TOK * CDIM + BSZ * KEEP) ? 1 : 0;
    topk_qc  <<<dim3(BSZ, 12), 256>>>(x, qkv_w);
    topk_u   <<<dim3(BSZ, NH), 256>>>(qkv_w);
    topk_wt  <<<dim3(BSZ, (SEQ + 7) / 8), 256>>>(x);
    topk_emit<<<BSZ, 256>>>(out + (size_t)TOK * CDIM, write_keep);

    /* QKV via HMMA split-bf16; q,k emitted bf16 hi/lo, v fp32 */
    hmma_gemm<<<dim3(3*CDIM/NT, (TOK + MT - 1)/MT), 256>>>(0, nullptr, nullptr);

    /* scores via HMMA split-bf16 */
    score_hmma<<<dim3(2, 2, BH), 256>>>();

    av_kernel2<<<dim3(BH, 4), 256, av_smem>>>();

    /* proj via HMMA split-bf16 (reads ctx hi/lo written by av) */
    hmma_gemm<<<dim3(CDIM/NT, (TOK + MT - 1)/MT), 256>>>(1, proj_b, out);
}

// round 8
// speedup vs baseline: 3.0423x; 1.0202x over previous
#include <cuda_runtime.h>
#include <cuda_bf16.h>
#include <math.h>
#include <stdint.h>

#define BSZ   64
#define SEQ   197
#define CDIM  768
#define NH    12
#define HD    64
#define KEEP  160
#define SCALEF 0.125f

#define BH   (BSZ*NH)
#define TOK  (BSZ*SEQ)

#define SEQP   228   /* padded n dim for V^T / P (k-dim of PV)        */
#define PPITCH 228   /* smem pitch (456B -> conflict-free frag loads) */

/* ---------------- scratch (device globals; no allocs allowed) ------ */
__device__ float g_sc[BH*SEQ*SEQ];

__device__ __nv_bfloat16 g_qh[BH*SEQ*HD], g_ql[BH*SEQ*HD];
__device__ __nv_bfloat16 g_kh[BH*SEQ*HD], g_kl[BH*SEQ*HD];
__device__ uint32_t      g_vt[BH*HD*SEQP];   /* V^T packed (hi|lo<<16); pad cols stay 0 */

__device__ __nv_bfloat16 g_xh[TOK*CDIM],  g_xl[TOK*CDIM];
__device__ __nv_bfloat16 g_wqh[3*CDIM*CDIM], g_wql[3*CDIM*CDIM];
__device__ __nv_bfloat16 g_wph[CDIM*CDIM],   g_wpl[CDIM*CDIM];
__device__ __nv_bfloat16 g_cth[TOK*CDIM], g_ctl[TOK*CDIM];

/* top-k staging */
__device__ float g_qc[BSZ*CDIM];
__device__ float g_u [BSZ*NH*CDIM];
__device__ float g_wt[BSZ*SEQ];

/* ---------------- helpers ------------------------------------------ */
__device__ __forceinline__ uint32_t pack_hi_lo(float v0, float v1, uint32_t* lo)
{
    __nv_bfloat16 h0 = __float2bfloat16(v0);
    __nv_bfloat16 h1 = __float2bfloat16(v1);
    __nv_bfloat16 l0 = __float2bfloat16(v0 - __bfloat162float(h0));
    __nv_bfloat16 l1 = __float2bfloat16(v1 - __bfloat162float(h1));
    uint32_t hi = ((uint32_t)__bfloat16_as_ushort(h1) << 16) | __bfloat16_as_ushort(h0);
    *lo         = ((uint32_t)__bfloat16_as_ushort(l1) << 16) | __bfloat16_as_ushort(l0);
    return hi;
}
__device__ __forceinline__ uint32_t pack_v(float v)
{
    __nv_bfloat16 h = __float2bfloat16(v);
    __nv_bfloat16 l = __float2bfloat16(v - __bfloat162float(h));
    return (uint32_t)__bfloat16_as_ushort(h) | ((uint32_t)__bfloat16_as_ushort(l) << 16);
}

/* ---------------- split fp32 -> bf16 hi/lo ------------------------- */
__global__ void split_kernel(const float* __restrict__ src, int which, int n)
{
    int i = blockIdx.x * 256 + threadIdx.x;
    if (i >= n) return;
    __nv_bfloat16 *hi, *lo;
    if      (which == 0) { hi = g_xh;  lo = g_xl;  }
    else if (which == 1) { hi = g_wqh; lo = g_wql; }
    else                 { hi = g_wph; lo = g_wpl; }
    float v = src[i];
    __nv_bfloat16 h = __float2bfloat16(v);
    hi[i] = h;
    lo[i] = __float2bfloat16(v - __bfloat162float(h));
}

/* ---------------- HMMA primitives ---------------------------------- */
#define MT 128
#define NT 128
#define KPAN 32
#define SPAD 40

__device__ __forceinline__ void mma16816(float* c, const uint32_t* a,
                                         uint32_t b0, uint32_t b1)
{
    asm volatile(
        "mma.sync.aligned.m16n8k16.row.col.f32.bf16.bf16.f32 "
        "{%0,%1,%2,%3}, {%4,%5,%6,%7}, {%8,%9}, {%0,%1,%2,%3};"
        : "+f"(c[0]), "+f"(c[1]), "+f"(c[2]), "+f"(c[3])
        : "r"(a[0]), "r"(a[1]), "r"(a[2]), "r"(a[3]), "r"(b0), "r"(b1));
}

__device__ __forceinline__ void stage_tile(__nv_bfloat16* s,
        const __nv_bfloat16* __restrict__ g, int row0, int rowmax, int kb, int t)
{
#pragma unroll
    for (int i = 0; i < 2; i++) {
        const int idx = t + i * 256;
        const int row = idx >> 2;
        const int c8  = (idx & 3) * 8;
        int gr = row0 + row; if (gr > rowmax) gr = rowmax;
        uint4 v = *reinterpret_cast<const uint4*>(g + (size_t)gr * CDIM + kb + c8);
        *reinterpret_cast<uint4*>(s + row * SPAD + c8) = v;
    }
}

__device__ __forceinline__ void stage_tile64(__nv_bfloat16* s,
        const __nv_bfloat16* __restrict__ g, int row0, int rowmax, int kb, int t)
{
#pragma unroll
    for (int i = 0; i < 2; i++) {
        const int idx = t + i * 256;
        const int row = idx >> 2;
        const int c8  = (idx & 3) * 8;
        int gr = row0 + row; if (gr > rowmax) gr = rowmax;
        uint4 v = *reinterpret_cast<const uint4*>(g + (size_t)gr * HD + kb + c8);
        *reinterpret_cast<uint4*>(s + row * SPAD + c8) = v;
    }
}

/* ---------------- K1/K5: big GEMMs (A @ B^T) ----------------------- */
__global__ __launch_bounds__(256, 2) void hmma_gemm(int mode,
        const float* __restrict__ bias, float* __restrict__ outp)
{
    __shared__ __align__(16) __nv_bfloat16 sAh[128*SPAD];
    __shared__ __align__(16) __nv_bfloat16 sAl[128*SPAD];
    __shared__ __align__(16) __nv_bfloat16 sBh[128*SPAD];
    __shared__ __align__(16) __nv_bfloat16 sBl[128*SPAD];

    const int t    = threadIdx.x;
    const int wid  = t >> 5, lane = t & 31;
    const int gq   = lane >> 2, tig = lane & 3;
    const int wm   = (wid & 3) * 32;
    const int wn   = (wid >> 2) * 64;
    const int m0   = blockIdx.y * MT;
    const int n0   = blockIdx.x * NT;

    const __nv_bfloat16 *Ah, *Al, *Bh, *Bl;
    if (mode == 0) { Ah = g_xh;  Al = g_xl;  Bh = g_wqh; Bl = g_wql; }
    else           { Ah = g_cth; Al = g_ctl; Bh = g_wph; Bl = g_wpl; }

    float acc[2][8][4];
#pragma unroll
    for (int mi = 0; mi < 2; mi++)
#pragma unroll
        for (int ni = 0; ni < 8; ni++)
#pragma unroll
            for (int r = 0; r < 4; r++) acc[mi][ni][r] = 0.f;

    for (int p = 0; p < CDIM / KPAN; p++) {
        const int kb = p * KPAN;
        stage_tile(sAh, Ah, m0, TOK - 1, kb, t);
        stage_tile(sAl, Al, m0, TOK - 1, kb, t);
        stage_tile(sBh, Bh, n0, 1 << 30, kb, t);
        stage_tile(sBl, Bl, n0, 1 << 30, kb, t);
        __syncthreads();

#pragma unroll
        for (int ks = 0; ks < 2; ks++) {
            const int ko = ks * 16;
            uint32_t ah[2][4], al[2][4];
#pragma unroll
            for (int mi = 0; mi < 2; mi++) {
                const int r = wm + mi * 16 + gq;
                ah[mi][0] = *reinterpret_cast<const uint32_t*>(&sAh[(r    ) * SPAD + ko     + 2*tig]);
                ah[mi][1] = *reinterpret_cast<const uint32_t*>(&sAh[(r + 8) * SPAD + ko     + 2*tig]);
                ah[mi][2] = *reinterpret_cast<const uint32_t*>(&sAh[(r    ) * SPAD + ko + 8 + 2*tig]);
                ah[mi][3] = *reinterpret_cast<const uint32_t*>(&sAh[(r + 8) * SPAD + ko + 8 + 2*tig]);
                al[mi][0] = *reinterpret_cast<const uint32_t*>(&sAl[(r    ) * SPAD + ko     + 2*tig]);
                al[mi][1] = *reinterpret_cast<const uint32_t*>(&sAl[(r + 8) * SPAD + ko     + 2*tig]);
                al[mi][2] = *reinterpret_cast<const uint32_t*>(&sAl[(r    ) * SPAD + ko + 8 + 2*tig]);
                al[mi][3] = *reinterpret_cast<const uint32_t*>(&sAl[(r + 8) * SPAD + ko + 8 + 2*tig]);
            }
#pragma unroll
            for (int ni = 0; ni < 8; ni++) {
                const int c = wn + ni * 8 + gq;
                const uint32_t bh0 = *reinterpret_cast<const uint32_t*>(&sBh[c * SPAD + ko     + 2*tig]);
                const uint32_t bh1 = *reinterpret_cast<const uint32_t*>(&sBh[c * SPAD + ko + 8 + 2*tig]);
                const uint32_t bl0 = *reinterpret_cast<const uint32_t*>(&sBl[c * SPAD + ko     + 2*tig]);
                const uint32_t bl1 = *reinterpret_cast<const uint32_t*>(&sBl[c * SPAD + ko + 8 + 2*tig]);
#pragma unroll
                for (int mi = 0; mi < 2; mi++) {
                    mma16816(acc[mi][ni], ah[mi], bh0, bh1);
                    mma16816(acc[mi][ni], ah[mi], bl0, bl1);
                    mma16816(acc[mi][ni], al[mi], bh0, bh1);
                }
            }
        }
        __syncthreads();
    }

#pragma unroll
    for (int mi = 0; mi < 2; mi++) {
#pragma unroll
        for (int h2 = 0; h2 < 2; h2++) {
            const int m = m0 + wm + mi * 16 + gq + h2 * 8;
            if (m >= TOK) continue;
#pragma unroll
            for (int ni = 0; ni < 8; ni++) {
                const int col = n0 + wn + ni * 8 + 2 * tig;
                const float v0 = acc[mi][ni][h2 * 2 + 0];
                const float v1 = acc[mi][ni][h2 * 2 + 1];
                if (mode == 1) {
                    float2 o = make_float2(v0 + bias[col], v1 + bias[col + 1]);
                    *reinterpret_cast<float2*>(&outp[(size_t)m * CDIM + col]) = o;
                } else {
                    const int s  = col / CDIM;
                    const int rm = col % CDIM;
                    const int h  = rm / HD, dd = rm % HD;
                    const int bidx = m / SEQ, n = m % SEQ;
                    if (s == 2) {
                        /* V transposed + packed: g_vt[bh][d][n] */
                        const size_t vo = ((size_t)(bidx * NH + h) * HD + dd) * SEQP + n;
                        g_vt[vo]        = pack_v(v0);
                        g_vt[vo + SEQP] = pack_v(v1);
                    } else {
                        const size_t off = ((size_t)(bidx * NH + h) * SEQ + n) * HD + dd;
                        uint32_t lo, hi = pack_hi_lo(v0, v1, &lo);
                        __nv_bfloat16 *dh = (s == 0) ? g_qh : g_kh;
                        __nv_bfloat16 *dl = (s == 0) ? g_ql : g_kl;
                        *reinterpret_cast<uint32_t*>(&dh[off]) = hi;
                        *reinterpret_cast<uint32_t*>(&dl[off]) = lo;
                    }
                }
            }
        }
    }
}

/* ---------------- K2: scores via HMMA split-bf16 ------------------- */
__global__ __launch_bounds__(256, 2) void score_hmma()
{
    __shared__ __align__(16) __nv_bfloat16 sAh[128*SPAD];
    __shared__ __align__(16) __nv_bfloat16 sAl[128*SPAD];
    __shared__ __align__(16) __nv_bfloat16 sBh[128*SPAD];
    __shared__ __align__(16) __nv_bfloat16 sBl[128*SPAD];

    const int t    = threadIdx.x;
    const int wid  = t >> 5, lane = t & 31;
    const int gq   = lane >> 2, tig = lane & 3;
    const int wm   = (wid & 3) * 32;
    const int wn   = (wid >> 2) * 64;
    const int bh   = blockIdx.z;
    const int i0   = blockIdx.y * MT;
    const int j0   = blockIdx.x * NT;

    const size_t base = (size_t)bh * SEQ * HD;
    const __nv_bfloat16 *Qh = g_qh + base, *Ql = g_ql + base;
    const __nv_bfloat16 *Kh = g_kh + base, *Kl = g_kl + base;

    float acc[2][8][4];
#pragma unroll
    for (int mi = 0; mi < 2; mi++)
#pragma unroll
        for (int ni = 0; ni < 8; ni++)
#pragma unroll
            for (int r = 0; r < 4; r++) acc[mi][ni][r] = 0.f;

#pragma unroll
    for (int p = 0; p < HD / KPAN; p++) {
        const int kb = p * KPAN;
        stage_tile64(sAh, Qh, i0, SEQ - 1, kb, t);
        stage_tile64(sAl, Ql, i0, SEQ - 1, kb, t);
        stage_tile64(sBh, Kh, j0, SEQ - 1, kb, t);
        stage_tile64(sBl, Kl, j0, SEQ - 1, kb, t);
        __syncthreads();

#pragma unroll
        for (int ks = 0; ks < 2; ks++) {
            const int ko = ks * 16;
            uint32_t ah[2][4], al[2][4];
#pragma unroll
            for (int mi = 0; mi < 2; mi++) {
                const int r = wm + mi * 16 + gq;
                ah[mi][0] = *reinterpret_cast<const uint32_t*>(&sAh[(r    ) * SPAD + ko     + 2*tig]);
                ah[mi][1] = *reinterpret_cast<const uint32_t*>(&sAh[(r + 8) * SPAD + ko     + 2*tig]);
                ah[mi][2] = *reinterpret_cast<const uint32_t*>(&sAh[(r    ) * SPAD + ko + 8 + 2*tig]);
                ah[mi][3] = *reinterpret_cast<const uint32_t*>(&sAh[(r + 8) * SPAD + ko + 8 + 2*tig]);
                al[mi][0] = *reinterpret_cast<const uint32_t*>(&sAl[(r    ) * SPAD + ko     + 2*tig]);
                al[mi][1] = *reinterpret_cast<const uint32_t*>(&sAl[(r + 8) * SPAD + ko     + 2*tig]);
                al[mi][2] = *reinterpret_cast<const uint32_t*>(&sAl[(r    ) * SPAD + ko + 8 + 2*tig]);
                al[mi][3] = *reinterpret_cast<const uint32_t*>(&sAl[(r + 8) * SPAD + ko + 8 + 2*tig]);
            }
#pragma unroll
            for (int ni = 0; ni < 8; ni++) {
                const int c = wn + ni * 8 + gq;
                const uint32_t bh0 = *reinterpret_cast<const uint32_t*>(&sBh[c * SPAD + ko     + 2*tig]);
                const uint32_t bh1 = *reinterpret_cast<const uint32_t*>(&sBh[c * SPAD + ko + 8 + 2*tig]);
                const uint32_t bl0 = *reinterpret_cast<const uint32_t*>(&sBl[c * SPAD + ko     + 2*tig]);
                const uint32_t bl1 = *reinterpret_cast<const uint32_t*>(&sBl[c * SPAD + ko + 8 + 2*tig]);
#pragma unroll
                for (int mi = 0; mi < 2; mi++) {
                    mma16816(acc[mi][ni], ah[mi], bh0, bh1);
                    mma16816(acc[mi][ni], ah[mi], bl0, bl1);
                    mma16816(acc[mi][ni], al[mi], bh0, bh1);
                }
            }
        }
        __syncthreads();
    }

    float* sc = g_sc + (size_t)bh * SEQ * SEQ;
#pragma unroll
    for (int mi = 0; mi < 2; mi++) {
#pragma unroll
        for (int h2 = 0; h2 < 2; h2++) {
            const int ii = i0 + wm + mi * 16 + gq + h2 * 8;
            if (ii >= SEQ) continue;
#pragma unroll
            for (int ni = 0; ni < 8; ni++) {
                const int jj = j0 + wn + ni * 8 + 2 * tig;
                if (jj < SEQ)     sc[(size_t)ii * SEQ + jj]     = acc[mi][ni][h2*2+0] * SCALEF;
                if (jj + 1 < SEQ) sc[(size_t)ii * SEQ + jj + 1] = acc[mi][ni][h2*2+1] * SCALEF;
            }
        }
    }
}

/* ---------------- top-k stages (exact fp32) ------------------------ */
__global__ __launch_bounds__(256) void topk_qc(const float* __restrict__ x,
                                               const float* __restrict__ w)
{
    __shared__ float xc[CDIM];
    const int b  = blockIdx.x;
    const int jt = blockIdx.y;
    const int t  = threadIdx.x;
    const int lane = t & 31, wrp = t >> 5;

    for (int i = t; i < CDIM; i += 256) xc[i] = x[(size_t)(b * SEQ) * CDIM + i];
    __syncthreads();

#pragma unroll
    for (int jj = 0; jj < 8; jj++) {
        const int j = jt * 64 + wrp * 8 + jj;
        const float* wr = w + (size_t)j * CDIM;
        float s = 0.f;
#pragma unroll
        for (int c4 = 0; c4 < 6; c4++) {
            const int c = (c4 * 32 + lane) * 4;
            const float4 wv = *reinterpret_cast<const float4*>(&wr[c]);
            s += wv.x * xc[c] + wv.y * xc[c+1] + wv.z * xc[c+2] + wv.w * xc[c+3];
        }
#pragma unroll
        for (int off = 16; off > 0; off >>= 1)
            s += __shfl_xor_sync(0xffffffffu, s, off);
        if (lane == 0) g_qc[b * CDIM + j] = s;
    }
}

__global__ __launch_bounds__(256) void topk_u(const float* __restrict__ w)
{
    __shared__ float qh[HD];
    const int b = blockIdx.x, h = blockIdx.y;
    const int t = threadIdx.x;
    if (t < HD) qh[t] = g_qc[b * CDIM + h * HD + t];
    __syncthreads();

    const float* wk = w + (size_t)(CDIM + h * HD) * CDIM;
#pragma unroll
    for (int cc = 0; cc < 3; cc++) {
        const int c = cc * 256 + t;
        float s = 0.f;
#pragma unroll 16
        for (int d = 0; d < HD; d++) s += wk[(size_t)d * CDIM + c] * qh[d];
        g_u[((size_t)b * NH + h) * CDIM + c] = s;
    }
}

__global__ __launch_bounds__(256) void topk_wt(const float* __restrict__ x)
{
    const int b = blockIdx.x;
    const int t = threadIdx.x;
    const int lane = t & 31, wrp = t >> 5;
    const int m = blockIdx.y * 8 + wrp;
    if (m >= SEQ) return;

    const float* xr = x + (size_t)(b * SEQ + m) * CDIM;
    float4 xv[6];
#pragma unroll
    for (int c4 = 0; c4 < 6; c4++)
        xv[c4] = *reinterpret_cast<const float4*>(&xr[(c4 * 32 + lane) * 4]);

    const float* ub = g_u + (size_t)b * NH * CDIM;
    float tot = 0.f;
#pragma unroll
    for (int h = 0; h < NH; h++) {
        const float* ur = ub + h * CDIM;
        float s = 0.f;
#pragma unroll
        for (int c4 = 0; c4 < 6; c4++) {
            const int c = (c4 * 32 + lane) * 4;
            const float4 uv = *reinterpret_cast<const float4*>(&ur[c]);
            s += uv.x * xv[c4].x + uv.y * xv[c4].y + uv.z * xv[c4].z + uv.w * xv[c4].w;
        }
#pragma unroll
        for (int off = 16; off > 0; off >>= 1)
            s += __shfl_xor_sync(0xffffffffu, s, off);
        tot += fabsf(s);
    }
    if (lane == 0) g_wt[b * SEQ + m] = tot;
}

__global__ __launch_bounds__(256) void topk_emit(float* __restrict__ out_keep,
                                                 int write_keep)
{
    __shared__ float wt[SEQ];
    __shared__ unsigned char keep[SEQ];
    const int b = blockIdx.x, t = threadIdx.x;

    if (t < SEQ) wt[t] = g_wt[b * SEQ + t];
    __syncthreads();
    if (t < SEQ) {
        const float wi = wt[t];
        int cnt = 0;
        for (int j = 0; j < SEQ; j++) {
            const float wj = wt[j];
            cnt += (wj > wi) || (wj == wi && j < t);
        }
        keep[t] = (cnt < KEEP) ? 1 : 0;
    }
    __syncthreads();
    if (write_keep && t < SEQ && keep[t]) {
        int pos = 0;
        for (int j = 0; j < t; j++) pos += keep[j];
        out_keep[b * KEEP + pos] = (float)t;
    }
}

/* ---------------- K4: softmax (fp32) + PV via HMMA split-bf16 ------ */
/* block = (bh, 128-row tile). smem: P hi/lo [128][228] + V^T hi/lo   */
/* [64][228]. PV = P @ (V^T)^T, K-dim = n padded to 224 (14 k16).    */
__global__ __launch_bounds__(256, 1) void av_hmma()
{
    extern __shared__ __nv_bfloat16 smb[];
    __nv_bfloat16* sPh  = smb;
    __nv_bfloat16* sPl  = smb + 128 * PPITCH;
    __nv_bfloat16* sVth = smb + 256 * PPITCH;
    __nv_bfloat16* sVtl = smb + 320 * PPITCH;

    const int bh   = blockIdx.x;
    const int b    = bh / NH, h = bh % NH;
    const int row0 = blockIdx.y * 128;
    const int t    = threadIdx.x;
    const int lane = t & 31;
    const int w    = t >> 5;

    /* stage V^T (unpack hi/lo); pad cols read 0 from zero-init global */
    const uint32_t* vt = g_vt + (size_t)bh * HD * SEQP;
#pragma unroll
    for (int dd = 0; dd < 8; dd++) {
        const int d = w * 8 + dd;
#pragma unroll
        for (int i = 0; i < 8; i++) {
            const int n = lane + i * 32;
            if (n < SEQP) {
                const uint32_t p = vt[d * SEQP + n];
                sVth[d * PPITCH + n] = __ushort_as_bfloat16((unsigned short)(p & 0xffffu));
                sVtl[d * PPITCH + n] = __ushort_as_bfloat16((unsigned short)(p >> 16));
            }
        }
    }

    /* softmax: warp w handles rows w*16 .. w*16+15; emit P hi/lo bf16 */
    const float* scb = g_sc + (size_t)bh * SEQ * SEQ;
#pragma unroll 1
    for (int r8 = 0; r8 < 16; r8++) {
        const int sr = w * 16 + r8;
        const int r  = row0 + sr;
        float vals[7];
        float inv = 0.f;
        if (r < SEQ) {
            const float* row = scb + (size_t)r * SEQ;
            float mx = -1e30f;
#pragma unroll
            for (int i = 0; i < 7; i++) {
                const int m = lane + i * 32;
                vals[i] = (m < SEQ) ? row[m] : -1e30f;
                mx = fmaxf(mx, vals[i]);
            }
#pragma unroll
            for (int off = 16; off > 0; off >>= 1)
                mx = fmaxf(mx, __shfl_xor_sync(0xffffffffu, mx, off));
            float s = 0.f;
#pragma unroll
            for (int i = 0; i < 7; i++) {
                const int m = lane + i * 32;
                const float e = (m < SEQ) ? __expf(vals[i] - mx) : 0.f;
                vals[i] = e;
                s += e;
            }
#pragma unroll
            for (int off = 16; off > 0; off >>= 1)
                s += __shfl_xor_sync(0xffffffffu, s, off);
            inv = 1.f / s;
        }
#pragma unroll
        for (int i = 0; i < 8; i++) {
            const int m = lane + i * 32;
            if (m < PPITCH) {
                float pv = (r < SEQ && i < 7 && m < SEQ) ? vals[i] * inv : 0.f;
                __nv_bfloat16 ph = __float2bfloat16(pv);
                __nv_bfloat16 pl = __float2bfloat16(pv - __bfloat162float(ph));
                sPh[sr * PPITCH + m] = ph;
                sPl[sr * PPITCH + m] = pl;
            }
        }
    }
    __syncthreads();

    /* PV: 8 warps; warp tile = 32 rows x 32 cols */
    const int gq = lane >> 2, tig = lane & 3;
    const int wm = (w & 3) * 32;
    const int wn = (w >> 2) * 32;

    float acc[2][4][4];
#pragma unroll
    for (int mi = 0; mi < 2; mi++)
#pragma unroll
        for (int ni = 0; ni < 4; ni++)
#pragma unroll
            for (int r = 0; r < 4; r++) acc[mi][ni][r] = 0.f;

#pragma unroll 2
    for (int ks = 0; ks < 14; ks++) {
        const int ko = ks * 16;
        uint32_t ah[2][4], al[2][4];
#pragma unroll
        for (int mi = 0; mi < 2; mi++) {
            const int r = wm + mi * 16 + gq;
            ah[mi][0] = *reinterpret_cast<const uint32_t*>(&sPh[(r    ) * PPITCH + ko     + 2*tig]);
            ah[mi][1] = *reinterpret_cast<const uint32_t*>(&sPh[(r + 8) * PPITCH + ko     + 2*tig]);
            ah[mi][2] = *reinterpret_cast<const uint32_t*>(&sPh[(r    ) * PPITCH + ko + 8 + 2*tig]);
            ah[mi][3] = *reinterpret_cast<const uint32_t*>(&sPh[(r + 8) * PPITCH + ko + 8 + 2*tig]);
            al[mi][0] = *reinterpret_cast<const uint32_t*>(&sPl[(r    ) * PPITCH + ko     + 2*tig]);
            al[mi][1] = *reinterpret_cast<const uint32_t*>(&sPl[(r + 8) * PPITCH + ko     + 2*tig]);
            al[mi][2] = *reinterpret_cast<const uint32_t*>(&sPl[(r    ) * PPITCH + ko + 8 + 2*tig]);
            al[mi][3] = *reinterpret_cast<const uint32_t*>(&sPl[(r + 8) * PPITCH + ko + 8 + 2*tig]);
        }
#pragma unroll
        for (int ni = 0; ni < 4; ni++) {
            const int c = wn + ni * 8 + gq;
            const uint32_t bh0 = *reinterpret_cast<const uint32_t*>(&sVth[c * PPITCH + ko     + 2*tig]);
            const uint32_t bh1 = *reinterpret_cast<const uint32_t*>(&sVth[c * PPITCH + ko + 8 + 2*tig]);
            const uint32_t bl0 = *reinterpret_cast<const uint32_t*>(&sVtl[c * PPITCH + ko     + 2*tig]);
            const uint32_t bl1 = *reinterpret_cast<const uint32_t*>(&sVtl[c * PPITCH + ko + 8 + 2*tig]);
#pragma unroll
            for (int mi = 0; mi < 2; mi++) {
                mma16816(acc[mi][ni], ah[mi], bh0, bh1);
                mma16816(acc[mi][ni], ah[mi], bl0, bl1);
                mma16816(acc[mi][ni], al[mi], bh0, bh1);
            }
        }
    }

    /* emit ctx as bf16 hi/lo (proj GEMM input format) */
#pragma unroll
    for (int mi = 0; mi < 2; mi++) {
#pragma unroll
        for (int h2 = 0; h2 < 2; h2++) {
            const int r = row0 + wm + mi * 16 + gq + h2 * 8;
            if (r >= SEQ) continue;
#pragma unroll
            for (int ni = 0; ni < 4; ni++) {
                const int col = wn + ni * 8 + 2 * tig;
                const size_t off = (size_t)(b * SEQ + r) * CDIM + h * HD + col;
                uint32_t lo, hi = pack_hi_lo(acc[mi][ni][h2*2+0], acc[mi][ni][h2*2+1], &lo);
                *reinterpret_cast<uint32_t*>(&g_cth[off]) = hi;
                *reinterpret_cast<uint32_t*>(&g_ctl[off]) = lo;
            }
        }
    }
}

/* ------------------------------------------------------------------ */
extern "C" void kernel_launch(void* const* d_in, const int* in_sizes, int n_in,
                              void* d_out, int out_size)
{
    const float* x      = (const float*)d_in[0];
    const float* qkv_w  = (const float*)d_in[1];
    const float* proj_w = (const float*)d_in[2];
    const float* proj_b = (const float*)d_in[3];
    float* out = (float*)d_out;

    const int av_smem = 384 * PPITCH * (int)sizeof(__nv_bfloat16); /* 175104 B */
    cudaFuncSetAttribute(av_hmma, cudaFuncAttributeMaxDynamicSharedMemorySize, av_smem);

    /* splits */
    split_kernel<<<(TOK*CDIM + 255)/256, 256>>>(x, 0, TOK*CDIM);
    split_kernel<<<(3*CDIM*CDIM + 255)/256, 256>>>(qkv_w, 1, 3*CDIM*CDIM);
    split_kernel<<<(CDIM*CDIM + 255)/256, 256>>>(proj_w, 2, CDIM*CDIM);

    /* exact fp32 top-k (decoupled from bf16 path) */
    const int write_keep = (out_size >= TOK * CDIM + BSZ * KEEP) ? 1 : 0;
    topk_qc  <<<dim3(BSZ, 12), 256>>>(x, qkv_w);
    topk_u   <<<dim3(BSZ, NH), 256>>>(qkv_w);
    topk_wt  <<<dim3(BSZ, (SEQ + 7) / 8), 256>>>(x);
    topk_emit<<<BSZ, 256>>>(out + (size_t)TOK * CDIM, write_keep);

    /* QKV via HMMA split-bf16; q,k bf16 hi/lo, V transposed+packed */
    hmma_gemm<<<dim3(3*CDIM/NT, (TOK + MT - 1)/MT), 256>>>(0, nullptr, nullptr);

    /* scores via HMMA split-bf16 */
    score_hmma<<<dim3(2, 2, BH), 256>>>();

    /* softmax + PV via HMMA */
    av_hmma<<<dim3(BH, 2), 256, av_smem>>>();

    /* proj via HMMA split-bf16 (reads ctx hi/lo written by av) */
    hmma_gemm<<<dim3(CDIM/NT, (TOK + MT - 1)/MT), 256>>>(1, proj_b, out);
}

// round 9
// speedup vs baseline: 3.1734x; 1.0431x over previous
#include <cuda_runtime.h>
#include <cuda_bf16.h>
#include <math.h>
#include <stdint.h>

#define BSZ   64
#define SEQ   197
#define CDIM  768
#define NH    12
#define HD    64
#define KEEP  160
#define SCALEF 0.125f

#define BH   (BSZ*NH)
#define TOK  (BSZ*SEQ)

#define SEQP   228
#define PPITCH 228

/* ---------------- scratch (device globals; no allocs allowed) ------ */
__device__ float g_sc[BH*SEQ*SEQ];

__device__ __nv_bfloat16 g_qh[BH*SEQ*HD], g_ql[BH*SEQ*HD];
__device__ __nv_bfloat16 g_kh[BH*SEQ*HD], g_kl[BH*SEQ*HD];
__device__ uint32_t      g_vt[BH*HD*SEQP];

__device__ __nv_bfloat16 g_xh[TOK*CDIM],  g_xl[TOK*CDIM];
__device__ __nv_bfloat16 g_wqh[3*CDIM*CDIM], g_wql[3*CDIM*CDIM];
__device__ __nv_bfloat16 g_wph[CDIM*CDIM],   g_wpl[CDIM*CDIM];
__device__ __nv_bfloat16 g_cth[TOK*CDIM], g_ctl[TOK*CDIM];

/* top-k staging */
__device__ float g_qc[BSZ*CDIM];
__device__ float g_u [BSZ*NH*CDIM];
__device__ float g_wt[BSZ*SEQ];

/* ---------------- helpers ------------------------------------------ */
__device__ __forceinline__ uint32_t pack_hi_lo(float v0, float v1, uint32_t* lo)
{
    __nv_bfloat16 h0 = __float2bfloat16(v0);
    __nv_bfloat16 h1 = __float2bfloat16(v1);
    __nv_bfloat16 l0 = __float2bfloat16(v0 - __bfloat162float(h0));
    __nv_bfloat16 l1 = __float2bfloat16(v1 - __bfloat162float(h1));
    uint32_t hi = ((uint32_t)__bfloat16_as_ushort(h1) << 16) | __bfloat16_as_ushort(h0);
    *lo         = ((uint32_t)__bfloat16_as_ushort(l1) << 16) | __bfloat16_as_ushort(l0);
    return hi;
}
__device__ __forceinline__ uint32_t pack_v(float v)
{
    __nv_bfloat16 h = __float2bfloat16(v);
    __nv_bfloat16 l = __float2bfloat16(v - __bfloat162float(h));
    return (uint32_t)__bfloat16_as_ushort(h) | ((uint32_t)__bfloat16_as_ushort(l) << 16);
}

#define CP_ASYNC16(dst, src) \
    asm volatile("cp.async.cg.shared.global [%0], [%1], 16;" :: "r"(dst), "l"(src))
#define CP_COMMIT() asm volatile("cp.async.commit_group;" ::: "memory")
#define CP_WAIT(n)  asm volatile("cp.async.wait_group %0;" :: "n"(n) : "memory")

/* ---------------- split fp32 -> bf16 hi/lo ------------------------- */
__global__ void split_kernel(const float* __restrict__ src, int which, int n)
{
    int i = blockIdx.x * 256 + threadIdx.x;
    if (i >= n) return;
    __nv_bfloat16 *hi, *lo;
    if      (which == 0) { hi = g_xh;  lo = g_xl;  }
    else if (which == 1) { hi = g_wqh; lo = g_wql; }
    else                 { hi = g_wph; lo = g_wpl; }
    float v = src[i];
    __nv_bfloat16 h = __float2bfloat16(v);
    hi[i] = h;
    lo[i] = __float2bfloat16(v - __bfloat162float(h));
}

/* ---------------- HMMA primitives ---------------------------------- */
#define MT 128
#define NT 128
#define KPAN 32
#define SPAD 40
#define TILEB (128*SPAD*2)   /* 10240 B per tile */
#define STAGEB (4*TILEB)     /* 40960 B per stage */

__device__ __forceinline__ void mma16816(float* c, const uint32_t* a,
                                         uint32_t b0, uint32_t b1)
{
    asm volatile(
        "mma.sync.aligned.m16n8k16.row.col.f32.bf16.bf16.f32 "
        "{%0,%1,%2,%3}, {%4,%5,%6,%7}, {%8,%9}, {%0,%1,%2,%3};"
        : "+f"(c[0]), "+f"(c[1]), "+f"(c[2]), "+f"(c[3])
        : "r"(a[0]), "r"(a[1]), "r"(a[2]), "r"(a[3]), "r"(b0), "r"(b1));
}

__device__ __forceinline__ void stage_tile(__nv_bfloat16* s,
        const __nv_bfloat16* __restrict__ g, int row0, int rowmax, int kb, int t)
{
#pragma unroll
    for (int i = 0; i < 2; i++) {
        const int idx = t + i * 256;
        const int row = idx >> 2;
        const int c8  = (idx & 3) * 8;
        int gr = row0 + row; if (gr > rowmax) gr = rowmax;
        uint4 v = *reinterpret_cast<const uint4*>(g + (size_t)gr * CDIM + kb + c8);
        *reinterpret_cast<uint4*>(s + row * SPAD + c8) = v;
    }
}

__device__ __forceinline__ void stage_async(uint32_t sbase,
        const __nv_bfloat16* __restrict__ g, int row0, int rowmax, int kb, int t)
{
#pragma unroll
    for (int i = 0; i < 2; i++) {
        const int idx = t + i * 256;
        const int row = idx >> 2;
        const int c8  = (idx & 3) * 8;
        int gr = row0 + row; if (gr > rowmax) gr = rowmax;
        CP_ASYNC16(sbase + (uint32_t)(row * SPAD + c8) * 2,
                   g + (size_t)gr * CDIM + kb + c8);
    }
}

__device__ __forceinline__ void stage_tile64(__nv_bfloat16* s,
        const __nv_bfloat16* __restrict__ g, int row0, int rowmax, int kb, int t)
{
#pragma unroll
    for (int i = 0; i < 2; i++) {
        const int idx = t + i * 256;
        const int row = idx >> 2;
        const int c8  = (idx & 3) * 8;
        int gr = row0 + row; if (gr > rowmax) gr = rowmax;
        uint4 v = *reinterpret_cast<const uint4*>(g + (size_t)gr * HD + kb + c8);
        *reinterpret_cast<uint4*>(s + row * SPAD + c8) = v;
    }
}

/* ---------------- K1/K5: big GEMMs, cp.async double-buffered ------- */
__global__ __launch_bounds__(256, 2) void hmma_gemm(int mode,
        const float* __restrict__ bias, float* __restrict__ outp)
{
    extern __shared__ __align__(16) char dynsm[];
    const uint32_t sb = (uint32_t)__cvta_generic_to_shared(dynsm);

    const int t    = threadIdx.x;
    const int wid  = t >> 5, lane = t & 31;
    const int gq   = lane >> 2, tig = lane & 3;
    const int wm   = (wid & 3) * 32;
    const int wn   = (wid >> 2) * 64;
    const int m0   = blockIdx.y * MT;
    const int n0   = blockIdx.x * NT;

    const __nv_bfloat16 *Ah, *Al, *Bh, *Bl;
    int brmax;
    if (mode == 0) { Ah = g_xh;  Al = g_xl;  Bh = g_wqh; Bl = g_wql; brmax = 3*CDIM - 1; }
    else           { Ah = g_cth; Al = g_ctl; Bh = g_wph; Bl = g_wpl; brmax = CDIM - 1;   }

    float acc[2][8][4];
#pragma unroll
    for (int mi = 0; mi < 2; mi++)
#pragma unroll
        for (int ni = 0; ni < 8; ni++)
#pragma unroll
            for (int r = 0; r < 4; r++) acc[mi][ni][r] = 0.f;

    /* prologue: stage panel 0 into buffer 0 */
    stage_async(sb + 0*TILEB, Ah, m0, TOK - 1, 0, t);
    stage_async(sb + 1*TILEB, Al, m0, TOK - 1, 0, t);
    stage_async(sb + 2*TILEB, Bh, n0, brmax,   0, t);
    stage_async(sb + 3*TILEB, Bl, n0, brmax,   0, t);
    CP_COMMIT();

    const int NP = CDIM / KPAN;
    for (int p = 0; p < NP; p++) {
        if (p + 1 < NP) {
            const uint32_t nb = sb + ((p + 1) & 1) * STAGEB;
            const int kb = (p + 1) * KPAN;
            stage_async(nb + 0*TILEB, Ah, m0, TOK - 1, kb, t);
            stage_async(nb + 1*TILEB, Al, m0, TOK - 1, kb, t);
            stage_async(nb + 2*TILEB, Bh, n0, brmax,   kb, t);
            stage_async(nb + 3*TILEB, Bl, n0, brmax,   kb, t);
            CP_COMMIT();
            CP_WAIT(1);
        } else {
            CP_WAIT(0);
        }
        __syncthreads();

        const char* cbuf = dynsm + (p & 1) * STAGEB;
        const __nv_bfloat16* sAh = (const __nv_bfloat16*)(cbuf + 0*TILEB);
        const __nv_bfloat16* sAl = (const __nv_bfloat16*)(cbuf + 1*TILEB);
        const __nv_bfloat16* sBh = (const __nv_bfloat16*)(cbuf + 2*TILEB);
        const __nv_bfloat16* sBl = (const __nv_bfloat16*)(cbuf + 3*TILEB);

#pragma unroll
        for (int ks = 0; ks < 2; ks++) {
            const int ko = ks * 16;
            uint32_t ah[2][4], al[2][4];
#pragma unroll
            for (int mi = 0; mi < 2; mi++) {
                const int r = wm + mi * 16 + gq;
                ah[mi][0] = *reinterpret_cast<const uint32_t*>(&sAh[(r    ) * SPAD + ko     + 2*tig]);
                ah[mi][1] = *reinterpret_cast<const uint32_t*>(&sAh[(r + 8) * SPAD + ko     + 2*tig]);
                ah[mi][2] = *reinterpret_cast<const uint32_t*>(&sAh[(r    ) * SPAD + ko + 8 + 2*tig]);
                ah[mi][3] = *reinterpret_cast<const uint32_t*>(&sAh[(r + 8) * SPAD + ko + 8 + 2*tig]);
                al[mi][0] = *reinterpret_cast<const uint32_t*>(&sAl[(r    ) * SPAD + ko     + 2*tig]);
                al[mi][1] = *reinterpret_cast<const uint32_t*>(&sAl[(r + 8) * SPAD + ko     + 2*tig]);
                al[mi][2] = *reinterpret_cast<const uint32_t*>(&sAl[(r    ) * SPAD + ko + 8 + 2*tig]);
                al[mi][3] = *reinterpret_cast<const uint32_t*>(&sAl[(r + 8) * SPAD + ko + 8 + 2*tig]);
            }
#pragma unroll
            for (int ni = 0; ni < 8; ni++) {
                const int c = wn + ni * 8 + gq;
                const uint32_t bh0 = *reinterpret_cast<const uint32_t*>(&sBh[c * SPAD + ko     + 2*tig]);
                const uint32_t bh1 = *reinterpret_cast<const uint32_t*>(&sBh[c * SPAD + ko + 8 + 2*tig]);
                const uint32_t bl0 = *reinterpret_cast<const uint32_t*>(&sBl[c * SPAD + ko     + 2*tig]);
                const uint32_t bl1 = *reinterpret_cast<const uint32_t*>(&sBl[c * SPAD + ko + 8 + 2*tig]);
#pragma unroll
                for (int mi = 0; mi < 2; mi++) {
                    mma16816(acc[mi][ni], ah[mi], bh0, bh1);
                    mma16816(acc[mi][ni], ah[mi], bl0, bl1);
                    mma16816(acc[mi][ni], al[mi], bh0, bh1);
                }
            }
        }
        __syncthreads();
    }

#pragma unroll
    for (int mi = 0; mi < 2; mi++) {
#pragma unroll
        for (int h2 = 0; h2 < 2; h2++) {
            const int m = m0 + wm + mi * 16 + gq + h2 * 8;
            if (m >= TOK) continue;
#pragma unroll
            for (int ni = 0; ni < 8; ni++) {
                const int col = n0 + wn + ni * 8 + 2 * tig;
                const float v0 = acc[mi][ni][h2 * 2 + 0];
                const float v1 = acc[mi][ni][h2 * 2 + 1];
                if (mode == 1) {
                    float2 o = make_float2(v0 + bias[col], v1 + bias[col + 1]);
                    *reinterpret_cast<float2*>(&outp[(size_t)m * CDIM + col]) = o;
                } else {
                    const int s  = col / CDIM;
                    const int rm = col % CDIM;
                    const int h  = rm / HD, dd = rm % HD;
                    const int bidx = m / SEQ, n = m % SEQ;
                    if (s == 2) {
                        const size_t vo = ((size_t)(bidx * NH + h) * HD + dd) * SEQP + n;
                        g_vt[vo]        = pack_v(v0);
                        g_vt[vo + SEQP] = pack_v(v1);
                    } else {
                        const size_t off = ((size_t)(bidx * NH + h) * SEQ + n) * HD + dd;
                        uint32_t lo, hi = pack_hi_lo(v0, v1, &lo);
                        __nv_bfloat16 *dh = (s == 0) ? g_qh : g_kh;
                        __nv_bfloat16 *dl = (s == 0) ? g_ql : g_kl;
                        *reinterpret_cast<uint32_t*>(&dh[off]) = hi;
                        *reinterpret_cast<uint32_t*>(&dl[off]) = lo;
                    }
                }
            }
        }
    }
}

/* ---------------- K2: scores via HMMA split-bf16 ------------------- */
__global__ __launch_bounds__(256, 2) void score_hmma()
{
    __shared__ __align__(16) __nv_bfloat16 sAh[128*SPAD];
    __shared__ __align__(16) __nv_bfloat16 sAl[128*SPAD];
    __shared__ __align__(16) __nv_bfloat16 sBh[128*SPAD];
    __shared__ __align__(16) __nv_bfloat16 sBl[128*SPAD];

    const int t    = threadIdx.x;
    const int wid  = t >> 5, lane = t & 31;
    const int gq   = lane >> 2, tig = lane & 3;
    const int wm   = (wid & 3) * 32;
    const int wn   = (wid >> 2) * 64;
    const int bh   = blockIdx.z;
    const int i0   = blockIdx.y * MT;
    const int j0   = blockIdx.x * NT;

    const size_t base = (size_t)bh * SEQ * HD;
    const __nv_bfloat16 *Qh = g_qh + base, *Ql = g_ql + base;
    const __nv_bfloat16 *Kh = g_kh + base, *Kl = g_kl + base;

    float acc[2][8][4];
#pragma unroll
    for (int mi = 0; mi < 2; mi++)
#pragma unroll
        for (int ni = 0; ni < 8; ni++)
#pragma unroll
            for (int r = 0; r < 4; r++) acc[mi][ni][r] = 0.f;

#pragma unroll
    for (int p = 0; p < HD / KPAN; p++) {
        const int kb = p * KPAN;
        stage_tile64(sAh, Qh, i0, SEQ - 1, kb, t);
        stage_tile64(sAl, Ql, i0, SEQ - 1, kb, t);
        stage_tile64(sBh, Kh, j0, SEQ - 1, kb, t);
        stage_tile64(sBl, Kl, j0, SEQ - 1, kb, t);
        __syncthreads();

#pragma unroll
        for (int ks = 0; ks < 2; ks++) {
            const int ko = ks * 16;
            uint32_t ah[2][4], al[2][4];
#pragma unroll
            for (int mi = 0; mi < 2; mi++) {
                const int r = wm + mi * 16 + gq;
                ah[mi][0] = *reinterpret_cast<const uint32_t*>(&sAh[(r    ) * SPAD + ko     + 2*tig]);
                ah[mi][1] = *reinterpret_cast<const uint32_t*>(&sAh[(r + 8) * SPAD + ko     + 2*tig]);
                ah[mi][2] = *reinterpret_cast<const uint32_t*>(&sAh[(r    ) * SPAD + ko + 8 + 2*tig]);
                ah[mi][3] = *reinterpret_cast<const uint32_t*>(&sAh[(r + 8) * SPAD + ko + 8 + 2*tig]);
                al[mi][0] = *reinterpret_cast<const uint32_t*>(&sAl[(r    ) * SPAD + ko     + 2*tig]);
                al[mi][1] = *reinterpret_cast<const uint32_t*>(&sAl[(r + 8) * SPAD + ko     + 2*tig]);
                al[mi][2] = *reinterpret_cast<const uint32_t*>(&sAl[(r    ) * SPAD + ko + 8 + 2*tig]);
                al[mi][3] = *reinterpret_cast<const uint32_t*>(&sAl[(r + 8) * SPAD + ko + 8 + 2*tig]);
            }
#pragma unroll
            for (int ni = 0; ni < 8; ni++) {
                const int c = wn + ni * 8 + gq;
                const uint32_t bh0 = *reinterpret_cast<const uint32_t*>(&sBh[c * SPAD + ko     + 2*tig]);
                const uint32_t bh1 = *reinterpret_cast<const uint32_t*>(&sBh[c * SPAD + ko + 8 + 2*tig]);
                const uint32_t bl0 = *reinterpret_cast<const uint32_t*>(&sBl[c * SPAD + ko     + 2*tig]);
                const uint32_t bl1 = *reinterpret_cast<const uint32_t*>(&sBl[c * SPAD + ko + 8 + 2*tig]);
#pragma unroll
                for (int mi = 0; mi < 2; mi++) {
                    mma16816(acc[mi][ni], ah[mi], bh0, bh1);
                    mma16816(acc[mi][ni], ah[mi], bl0, bl1);
                    mma16816(acc[mi][ni], al[mi], bh0, bh1);
                }
            }
        }
        __syncthreads();
    }

    float* sc = g_sc + (size_t)bh * SEQ * SEQ;
#pragma unroll
    for (int mi = 0; mi < 2; mi++) {
#pragma unroll
        for (int h2 = 0; h2 < 2; h2++) {
            const int ii = i0 + wm + mi * 16 + gq + h2 * 8;
            if (ii >= SEQ) continue;
#pragma unroll
            for (int ni = 0; ni < 8; ni++) {
                const int jj = j0 + wn + ni * 8 + 2 * tig;
                if (jj < SEQ)     sc[(size_t)ii * SEQ + jj]     = acc[mi][ni][h2*2+0] * SCALEF;
                if (jj + 1 < SEQ) sc[(size_t)ii * SEQ + jj + 1] = acc[mi][ni][h2*2+1] * SCALEF;
            }
        }
    }
}

/* ---------------- top-k stages (exact fp32) ------------------------ */
__global__ __launch_bounds__(256) void topk_qc(const float* __restrict__ x,
                                               const float* __restrict__ w)
{
    __shared__ float xc[CDIM];
    const int b  = blockIdx.x;
    const int jt = blockIdx.y;
    const int t  = threadIdx.x;
    const int lane = t & 31, wrp = t >> 5;

    for (int i = t; i < CDIM; i += 256) xc[i] = x[(size_t)(b * SEQ) * CDIM + i];
    __syncthreads();

#pragma unroll
    for (int jj = 0; jj < 8; jj++) {
        const int j = jt * 64 + wrp * 8 + jj;
        const float* wr = w + (size_t)j * CDIM;
        float s = 0.f;
#pragma unroll
        for (int c4 = 0; c4 < 6; c4++) {
            const int c = (c4 * 32 + lane) * 4;
            const float4 wv = *reinterpret_cast<const float4*>(&wr[c]);
            s += wv.x * xc[c] + wv.y * xc[c+1] + wv.z * xc[c+2] + wv.w * xc[c+3];
        }
#pragma unroll
        for (int off = 16; off > 0; off >>= 1)
            s += __shfl_xor_sync(0xffffffffu, s, off);
        if (lane == 0) g_qc[b * CDIM + j] = s;
    }
}

__global__ __launch_bounds__(256) void topk_u(const float* __restrict__ w)
{
    __shared__ float qh[HD];
    const int b = blockIdx.x, h = blockIdx.y;
    const int t = threadIdx.x;
    if (t < HD) qh[t] = g_qc[b * CDIM + h * HD + t];
    __syncthreads();

    const float* wk = w + (size_t)(CDIM + h * HD) * CDIM;
#pragma unroll
    for (int cc = 0; cc < 3; cc++) {
        const int c = cc * 256 + t;
        float s = 0.f;
#pragma unroll 16
        for (int d = 0; d < HD; d++) s += wk[(size_t)d * CDIM + c] * qh[d];
        g_u[((size_t)b * NH + h) * CDIM + c] = s;
    }
}

__global__ __launch_bounds__(256) void topk_wt(const float* __restrict__ x)
{
    const int b = blockIdx.x;
    const int t = threadIdx.x;
    const int lane = t & 31, wrp = t >> 5;
    const int m = blockIdx.y * 8 + wrp;
    if (m >= SEQ) return;

    const float* xr = x + (size_t)(b * SEQ + m) * CDIM;
    float4 xv[6];
#pragma unroll
    for (int c4 = 0; c4 < 6; c4++)
        xv[c4] = *reinterpret_cast<const float4*>(&xr[(c4 * 32 + lane) * 4]);

    const float* ub = g_u + (size_t)b * NH * CDIM;
    float tot = 0.f;
#pragma unroll
    for (int h = 0; h < NH; h++) {
        const float* ur = ub + h * CDIM;
        float s = 0.f;
#pragma unroll
        for (int c4 = 0; c4 < 6; c4++) {
            const int c = (c4 * 32 + lane) * 4;
            const float4 uv = *reinterpret_cast<const float4*>(&ur[c]);
            s += uv.x * xv[c4].x + uv.y * xv[c4].y + uv.z * xv[c4].z + uv.w * xv[c4].w;
        }
#pragma unroll
        for (int off = 16; off > 0; off >>= 1)
            s += __shfl_xor_sync(0xffffffffu, s, off);
        tot += fabsf(s);
    }
    if (lane == 0) g_wt[b * SEQ + m] = tot;
}

__global__ __launch_bounds__(256) void topk_emit(float* __restrict__ out_keep,
                                                 int write_keep)
{
    __shared__ float wt[SEQ];
    __shared__ unsigned char keep[SEQ];
    const int b = blockIdx.x, t = threadIdx.x;

    if (t < SEQ) wt[t] = g_wt[b * SEQ + t];
    __syncthreads();
    if (t < SEQ) {
        const float wi = wt[t];
        int cnt = 0;
        for (int j = 0; j < SEQ; j++) {
            const float wj = wt[j];
            cnt += (wj > wi) || (wj == wi && j < t);
        }
        keep[t] = (cnt < KEEP) ? 1 : 0;
    }
    __syncthreads();
    if (write_keep && t < SEQ && keep[t]) {
        int pos = 0;
        for (int j = 0; j < t; j++) pos += keep[j];
        out_keep[b * KEEP + pos] = (float)t;
    }
}

/* ---------------- K4: softmax (fp32) + PV via HMMA split-bf16 ------ */
__global__ __launch_bounds__(256, 1) void av_hmma()
{
    extern __shared__ __nv_bfloat16 smb[];
    __nv_bfloat16* sPh  = smb;
    __nv_bfloat16* sPl  = smb + 128 * PPITCH;
    __nv_bfloat16* sVth = smb + 256 * PPITCH;
    __nv_bfloat16* sVtl = smb + 320 * PPITCH;

    const int bh   = blockIdx.x;
    const int b    = bh / NH, h = bh % NH;
    const int row0 = blockIdx.y * 128;
    const int t    = threadIdx.x;
    const int lane = t & 31;
    const int w    = t >> 5;

    const uint32_t* vt = g_vt + (size_t)bh * HD * SEQP;
#pragma unroll
    for (int dd = 0; dd < 8; dd++) {
        const int d = w * 8 + dd;
#pragma unroll
        for (int i = 0; i < 8; i++) {
            const int n = lane + i * 32;
            if (n < SEQP) {
                const uint32_t p = vt[d * SEQP + n];
                sVth[d * PPITCH + n] = __ushort_as_bfloat16((unsigned short)(p & 0xffffu));
                sVtl[d * PPITCH + n] = __ushort_as_bfloat16((unsigned short)(p >> 16));
            }
        }
    }

    const float* scb = g_sc + (size_t)bh * SEQ * SEQ;
#pragma unroll 1
    for (int r8 = 0; r8 < 16; r8++) {
        const int sr = w * 16 + r8;
        const int r  = row0 + sr;
        float vals[7];
        float inv = 0.f;
        if (r < SEQ) {
            const float* row = scb + (size_t)r * SEQ;
            float mx = -1e30f;
#pragma unroll
            for (int i = 0; i < 7; i++) {
                const int m = lane + i * 32;
                vals[i] = (m < SEQ) ? row[m] : -1e30f;
                mx = fmaxf(mx, vals[i]);
            }
#pragma unroll
            for (int off = 16; off > 0; off >>= 1)
                mx = fmaxf(mx, __shfl_xor_sync(0xffffffffu, mx, off));
            float s = 0.f;
#pragma unroll
            for (int i = 0; i < 7; i++) {
                const int m = lane + i * 32;
                const float e = (m < SEQ) ? __expf(vals[i] - mx) : 0.f;
                vals[i] = e;
                s += e;
            }
#pragma unroll
            for (int off = 16; off > 0; off >>= 1)
                s += __shfl_xor_sync(0xffffffffu, s, off);
            inv = 1.f / s;
        }
#pragma unroll
        for (int i = 0; i < 8; i++) {
            const int m = lane + i * 32;
            if (m < PPITCH) {
                float pv = (r < SEQ && i < 7 && m < SEQ) ? vals[i] * inv : 0.f;
                __nv_bfloat16 ph = __float2bfloat16(pv);
                __nv_bfloat16 pl = __float2bfloat16(pv - __bfloat162float(ph));
                sPh[sr * PPITCH + m] = ph;
                sPl[sr * PPITCH + m] = pl;
            }
        }
    }
    __syncthreads();

    const int gq = lane >> 2, tig = lane & 3;
    const int wm = (w & 3) * 32;
    const int wn = (w >> 2) * 32;

    float acc[2][4][4];
#pragma unroll
    for (int mi = 0; mi < 2; mi++)
#pragma unroll
        for (int ni = 0; ni < 4; ni++)
#pragma unroll
            for (int r = 0; r < 4; r++) acc[mi][ni][r] = 0.f;

#pragma unroll 2
    for (int ks = 0; ks < 14; ks++) {
        const int ko = ks * 16;
        uint32_t ah[2][4], al[2][4];
#pragma unroll
        for (int mi = 0; mi < 2; mi++) {
            const int r = wm + mi * 16 + gq;
            ah[mi][0] = *reinterpret_cast<const uint32_t*>(&sPh[(r    ) * PPITCH + ko     + 2*tig]);
            ah[mi][1] = *reinterpret_cast<const uint32_t*>(&sPh[(r + 8) * PPITCH + ko     + 2*tig]);
            ah[mi][2] = *reinterpret_cast<const uint32_t*>(&sPh[(r    ) * PPITCH + ko + 8 + 2*tig]);
            ah[mi][3] = *reinterpret_cast<const uint32_t*>(&sPh[(r + 8) * PPITCH + ko + 8 + 2*tig]);
            al[mi][0] = *reinterpret_cast<const uint32_t*>(&sPl[(r    ) * PPITCH + ko     + 2*tig]);
            al[mi][1] = *reinterpret_cast<const uint32_t*>(&sPl[(r + 8) * PPITCH + ko     + 2*tig]);
            al[mi][2] = *reinterpret_cast<const uint32_t*>(&sPl[(r    ) * PPITCH + ko + 8 + 2*tig]);
            al[mi][3] = *reinterpret_cast<const uint32_t*>(&sPl[(r + 8) * PPITCH + ko + 8 + 2*tig]);
        }
#pragma unroll
        for (int ni = 0; ni < 4; ni++) {
            const int c = wn + ni * 8 + gq;
            const uint32_t bh0 = *reinterpret_cast<const uint32_t*>(&sVth[c * PPITCH + ko     + 2*tig]);
            const uint32_t bh1 = *reinterpret_cast<const uint32_t*>(&sVth[c * PPITCH + ko + 8 + 2*tig]);
            const uint32_t bl0 = *reinterpret_cast<const uint32_t*>(&sVtl[c * PPITCH + ko     + 2*tig]);
            const uint32_t bl1 = *reinterpret_cast<const uint32_t*>(&sVtl[c * PPITCH + ko + 8 + 2*tig]);
#pragma unroll
            for (int mi = 0; mi < 2; mi++) {
                mma16816(acc[mi][ni], ah[mi], bh0, bh1);
                mma16816(acc[mi][ni], ah[mi], bl0, bl1);
                mma16816(acc[mi][ni], al[mi], bh0, bh1);
            }
        }
    }

#pragma unroll
    for (int mi = 0; mi < 2; mi++) {
#pragma unroll
        for (int h2 = 0; h2 < 2; h2++) {
            const int r = row0 + wm + mi * 16 + gq + h2 * 8;
            if (r >= SEQ) continue;
#pragma unroll
            for (int ni = 0; ni < 4; ni++) {
                const int col = wn + ni * 8 + 2 * tig;
                const size_t off = (size_t)(b * SEQ + r) * CDIM + h * HD + col;
                uint32_t lo, hi = pack_hi_lo(acc[mi][ni][h2*2+0], acc[mi][ni][h2*2+1], &lo);
                *reinterpret_cast<uint32_t*>(&g_cth[off]) = hi;
                *reinterpret_cast<uint32_t*>(&g_ctl[off]) = lo;
            }
        }
    }
}

/* ------------------------------------------------------------------ */
extern "C" void kernel_launch(void* const* d_in, const int* in_sizes, int n_in,
                              void* d_out, int out_size)
{
    const float* x      = (const float*)d_in[0];
    const float* qkv_w  = (const float*)d_in[1];
    const float* proj_w = (const float*)d_in[2];
    const float* proj_b = (const float*)d_in[3];
    float* out = (float*)d_out;

    const int av_smem   = 384 * PPITCH * (int)sizeof(__nv_bfloat16);
    const int gemm_smem = 2 * STAGEB;   /* 81920 B */
    cudaFuncSetAttribute(av_hmma,  cudaFuncAttributeMaxDynamicSharedMemorySize, av_smem);
    cudaFuncSetAttribute(hmma_gemm, cudaFuncAttributeMaxDynamicSharedMemorySize, gemm_smem);

    /* splits */
    split_kernel<<<(TOK*CDIM + 255)/256, 256>>>(x, 0, TOK*CDIM);
    split_kernel<<<(3*CDIM*CDIM + 255)/256, 256>>>(qkv_w, 1, 3*CDIM*CDIM);
    split_kernel<<<(CDIM*CDIM + 255)/256, 256>>>(proj_w, 2, CDIM*CDIM);

    /* exact fp32 top-k (decoupled from bf16 path) */
    const int write_keep = (out_size >= TOK * CDIM + BSZ * KEEP) ? 1 : 0;
    topk_qc  <<<dim3(BSZ, 12), 256>>>(x, qkv_w);
    topk_u   <<<dim3(BSZ, NH), 256>>>(qkv_w);
    topk_wt  <<<dim3(BSZ, (SEQ + 7) / 8), 256>>>(x);
    topk_emit<<<BSZ, 256>>>(out + (size_t)TOK * CDIM, write_keep);

    /* QKV via pipelined HMMA split-bf16 */
    hmma_gemm<<<dim3(3*CDIM/NT, (TOK + MT - 1)/MT), 256, gemm_smem>>>(0, nullptr, nullptr);

    /* scores via HMMA split-bf16 */
    score_hmma<<<dim3(2, 2, BH), 256>>>();

    /* softmax + PV via HMMA */
    av_hmma<<<dim3(BH, 2), 256, av_smem>>>();

    /* proj via pipelined HMMA split-bf16 */
    hmma_gemm<<<dim3(CDIM/NT, (TOK + MT - 1)/MT), 256, gemm_smem>>>(1, proj_b, out);
}

// round 10
// speedup vs baseline: 3.1783x; 1.0016x over previous
#include <cuda_runtime.h>
#include <cuda_bf16.h>
#include <math.h>
#include <stdint.h>

#define BSZ   64
#define SEQ   197
#define CDIM  768
#define NH    12
#define HD    64
#define KEEP  160
#define SCALEF 0.125f

#define BH   (BSZ*NH)
#define TOK  (BSZ*SEQ)

#define SEQP   228   /* global V^T pitch (u32 elems)                  */
#define PPITCH 232   /* smem pitch for P/V^T: 464B = 29*16B, LDSM ok  */

/* ---------------- scratch (device globals; no allocs allowed) ------ */
__device__ float g_sc[BH*SEQ*SEQ];

__device__ __nv_bfloat16 g_qh[BH*SEQ*HD], g_ql[BH*SEQ*HD];
__device__ __nv_bfloat16 g_kh[BH*SEQ*HD], g_kl[BH*SEQ*HD];
__device__ uint32_t      g_vt[BH*HD*SEQP];

__device__ __nv_bfloat16 g_xh[TOK*CDIM],  g_xl[TOK*CDIM];
__device__ __nv_bfloat16 g_wqh[3*CDIM*CDIM], g_wql[3*CDIM*CDIM];
__device__ __nv_bfloat16 g_wph[CDIM*CDIM],   g_wpl[CDIM*CDIM];
__device__ __nv_bfloat16 g_cth[TOK*CDIM], g_ctl[TOK*CDIM];

/* top-k staging */
__device__ float g_qc[BSZ*CDIM];
__device__ float g_u [BSZ*NH*CDIM];
__device__ float g_wt[BSZ*SEQ];

/* ---------------- helpers ------------------------------------------ */
__device__ __forceinline__ uint32_t pack_hi_lo(float v0, float v1, uint32_t* lo)
{
    __nv_bfloat16 h0 = __float2bfloat16(v0);
    __nv_bfloat16 h1 = __float2bfloat16(v1);
    __nv_bfloat16 l0 = __float2bfloat16(v0 - __bfloat162float(h0));
    __nv_bfloat16 l1 = __float2bfloat16(v1 - __bfloat162float(h1));
    uint32_t hi = ((uint32_t)__bfloat16_as_ushort(h1) << 16) | __bfloat16_as_ushort(h0);
    *lo         = ((uint32_t)__bfloat16_as_ushort(l1) << 16) | __bfloat16_as_ushort(l0);
    return hi;
}
__device__ __forceinline__ uint32_t pack_v(float v)
{
    __nv_bfloat16 h = __float2bfloat16(v);
    __nv_bfloat16 l = __float2bfloat16(v - __bfloat162float(h));
    return (uint32_t)__bfloat16_as_ushort(h) | ((uint32_t)__bfloat16_as_ushort(l) << 16);
}

#define CP_ASYNC16(dst, src) \
    asm volatile("cp.async.cg.shared.global [%0], [%1], 16;" :: "r"(dst), "l"(src))
#define CP_COMMIT() asm volatile("cp.async.commit_group;" ::: "memory")
#define CP_WAIT(n)  asm volatile("cp.async.wait_group %0;" :: "n"(n) : "memory")

__device__ __forceinline__ void ldsm4(uint32_t* r, const void* p)
{
    uint32_t a = (uint32_t)__cvta_generic_to_shared(p);
    asm volatile("ldmatrix.sync.aligned.m8n8.x4.shared.b16 {%0,%1,%2,%3}, [%4];"
                 : "=r"(r[0]), "=r"(r[1]), "=r"(r[2]), "=r"(r[3]) : "r"(a));
}

/* ---------------- split fp32 -> bf16 hi/lo ------------------------- */
__global__ void split_kernel(const float* __restrict__ src, int which, int n)
{
    int i = blockIdx.x * 256 + threadIdx.x;
    if (i >= n) return;
    __nv_bfloat16 *hi, *lo;
    if      (which == 0) { hi = g_xh;  lo = g_xl;  }
    else if (which == 1) { hi = g_wqh; lo = g_wql; }
    else                 { hi = g_wph; lo = g_wpl; }
    float v = src[i];
    __nv_bfloat16 h = __float2bfloat16(v);
    hi[i] = h;
    lo[i] = __float2bfloat16(v - __bfloat162float(h));
}

/* ---------------- HMMA primitives ---------------------------------- */
#define MT 128
#define NT 128
#define KPAN 32
#define SPAD 40
#define TILEB (128*SPAD*2)
#define STAGEB (4*TILEB)

__device__ __forceinline__ void mma16816(float* c, const uint32_t* a,
                                         uint32_t b0, uint32_t b1)
{
    asm volatile(
        "mma.sync.aligned.m16n8k16.row.col.f32.bf16.bf16.f32 "
        "{%0,%1,%2,%3}, {%4,%5,%6,%7}, {%8,%9}, {%0,%1,%2,%3};"
        : "+f"(c[0]), "+f"(c[1]), "+f"(c[2]), "+f"(c[3])
        : "r"(a[0]), "r"(a[1]), "r"(a[2]), "r"(a[3]), "r"(b0), "r"(b1));
}

__device__ __forceinline__ void stage_async(uint32_t sbase,
        const __nv_bfloat16* __restrict__ g, int row0, int rowmax, int kb, int t)
{
#pragma unroll
    for (int i = 0; i < 2; i++) {
        const int idx = t + i * 256;
        const int row = idx >> 2;
        const int c8  = (idx & 3) * 8;
        int gr = row0 + row; if (gr > rowmax) gr = rowmax;
        CP_ASYNC16(sbase + (uint32_t)(row * SPAD + c8) * 2,
                   g + (size_t)gr * CDIM + kb + c8);
    }
}

__device__ __forceinline__ void stage_tile64(__nv_bfloat16* s,
        const __nv_bfloat16* __restrict__ g, int row0, int rowmax, int kb, int t)
{
#pragma unroll
    for (int i = 0; i < 2; i++) {
        const int idx = t + i * 256;
        const int row = idx >> 2;
        const int c8  = (idx & 3) * 8;
        int gr = row0 + row; if (gr > rowmax) gr = rowmax;
        uint4 v = *reinterpret_cast<const uint4*>(g + (size_t)gr * HD + kb + c8);
        *reinterpret_cast<uint4*>(s + row * SPAD + c8) = v;
    }
}

/* 3-pass split-bf16 MMA over one staged 128x32 panel pair (A,B) via LDSM.
   lrA/lcA, lrB/lcB are the ldmatrix lane->address offsets.             */
__device__ __forceinline__ void panel_mma(
        const __nv_bfloat16* sAh, const __nv_bfloat16* sAl,
        const __nv_bfloat16* sBh, const __nv_bfloat16* sBl,
        int pitch, int wm, int wn, int nNi2, int lane, float acc[][8][4])
{
    const int lrA = lane & 15;
    const int lcA = (lane >> 4) << 3;
    const int lrB = ((lane >> 4) << 3) | (lane & 7);
    const int lcB = lane & 8;

#pragma unroll
    for (int ks = 0; ks < 2; ks++) {
        const int ko = ks * 16;
        uint32_t ah[2][4], al[2][4];
#pragma unroll
        for (int mi = 0; mi < 2; mi++) {
            ldsm4(ah[mi], &sAh[(wm + mi * 16 + lrA) * pitch + ko + lcA]);
            ldsm4(al[mi], &sAl[(wm + mi * 16 + lrA) * pitch + ko + lcA]);
        }
#pragma unroll
        for (int ni2 = 0; ni2 < 4; ni2++) {
            if (ni2 >= nNi2) break;
            uint32_t bh4[4], bl4[4];
            ldsm4(bh4, &sBh[(wn + ni2 * 16 + lrB) * pitch + ko + lcB]);
            ldsm4(bl4, &sBl[(wn + ni2 * 16 + lrB) * pitch + ko + lcB]);
#pragma unroll
            for (int mi = 0; mi < 2; mi++) {
                mma16816(acc[mi][2*ni2    ], ah[mi], bh4[0], bh4[1]);
                mma16816(acc[mi][2*ni2    ], ah[mi], bl4[0], bl4[1]);
                mma16816(acc[mi][2*ni2    ], al[mi], bh4[0], bh4[1]);
                mma16816(acc[mi][2*ni2 + 1], ah[mi], bh4[2], bh4[3]);
                mma16816(acc[mi][2*ni2 + 1], ah[mi], bl4[2], bl4[3]);
                mma16816(acc[mi][2*ni2 + 1], al[mi], bh4[2], bh4[3]);
            }
        }
    }
}

/* ---------------- K1/K5: big GEMMs, cp.async + LDSM ---------------- */
__global__ __launch_bounds__(256, 2) void hmma_gemm(int mode,
        const float* __restrict__ bias, float* __restrict__ outp)
{
    extern __shared__ __align__(16) char dynsm[];
    const uint32_t sb = (uint32_t)__cvta_generic_to_shared(dynsm);

    const int t    = threadIdx.x;
    const int wid  = t >> 5, lane = t & 31;
    const int gq   = lane >> 2, tig = lane & 3;
    const int wm   = (wid & 3) * 32;
    const int wn   = (wid >> 2) * 64;
    const int m0   = blockIdx.y * MT;
    const int n0   = blockIdx.x * NT;

    const __nv_bfloat16 *Ah, *Al, *Bh, *Bl;
    int brmax;
    if (mode == 0) { Ah = g_xh;  Al = g_xl;  Bh = g_wqh; Bl = g_wql; brmax = 3*CDIM - 1; }
    else           { Ah = g_cth; Al = g_ctl; Bh = g_wph; Bl = g_wpl; brmax = CDIM - 1;   }

    float acc[2][8][4];
#pragma unroll
    for (int mi = 0; mi < 2; mi++)
#pragma unroll
        for (int ni = 0; ni < 8; ni++)
#pragma unroll
            for (int r = 0; r < 4; r++) acc[mi][ni][r] = 0.f;

    stage_async(sb + 0*TILEB, Ah, m0, TOK - 1, 0, t);
    stage_async(sb + 1*TILEB, Al, m0, TOK - 1, 0, t);
    stage_async(sb + 2*TILEB, Bh, n0, brmax,   0, t);
    stage_async(sb + 3*TILEB, Bl, n0, brmax,   0, t);
    CP_COMMIT();

    const int NP = CDIM / KPAN;
    for (int p = 0; p < NP; p++) {
        if (p + 1 < NP) {
            const uint32_t nb = sb + ((p + 1) & 1) * STAGEB;
            const int kb = (p + 1) * KPAN;
            stage_async(nb + 0*TILEB, Ah, m0, TOK - 1, kb, t);
            stage_async(nb + 1*TILEB, Al, m0, TOK - 1, kb, t);
            stage_async(nb + 2*TILEB, Bh, n0, brmax,   kb, t);
            stage_async(nb + 3*TILEB, Bl, n0, brmax,   kb, t);
            CP_COMMIT();
            CP_WAIT(1);
        } else {
            CP_WAIT(0);
        }
        __syncthreads();

        const char* cbuf = dynsm + (p & 1) * STAGEB;
        panel_mma((const __nv_bfloat16*)(cbuf + 0*TILEB),
                  (const __nv_bfloat16*)(cbuf + 1*TILEB),
                  (const __nv_bfloat16*)(cbuf + 2*TILEB),
                  (const __nv_bfloat16*)(cbuf + 3*TILEB),
                  SPAD, wm, wn, 4, lane, acc);
        __syncthreads();
    }

#pragma unroll
    for (int mi = 0; mi < 2; mi++) {
#pragma unroll
        for (int h2 = 0; h2 < 2; h2++) {
            const int m = m0 + wm + mi * 16 + gq + h2 * 8;
            if (m >= TOK) continue;
#pragma unroll
            for (int ni = 0; ni < 8; ni++) {
                const int col = n0 + wn + ni * 8 + 2 * tig;
                const float v0 = acc[mi][ni][h2 * 2 + 0];
                const float v1 = acc[mi][ni][h2 * 2 + 1];
                if (mode == 1) {
                    float2 o = make_float2(v0 + bias[col], v1 + bias[col + 1]);
                    *reinterpret_cast<float2*>(&outp[(size_t)m * CDIM + col]) = o;
                } else {
                    const int s  = col / CDIM;
                    const int rm = col % CDIM;
                    const int h  = rm / HD, dd = rm % HD;
                    const int bidx = m / SEQ, n = m % SEQ;
                    if (s == 2) {
                        const size_t vo = ((size_t)(bidx * NH + h) * HD + dd) * SEQP + n;
                        g_vt[vo]        = pack_v(v0);
                        g_vt[vo + SEQP] = pack_v(v1);
                    } else {
                        const size_t off = ((size_t)(bidx * NH + h) * SEQ + n) * HD + dd;
                        uint32_t lo, hi = pack_hi_lo(v0, v1, &lo);
                        __nv_bfloat16 *dh = (s == 0) ? g_qh : g_kh;
                        __nv_bfloat16 *dl = (s == 0) ? g_ql : g_kl;
                        *reinterpret_cast<uint32_t*>(&dh[off]) = hi;
                        *reinterpret_cast<uint32_t*>(&dl[off]) = lo;
                    }
                }
            }
        }
    }
}

/* ---------------- K2: scores via HMMA split-bf16 + LDSM ------------ */
__global__ __launch_bounds__(256, 2) void score_hmma()
{
    __shared__ __align__(16) __nv_bfloat16 sAh[128*SPAD];
    __shared__ __align__(16) __nv_bfloat16 sAl[128*SPAD];
    __shared__ __align__(16) __nv_bfloat16 sBh[128*SPAD];
    __shared__ __align__(16) __nv_bfloat16 sBl[128*SPAD];

    const int t    = threadIdx.x;
    const int wid  = t >> 5, lane = t & 31;
    const int gq   = lane >> 2, tig = lane & 3;
    const int wm   = (wid & 3) * 32;
    const int wn   = (wid >> 2) * 64;
    const int bh   = blockIdx.z;
    const int i0   = blockIdx.y * MT;
    const int j0   = blockIdx.x * NT;

    const size_t base = (size_t)bh * SEQ * HD;
    const __nv_bfloat16 *Qh = g_qh + base, *Ql = g_ql + base;
    const __nv_bfloat16 *Kh = g_kh + base, *Kl = g_kl + base;

    float acc[2][8][4];
#pragma unroll
    for (int mi = 0; mi < 2; mi++)
#pragma unroll
        for (int ni = 0; ni < 8; ni++)
#pragma unroll
            for (int r = 0; r < 4; r++) acc[mi][ni][r] = 0.f;

#pragma unroll
    for (int p = 0; p < HD / KPAN; p++) {
        const int kb = p * KPAN;
        stage_tile64(sAh, Qh, i0, SEQ - 1, kb, t);
        stage_tile64(sAl, Ql, i0, SEQ - 1, kb, t);
        stage_tile64(sBh, Kh, j0, SEQ - 1, kb, t);
        stage_tile64(sBl, Kl, j0, SEQ - 1, kb, t);
        __syncthreads();
        panel_mma(sAh, sAl, sBh, sBl, SPAD, wm, wn, 4, lane, acc);
        __syncthreads();
    }

    float* sc = g_sc + (size_t)bh * SEQ * SEQ;
#pragma unroll
    for (int mi = 0; mi < 2; mi++) {
#pragma unroll
        for (int h2 = 0; h2 < 2; h2++) {
            const int ii = i0 + wm + mi * 16 + gq + h2 * 8;
            if (ii >= SEQ) continue;
#pragma unroll
            for (int ni = 0; ni < 8; ni++) {
                const int jj = j0 + wn + ni * 8 + 2 * tig;
                if (jj < SEQ)     sc[(size_t)ii * SEQ + jj]     = acc[mi][ni][h2*2+0] * SCALEF;
                if (jj + 1 < SEQ) sc[(size_t)ii * SEQ + jj + 1] = acc[mi][ni][h2*2+1] * SCALEF;
            }
        }
    }
}

/* ---------------- top-k stages (exact fp32) ------------------------ */
__global__ __launch_bounds__(256) void topk_qc(const float* __restrict__ x,
                                               const float* __restrict__ w)
{
    __shared__ float xc[CDIM];
    const int b  = blockIdx.x;
    const int jt = blockIdx.y;
    const int t  = threadIdx.x;
    const int lane = t & 31, wrp = t >> 5;

    for (int i = t; i < CDIM; i += 256) xc[i] = x[(size_t)(b * SEQ) * CDIM + i];
    __syncthreads();

#pragma unroll
    for (int jj = 0; jj < 8; jj++) {
        const int j = jt * 64 + wrp * 8 + jj;
        const float* wr = w + (size_t)j * CDIM;
        float s = 0.f;
#pragma unroll
        for (int c4 = 0; c4 < 6; c4++) {
            const int c = (c4 * 32 + lane) * 4;
            const float4 wv = *reinterpret_cast<const float4*>(&wr[c]);
            s += wv.x * xc[c] + wv.y * xc[c+1] + wv.z * xc[c+2] + wv.w * xc[c+3];
        }
#pragma unroll
        for (int off = 16; off > 0; off >>= 1)
            s += __shfl_xor_sync(0xffffffffu, s, off);
        if (lane == 0) g_qc[b * CDIM + j] = s;
    }
}

__global__ __launch_bounds__(256) void topk_u(const float* __restrict__ w)
{
    __shared__ float qh[HD];
    const int b = blockIdx.x, h = blockIdx.y;
    const int t = threadIdx.x;
    if (t < HD) qh[t] = g_qc[b * CDIM + h * HD + t];
    __syncthreads();

    const float* wk = w + (size_t)(CDIM + h * HD) * CDIM;
#pragma unroll
    for (int cc = 0; cc < 3; cc++) {
        const int c = cc * 256 + t;
        float s = 0.f;
#pragma unroll 16
        for (int d = 0; d < HD; d++) s += wk[(size_t)d * CDIM + c] * qh[d];
        g_u[((size_t)b * NH + h) * CDIM + c] = s;
    }
}

__global__ __launch_bounds__(256) void topk_wt(const float* __restrict__ x)
{
    const int b = blockIdx.x;
    const int t = threadIdx.x;
    const int lane = t & 31, wrp = t >> 5;
    const int m = blockIdx.y * 8 + wrp;
    if (m >= SEQ) return;

    const float* xr = x + (size_t)(b * SEQ + m) * CDIM;
    float4 xv[6];
#pragma unroll
    for (int c4 = 0; c4 < 6; c4++)
        xv[c4] = *reinterpret_cast<const float4*>(&xr[(c4 * 32 + lane) * 4]);

    const float* ub = g_u + (size_t)b * NH * CDIM;
    float tot = 0.f;
#pragma unroll
    for (int h = 0; h < NH; h++) {
        const float* ur = ub + h * CDIM;
        float s = 0.f;
#pragma unroll
        for (int c4 = 0; c4 < 6; c4++) {
            const int c = (c4 * 32 + lane) * 4;
            const float4 uv = *reinterpret_cast<const float4*>(&ur[c]);
            s += uv.x * xv[c4].x + uv.y * xv[c4].y + uv.z * xv[c4].z + uv.w * xv[c4].w;
        }
#pragma unroll
        for (int off = 16; off > 0; off >>= 1)
            s += __shfl_xor_sync(0xffffffffu, s, off);
        tot += fabsf(s);
    }
    if (lane == 0) g_wt[b * SEQ + m] = tot;
}

__global__ __launch_bounds__(256) void topk_emit(float* __restrict__ out_keep,
                                                 int write_keep)
{
    __shared__ float wt[SEQ];
    __shared__ unsigned char keep[SEQ];
    const int b = blockIdx.x, t = threadIdx.x;

    if (t < SEQ) wt[t] = g_wt[b * SEQ + t];
    __syncthreads();
    if (t < SEQ) {
        const float wi = wt[t];
        int cnt = 0;
        for (int j = 0; j < SEQ; j++) {
            const float wj = wt[j];
            cnt += (wj > wi) || (wj == wi && j < t);
        }
        keep[t] = (cnt < KEEP) ? 1 : 0;
    }
    __syncthreads();
    if (write_keep && t < SEQ && keep[t]) {
        int pos = 0;
        for (int j = 0; j < t; j++) pos += keep[j];
        out_keep[b * KEEP + pos] = (float)t;
    }
}

/* ---------------- K4: softmax (fp32) + PV via HMMA + LDSM ---------- */
__global__ __launch_bounds__(256, 1) void av_hmma()
{
    extern __shared__ __nv_bfloat16 smb[];
    __nv_bfloat16* sPh  = smb;
    __nv_bfloat16* sPl  = smb + 128 * PPITCH;
    __nv_bfloat16* sVth = smb + 256 * PPITCH;
    __nv_bfloat16* sVtl = smb + 320 * PPITCH;

    const int bh   = blockIdx.x;
    const int b    = bh / NH, h = bh % NH;
    const int row0 = blockIdx.y * 128;
    const int t    = threadIdx.x;
    const int lane = t & 31;
    const int w    = t >> 5;

    const uint32_t* vt = g_vt + (size_t)bh * HD * SEQP;
#pragma unroll
    for (int dd = 0; dd < 8; dd++) {
        const int d = w * 8 + dd;
#pragma unroll
        for (int i = 0; i < 8; i++) {
            const int n = lane + i * 32;
            if (n < SEQP) {
                const uint32_t p = vt[d * SEQP + n];
                sVth[d * PPITCH + n] = __ushort_as_bfloat16((unsigned short)(p & 0xffffu));
                sVtl[d * PPITCH + n] = __ushort_as_bfloat16((unsigned short)(p >> 16));
            } else if (n < PPITCH) {
                sVth[d * PPITCH + n] = __ushort_as_bfloat16((unsigned short)0);
                sVtl[d * PPITCH + n] = __ushort_as_bfloat16((unsigned short)0);
            }
        }
    }

    const float* scb = g_sc + (size_t)bh * SEQ * SEQ;
#pragma unroll 1
    for (int r8 = 0; r8 < 16; r8++) {
        const int sr = w * 16 + r8;
        const int r  = row0 + sr;
        float vals[7];
        float inv = 0.f;
        if (r < SEQ) {
            const float* row = scb + (size_t)r * SEQ;
            float mx = -1e30f;
#pragma unroll
            for (int i = 0; i < 7; i++) {
                const int m = lane + i * 32;
                vals[i] = (m < SEQ) ? row[m] : -1e30f;
                mx = fmaxf(mx, vals[i]);
            }
#pragma unroll
            for (int off = 16; off > 0; off >>= 1)
                mx = fmaxf(mx, __shfl_xor_sync(0xffffffffu, mx, off));
            float s = 0.f;
#pragma unroll
            for (int i = 0; i < 7; i++) {
                const int m = lane + i * 32;
                const float e = (m < SEQ) ? __expf(vals[i] - mx) : 0.f;
                vals[i] = e;
                s += e;
            }
#pragma unroll
            for (int off = 16; off > 0; off >>= 1)
                s += __shfl_xor_sync(0xffffffffu, s, off);
            inv = 1.f / s;
        }
#pragma unroll
        for (int i = 0; i < 8; i++) {
            const int m = lane + i * 32;
            if (m < PPITCH) {
                float pv = (r < SEQ && i < 7 && m < SEQ) ? vals[i] * inv : 0.f;
                __nv_bfloat16 ph = __float2bfloat16(pv);
                __nv_bfloat16 pl = __float2bfloat16(pv - __bfloat162float(ph));
                sPh[sr * PPITCH + m] = ph;
                sPl[sr * PPITCH + m] = pl;
            }
        }
    }
    __syncthreads();

    const int gq = lane >> 2, tig = lane & 3;
    const int wm = (w & 3) * 32;
    const int wn = (w >> 2) * 32;
    const int lrA = lane & 15;
    const int lcA = (lane >> 4) << 3;
    const int lrB = ((lane >> 4) << 3) | (lane & 7);
    const int lcB = lane & 8;

    float acc[2][4][4];
#pragma unroll
    for (int mi = 0; mi < 2; mi++)
#pragma unroll
        for (int ni = 0; ni < 4; ni++)
#pragma unroll
            for (int r = 0; r < 4; r++) acc[mi][ni][r] = 0.f;

#pragma unroll 2
    for (int ks = 0; ks < 14; ks++) {
        const int ko = ks * 16;
        uint32_t ah[2][4], al[2][4];
#pragma unroll
        for (int mi = 0; mi < 2; mi++) {
            ldsm4(ah[mi], &sPh[(wm + mi * 16 + lrA) * PPITCH + ko + lcA]);
            ldsm4(al[mi], &sPl[(wm + mi * 16 + lrA) * PPITCH + ko + lcA]);
        }
#pragma unroll
        for (int ni2 = 0; ni2 < 2; ni2++) {
            uint32_t bh4[4], bl4[4];
            ldsm4(bh4, &sVth[(wn + ni2 * 16 + lrB) * PPITCH + ko + lcB]);
            ldsm4(bl4, &sVtl[(wn + ni2 * 16 + lrB) * PPITCH + ko + lcB]);
#pragma unroll
            for (int mi = 0; mi < 2; mi++) {
                mma16816(acc[mi][2*ni2    ], ah[mi], bh4[0], bh4[1]);
                mma16816(acc[mi][2*ni2    ], ah[mi], bl4[0], bl4[1]);
                mma16816(acc[mi][2*ni2    ], al[mi], bh4[0], bh4[1]);
                mma16816(acc[mi][2*ni2 + 1], ah[mi], bh4[2], bh4[3]);
                mma16816(acc[mi][2*ni2 + 1], ah[mi], bl4[2], bl4[3]);
                mma16816(acc[mi][2*ni2 + 1], al[mi], bh4[2], bh4[3]);
            }
        }
    }

#pragma unroll
    for (int mi = 0; mi < 2; mi++) {
#pragma unroll
        for (int h2 = 0; h2 < 2; h2++) {
            const int r = row0 + wm + mi * 16 + gq + h2 * 8;
            if (r >= SEQ) continue;
#pragma unroll
            for (int ni = 0; ni < 4; ni++) {
                const int col = wn + ni * 8 + 2 * tig;
                const size_t off = (size_t)(b * SEQ + r) * CDIM + h * HD + col;
                uint32_t lo, hi = pack_hi_lo(acc[mi][ni][h2*2+0], acc[mi][ni][h2*2+1], &lo);
                *reinterpret_cast<uint32_t*>(&g_cth[off]) = hi;
                *reinterpret_cast<uint32_t*>(&g_ctl[off]) = lo;
            }
        }
    }
}

/* ------------------------------------------------------------------ */
extern "C" void kernel_launch(void* const* d_in, const int* in_sizes, int n_in,
                              void* d_out, int out_size)
{
    const float* x      = (const float*)d_in[0];
    const float* qkv_w  = (const float*)d_in[1];
    const float* proj_w = (const float*)d_in[2];
    const float* proj_b = (const float*)d_in[3];
    float* out = (float*)d_out;

    const int av_smem   = 384 * PPITCH * (int)sizeof(__nv_bfloat16); /* 178176 */
    const int gemm_smem = 2 * STAGEB;
    cudaFuncSetAttribute(av_hmma,   cudaFuncAttributeMaxDynamicSharedMemorySize, av_smem);
    cudaFuncSetAttribute(hmma_gemm, cudaFuncAttributeMaxDynamicSharedMemorySize, gemm_smem);

    /* splits */
    split_kernel<<<(TOK*CDIM + 255)/256, 256>>>(x, 0, TOK*CDIM);
    split_kernel<<<(3*CDIM*CDIM + 255)/256, 256>>>(qkv_w, 1, 3*CDIM*CDIM);
    split_kernel<<<(CDIM*CDIM + 255)/256, 256>>>(proj_w, 2, CDIM*CDIM);

    /* exact fp32 top-k (decoupled from bf16 path) */
    const int write_keep = (out_size >= TOK * CDIM + BSZ * KEEP) ? 1 : 0;
    topk_qc  <<<dim3(BSZ, 12), 256>>>(x, qkv_w);
    topk_u   <<<dim3(BSZ, NH), 256>>>(qkv_w);
    topk_wt  <<<dim3(BSZ, (SEQ + 7) / 8), 256>>>(x);
    topk_emit<<<BSZ, 256>>>(out + (size_t)TOK * CDIM, write_keep);

    /* QKV via pipelined HMMA split-bf16 + LDSM */
    hmma_gemm<<<dim3(3*CDIM/NT, (TOK + MT - 1)/MT), 256, gemm_smem>>>(0, nullptr, nullptr);

    /* scores */
    score_hmma<<<dim3(2, 2, BH), 256>>>();

    /* softmax + PV */
    av_hmma<<<dim3(BH, 2), 256, av_smem>>>();

    /* proj */
    hmma_gemm<<<dim3(CDIM/NT, (TOK + MT - 1)/MT), 256, gemm_smem>>>(1, proj_b, out);
}

// round 11
// speedup vs baseline: 3.2442x; 1.0207x over previous
#include <cuda_runtime.h>
#include <cuda_bf16.h>
#include <math.h>
#include <stdint.h>

#define BSZ   64
#define SEQ   197
#define CDIM  768
#define NH    12
#define HD    64
#define KEEP  160
#define SCALEF 0.125f

#define BH   (BSZ*NH)
#define TOK  (BSZ*SEQ)

#define SEQP   228   /* global V^T pitch (u32 elems)                  */
#define PPITCH 232   /* smem pitch for P/V^T: 464B = 29*16B, LDSM ok  */

/* ---------------- scratch (device globals; no allocs allowed) ------ */
__device__ float g_sc[BH*SEQ*SEQ];

__device__ __nv_bfloat16 g_qh[BH*SEQ*HD], g_ql[BH*SEQ*HD];
__device__ __nv_bfloat16 g_kh[BH*SEQ*HD], g_kl[BH*SEQ*HD];
__device__ uint32_t      g_vt[BH*HD*SEQP];

__device__ __nv_bfloat16 g_xh[TOK*CDIM],  g_xl[TOK*CDIM];
__device__ __nv_bfloat16 g_wqh[3*CDIM*CDIM], g_wql[3*CDIM*CDIM];
__device__ __nv_bfloat16 g_wph[CDIM*CDIM],   g_wpl[CDIM*CDIM];
__device__ __nv_bfloat16 g_cth[TOK*CDIM], g_ctl[TOK*CDIM];

/* top-k staging */
__device__ float g_qc[BSZ*CDIM];
__device__ float g_u [BSZ*NH*CDIM];
__device__ float g_wt[BSZ*SEQ];

/* ---------------- helpers ------------------------------------------ */
__device__ __forceinline__ uint32_t pack_hi_lo(float v0, float v1, uint32_t* lo)
{
    __nv_bfloat16 h0 = __float2bfloat16(v0);
    __nv_bfloat16 h1 = __float2bfloat16(v1);
    __nv_bfloat16 l0 = __float2bfloat16(v0 - __bfloat162float(h0));
    __nv_bfloat16 l1 = __float2bfloat16(v1 - __bfloat162float(h1));
    uint32_t hi = ((uint32_t)__bfloat16_as_ushort(h1) << 16) | __bfloat16_as_ushort(h0);
    *lo         = ((uint32_t)__bfloat16_as_ushort(l1) << 16) | __bfloat16_as_ushort(l0);
    return hi;
}
__device__ __forceinline__ uint32_t pack_v(float v)
{
    __nv_bfloat16 h = __float2bfloat16(v);
    __nv_bfloat16 l = __float2bfloat16(v - __bfloat162float(h));
    return (uint32_t)__bfloat16_as_ushort(h) | ((uint32_t)__bfloat16_as_ushort(l) << 16);
}

#define CP_ASYNC16(dst, src) \
    asm volatile("cp.async.cg.shared.global [%0], [%1], 16;" :: "r"(dst), "l"(src))
#define CP_COMMIT() asm volatile("cp.async.commit_group;" ::: "memory")
#define CP_WAIT(n)  asm volatile("cp.async.wait_group %0;" :: "n"(n) : "memory")

__device__ __forceinline__ void ldsm4(uint32_t* r, const void* p)
{
    uint32_t a = (uint32_t)__cvta_generic_to_shared(p);
    asm volatile("ldmatrix.sync.aligned.m8n8.x4.shared.b16 {%0,%1,%2,%3}, [%4];"
                 : "=r"(r[0]), "=r"(r[1]), "=r"(r[2]), "=r"(r[3]) : "r"(a));
}

/* ---------------- merged split fp32 -> bf16 hi/lo ------------------ */
#define NX  (TOK*CDIM)          /* 9,682,944  */
#define NWQ (3*CDIM*CDIM)       /* 1,769,472  */
#define NWP (CDIM*CDIM)         /*   589,824  */
#define NSPLIT (NX + NWQ + NWP)

__global__ void split_all_kernel(const float* __restrict__ x,
                                 const float* __restrict__ wq,
                                 const float* __restrict__ wp)
{
    int i = blockIdx.x * 256 + threadIdx.x;
    if (i >= NSPLIT) return;
    const float* s;
    __nv_bfloat16 *hi, *lo;
    int j;
    if (i < NX)            { s = x;  hi = g_xh;  lo = g_xl;  j = i; }
    else if (i < NX + NWQ) { s = wq; hi = g_wqh; lo = g_wql; j = i - NX; }
    else                   { s = wp; hi = g_wph; lo = g_wpl; j = i - NX - NWQ; }
    float v = s[j];
    __nv_bfloat16 h = __float2bfloat16(v);
    hi[j] = h;
    lo[j] = __float2bfloat16(v - __bfloat162float(h));
}

/* ---------------- HMMA primitives ---------------------------------- */
#define MT 128
#define NT 128
#define KPAN 32
#define SPAD 40
#define TILEB (128*SPAD*2)
#define STAGEB (4*TILEB)

__device__ __forceinline__ void mma16816(float* c, const uint32_t* a,
                                         uint32_t b0, uint32_t b1)
{
    asm volatile(
        "mma.sync.aligned.m16n8k16.row.col.f32.bf16.bf16.f32 "
        "{%0,%1,%2,%3}, {%4,%5,%6,%7}, {%8,%9}, {%0,%1,%2,%3};"
        : "+f"(c[0]), "+f"(c[1]), "+f"(c[2]), "+f"(c[3])
        : "r"(a[0]), "r"(a[1]), "r"(a[2]), "r"(a[3]), "r"(b0), "r"(b1));
}

__device__ __forceinline__ void stage_async(uint32_t sbase,
        const __nv_bfloat16* __restrict__ g, int row0, int rowmax, int kb, int t)
{
#pragma unroll
    for (int i = 0; i < 2; i++) {
        const int idx = t + i * 256;
        const int row = idx >> 2;
        const int c8  = (idx & 3) * 8;
        int gr = row0 + row; if (gr > rowmax) gr = rowmax;
        CP_ASYNC16(sbase + (uint32_t)(row * SPAD + c8) * 2,
                   g + (size_t)gr * CDIM + kb + c8);
    }
}

__device__ __forceinline__ void stage_tile64(__nv_bfloat16* s,
        const __nv_bfloat16* __restrict__ g, int row0, int rowmax, int kb, int t)
{
#pragma unroll
    for (int i = 0; i < 2; i++) {
        const int idx = t + i * 256;
        const int row = idx >> 2;
        const int c8  = (idx & 3) * 8;
        int gr = row0 + row; if (gr > rowmax) gr = rowmax;
        uint4 v = *reinterpret_cast<const uint4*>(g + (size_t)gr * HD + kb + c8);
        *reinterpret_cast<uint4*>(s + row * SPAD + c8) = v;
    }
}

/* 3-pass split-bf16 MMA over one staged 128x32 panel pair via LDSM.  */
__device__ __forceinline__ void panel_mma(
        const __nv_bfloat16* sAh, const __nv_bfloat16* sAl,
        const __nv_bfloat16* sBh, const __nv_bfloat16* sBl,
        int pitch, int wm, int wn, int nNi2, int lane, float acc[][8][4])
{
    const int lrA = lane & 15;
    const int lcA = (lane >> 4) << 3;
    const int lrB = ((lane >> 4) << 3) | (lane & 7);
    const int lcB = lane & 8;

#pragma unroll
    for (int ks = 0; ks < 2; ks++) {
        const int ko = ks * 16;
        uint32_t ah[2][4], al[2][4];
#pragma unroll
        for (int mi = 0; mi < 2; mi++) {
            ldsm4(ah[mi], &sAh[(wm + mi * 16 + lrA) * pitch + ko + lcA]);
            ldsm4(al[mi], &sAl[(wm + mi * 16 + lrA) * pitch + ko + lcA]);
        }
#pragma unroll
        for (int ni2 = 0; ni2 < 4; ni2++) {
            if (ni2 >= nNi2) break;
            uint32_t bh4[4], bl4[4];
            ldsm4(bh4, &sBh[(wn + ni2 * 16 + lrB) * pitch + ko + lcB]);
            ldsm4(bl4, &sBl[(wn + ni2 * 16 + lrB) * pitch + ko + lcB]);
#pragma unroll
            for (int mi = 0; mi < 2; mi++) {
                mma16816(acc[mi][2*ni2    ], ah[mi], bh4[0], bh4[1]);
                mma16816(acc[mi][2*ni2    ], ah[mi], bl4[0], bl4[1]);
                mma16816(acc[mi][2*ni2    ], al[mi], bh4[0], bh4[1]);
                mma16816(acc[mi][2*ni2 + 1], ah[mi], bh4[2], bh4[3]);
                mma16816(acc[mi][2*ni2 + 1], ah[mi], bl4[2], bl4[3]);
                mma16816(acc[mi][2*ni2 + 1], al[mi], bh4[2], bh4[3]);
            }
        }
    }
}

/* ---------------- K1/K5: big GEMMs, cp.async + LDSM ---------------- */
__global__ __launch_bounds__(256, 2) void hmma_gemm(int mode,
        const float* __restrict__ bias, float* __restrict__ outp)
{
    extern __shared__ __align__(16) char dynsm[];
    const uint32_t sb = (uint32_t)__cvta_generic_to_shared(dynsm);

    const int t    = threadIdx.x;
    const int wid  = t >> 5, lane = t & 31;
    const int gq   = lane >> 2, tig = lane & 3;
    const int wm   = (wid & 3) * 32;
    const int wn   = (wid >> 2) * 64;
    const int m0   = blockIdx.y * MT;
    const int n0   = blockIdx.x * NT;

    const __nv_bfloat16 *Ah, *Al, *Bh, *Bl;
    int brmax;
    if (mode == 0) { Ah = g_xh;  Al = g_xl;  Bh = g_wqh; Bl = g_wql; brmax = 3*CDIM - 1; }
    else           { Ah = g_cth; Al = g_ctl; Bh = g_wph; Bl = g_wpl; brmax = CDIM - 1;   }

    float acc[2][8][4];
#pragma unroll
    for (int mi = 0; mi < 2; mi++)
#pragma unroll
        for (int ni = 0; ni < 8; ni++)
#pragma unroll
            for (int r = 0; r < 4; r++) acc[mi][ni][r] = 0.f;

    stage_async(sb + 0*TILEB, Ah, m0, TOK - 1, 0, t);
    stage_async(sb + 1*TILEB, Al, m0, TOK - 1, 0, t);
    stage_async(sb + 2*TILEB, Bh, n0, brmax,   0, t);
    stage_async(sb + 3*TILEB, Bl, n0, brmax,   0, t);
    CP_COMMIT();

    const int NP = CDIM / KPAN;
    for (int p = 0; p < NP; p++) {
        if (p + 1 < NP) {
            const uint32_t nb = sb + ((p + 1) & 1) * STAGEB;
            const int kb = (p + 1) * KPAN;
            stage_async(nb + 0*TILEB, Ah, m0, TOK - 1, kb, t);
            stage_async(nb + 1*TILEB, Al, m0, TOK - 1, kb, t);
            stage_async(nb + 2*TILEB, Bh, n0, brmax,   kb, t);
            stage_async(nb + 3*TILEB, Bl, n0, brmax,   kb, t);
            CP_COMMIT();
            CP_WAIT(1);
        } else {
            CP_WAIT(0);
        }
        __syncthreads();

        const char* cbuf = dynsm + (p & 1) * STAGEB;
        panel_mma((const __nv_bfloat16*)(cbuf + 0*TILEB),
                  (const __nv_bfloat16*)(cbuf + 1*TILEB),
                  (const __nv_bfloat16*)(cbuf + 2*TILEB),
                  (const __nv_bfloat16*)(cbuf + 3*TILEB),
                  SPAD, wm, wn, 4, lane, acc);
        __syncthreads();
    }

#pragma unroll
    for (int mi = 0; mi < 2; mi++) {
#pragma unroll
        for (int h2 = 0; h2 < 2; h2++) {
            const int m = m0 + wm + mi * 16 + gq + h2 * 8;
            if (m >= TOK) continue;
#pragma unroll
            for (int ni = 0; ni < 8; ni++) {
                const int col = n0 + wn + ni * 8 + 2 * tig;
                const float v0 = acc[mi][ni][h2 * 2 + 0];
                const float v1 = acc[mi][ni][h2 * 2 + 1];
                if (mode == 1) {
                    float2 o = make_float2(v0 + bias[col], v1 + bias[col + 1]);
                    *reinterpret_cast<float2*>(&outp[(size_t)m * CDIM + col]) = o;
                } else {
                    const int s  = col / CDIM;
                    const int rm = col % CDIM;
                    const int h  = rm / HD, dd = rm % HD;
                    const int bidx = m / SEQ, n = m % SEQ;
                    if (s == 2) {
                        const size_t vo = ((size_t)(bidx * NH + h) * HD + dd) * SEQP + n;
                        g_vt[vo]        = pack_v(v0);
                        g_vt[vo + SEQP] = pack_v(v1);
                    } else {
                        const size_t off = ((size_t)(bidx * NH + h) * SEQ + n) * HD + dd;
                        uint32_t lo, hi = pack_hi_lo(v0, v1, &lo);
                        __nv_bfloat16 *dh = (s == 0) ? g_qh : g_kh;
                        __nv_bfloat16 *dl = (s == 0) ? g_ql : g_kl;
                        *reinterpret_cast<uint32_t*>(&dh[off]) = hi;
                        *reinterpret_cast<uint32_t*>(&dl[off]) = lo;
                    }
                }
            }
        }
    }
}

/* ---------------- K2: scores via HMMA split-bf16 + LDSM ------------ */
__global__ __launch_bounds__(256, 2) void score_hmma()
{
    __shared__ __align__(16) __nv_bfloat16 sAh[128*SPAD];
    __shared__ __align__(16) __nv_bfloat16 sAl[128*SPAD];
    __shared__ __align__(16) __nv_bfloat16 sBh[128*SPAD];
    __shared__ __align__(16) __nv_bfloat16 sBl[128*SPAD];

    const int t    = threadIdx.x;
    const int wid  = t >> 5, lane = t & 31;
    const int gq   = lane >> 2, tig = lane & 3;
    const int wm   = (wid & 3) * 32;
    const int wn   = (wid >> 2) * 64;
    const int bh   = blockIdx.z;
    const int i0   = blockIdx.y * MT;
    const int j0   = blockIdx.x * NT;

    const size_t base = (size_t)bh * SEQ * HD;
    const __nv_bfloat16 *Qh = g_qh + base, *Ql = g_ql + base;
    const __nv_bfloat16 *Kh = g_kh + base, *Kl = g_kl + base;

    float acc[2][8][4];
#pragma unroll
    for (int mi = 0; mi < 2; mi++)
#pragma unroll
        for (int ni = 0; ni < 8; ni++)
#pragma unroll
            for (int r = 0; r < 4; r++) acc[mi][ni][r] = 0.f;

#pragma unroll
    for (int p = 0; p < HD / KPAN; p++) {
        const int kb = p * KPAN;
        stage_tile64(sAh, Qh, i0, SEQ - 1, kb, t);
        stage_tile64(sAl, Ql, i0, SEQ - 1, kb, t);
        stage_tile64(sBh, Kh, j0, SEQ - 1, kb, t);
        stage_tile64(sBl, Kl, j0, SEQ - 1, kb, t);
        __syncthreads();
        panel_mma(sAh, sAl, sBh, sBl, SPAD, wm, wn, 4, lane, acc);
        __syncthreads();
    }

    float* sc = g_sc + (size_t)bh * SEQ * SEQ;
#pragma unroll
    for (int mi = 0; mi < 2; mi++) {
#pragma unroll
        for (int h2 = 0; h2 < 2; h2++) {
            const int ii = i0 + wm + mi * 16 + gq + h2 * 8;
            if (ii >= SEQ) continue;
#pragma unroll
            for (int ni = 0; ni < 8; ni++) {
                const int jj = j0 + wn + ni * 8 + 2 * tig;
                if (jj < SEQ)     sc[(size_t)ii * SEQ + jj]     = acc[mi][ni][h2*2+0] * SCALEF;
                if (jj + 1 < SEQ) sc[(size_t)ii * SEQ + jj + 1] = acc[mi][ni][h2*2+1] * SCALEF;
            }
        }
    }
}

/* ---------------- top-k stages (exact fp32) ------------------------ */
__global__ __launch_bounds__(256) void topk_qc(const float* __restrict__ x,
                                               const float* __restrict__ w)
{
    __shared__ float xc[CDIM];
    const int b  = blockIdx.x;
    const int jt = blockIdx.y;
    const int t  = threadIdx.x;
    const int lane = t & 31, wrp = t >> 5;

    for (int i = t; i < CDIM; i += 256) xc[i] = x[(size_t)(b * SEQ) * CDIM + i];
    __syncthreads();

#pragma unroll
    for (int jj = 0; jj < 8; jj++) {
        const int j = jt * 64 + wrp * 8 + jj;
        const float* wr = w + (size_t)j * CDIM;
        float s = 0.f;
#pragma unroll
        for (int c4 = 0; c4 < 6; c4++) {
            const int c = (c4 * 32 + lane) * 4;
            const float4 wv = *reinterpret_cast<const float4*>(&wr[c]);
            s += wv.x * xc[c] + wv.y * xc[c+1] + wv.z * xc[c+2] + wv.w * xc[c+3];
        }
#pragma unroll
        for (int off = 16; off > 0; off >>= 1)
            s += __shfl_xor_sync(0xffffffffu, s, off);
        if (lane == 0) g_qc[b * CDIM + j] = s;
    }
}

__global__ __launch_bounds__(256) void topk_u(const float* __restrict__ w)
{
    __shared__ float qh[HD];
    const int b = blockIdx.x, h = blockIdx.y;
    const int t = threadIdx.x;
    if (t < HD) qh[t] = g_qc[b * CDIM + h * HD + t];
    __syncthreads();

    const float* wk = w + (size_t)(CDIM + h * HD) * CDIM;
#pragma unroll
    for (int cc = 0; cc < 3; cc++) {
        const int c = cc * 256 + t;
        float s = 0.f;
#pragma unroll 16
        for (int d = 0; d < HD; d++) s += wk[(size_t)d * CDIM + c] * qh[d];
        g_u[((size_t)b * NH + h) * CDIM + c] = s;
    }
}

__global__ __launch_bounds__(256) void topk_wt(const float* __restrict__ x)
{
    const int b = blockIdx.x;
    const int t = threadIdx.x;
    const int lane = t & 31, wrp = t >> 5;
    const int m = blockIdx.y * 8 + wrp;
    if (m >= SEQ) return;

    const float* xr = x + (size_t)(b * SEQ + m) * CDIM;
    float4 xv[6];
#pragma unroll
    for (int c4 = 0; c4 < 6; c4++)
        xv[c4] = *reinterpret_cast<const float4*>(&xr[(c4 * 32 + lane) * 4]);

    const float* ub = g_u + (size_t)b * NH * CDIM;
    float tot = 0.f;
#pragma unroll
    for (int h = 0; h < NH; h++) {
        const float* ur = ub + h * CDIM;
        float s = 0.f;
#pragma unroll
        for (int c4 = 0; c4 < 6; c4++) {
            const int c = (c4 * 32 + lane) * 4;
            const float4 uv = *reinterpret_cast<const float4*>(&ur[c]);
            s += uv.x * xv[c4].x + uv.y * xv[c4].y + uv.z * xv[c4].z + uv.w * xv[c4].w;
        }
#pragma unroll
        for (int off = 16; off > 0; off >>= 1)
            s += __shfl_xor_sync(0xffffffffu, s, off);
        tot += fabsf(s);
    }
    if (lane == 0) g_wt[b * SEQ + m] = tot;
}

__global__ __launch_bounds__(256) void topk_emit(float* __restrict__ out_keep,
                                                 int write_keep)
{
    __shared__ float wt[SEQ];
    __shared__ unsigned char keep[SEQ];
    const int b = blockIdx.x, t = threadIdx.x;

    if (t < SEQ) wt[t] = g_wt[b * SEQ + t];
    __syncthreads();
    if (t < SEQ) {
        const float wi = wt[t];
        int cnt = 0;
        for (int j = 0; j < SEQ; j++) {
            const float wj = wt[j];
            cnt += (wj > wi) || (wj == wi && j < t);
        }
        keep[t] = (cnt < KEEP) ? 1 : 0;
    }
    __syncthreads();
    if (write_keep && t < SEQ && keep[t]) {
        int pos = 0;
        for (int j = 0; j < t; j++) pos += keep[j];
        out_keep[b * KEEP + pos] = (float)t;
    }
}

/* ---------------- K4: softmax (fp32) + PV via HMMA + LDSM ---------- */
__global__ __launch_bounds__(256, 1) void av_hmma()
{
    extern __shared__ __nv_bfloat16 smb[];
    __nv_bfloat16* sPh  = smb;
    __nv_bfloat16* sPl  = smb + 128 * PPITCH;
    __nv_bfloat16* sVth = smb + 256 * PPITCH;
    __nv_bfloat16* sVtl = smb + 320 * PPITCH;

    const int bh   = blockIdx.x;
    const int b    = bh / NH, h = bh % NH;
    const int row0 = blockIdx.y * 128;
    const int t    = threadIdx.x;
    const int lane = t & 31;
    const int w    = t >> 5;

    const uint32_t* vt = g_vt + (size_t)bh * HD * SEQP;
#pragma unroll
    for (int dd = 0; dd < 8; dd++) {
        const int d = w * 8 + dd;
#pragma unroll
        for (int i = 0; i < 8; i++) {
            const int n = lane + i * 32;
            if (n < SEQP) {
                const uint32_t p = vt[d * SEQP + n];
                sVth[d * PPITCH + n] = __ushort_as_bfloat16((unsigned short)(p & 0xffffu));
                sVtl[d * PPITCH + n] = __ushort_as_bfloat16((unsigned short)(p >> 16));
            } else if (n < PPITCH) {
                sVth[d * PPITCH + n] = __ushort_as_bfloat16((unsigned short)0);
                sVtl[d * PPITCH + n] = __ushort_as_bfloat16((unsigned short)0);
            }
        }
    }

    const float* scb = g_sc + (size_t)bh * SEQ * SEQ;
#pragma unroll 1
    for (int r8 = 0; r8 < 16; r8++) {
        const int sr = w * 16 + r8;
        const int r  = row0 + sr;
        float vals[7];
        float inv = 0.f;
        if (r < SEQ) {
            const float* row = scb + (size_t)r * SEQ;
            float mx = -1e30f;
#pragma unroll
            for (int i = 0; i < 7; i++) {
                const int m = lane + i * 32;
                vals[i] = (m < SEQ) ? row[m] : -1e30f;
                mx = fmaxf(mx, vals[i]);
            }
#pragma unroll
            for (int off = 16; off > 0; off >>= 1)
                mx = fmaxf(mx, __shfl_xor_sync(0xffffffffu, mx, off));
            float s = 0.f;
#pragma unroll
            for (int i = 0; i < 7; i++) {
                const int m = lane + i * 32;
                const float e = (m < SEQ) ? __expf(vals[i] - mx) : 0.f;
                vals[i] = e;
                s += e;
            }
#pragma unroll
            for (int off = 16; off > 0; off >>= 1)
                s += __shfl_xor_sync(0xffffffffu, s, off);
            inv = 1.f / s;
        }
#pragma unroll
        for (int i = 0; i < 8; i++) {
            const int m = lane + i * 32;
            if (m < PPITCH) {
                float pv = (r < SEQ && i < 7 && m < SEQ) ? vals[i] * inv : 0.f;
                __nv_bfloat16 ph = __float2bfloat16(pv);
                __nv_bfloat16 pl = __float2bfloat16(pv - __bfloat162float(ph));
                sPh[sr * PPITCH + m] = ph;
                sPl[sr * PPITCH + m] = pl;
            }
        }
    }
    __syncthreads();

    const int gq = lane >> 2, tig = lane & 3;
    const int wm = (w & 3) * 32;
    const int wn = (w >> 2) * 32;
    const int lrA = lane & 15;
    const int lcA = (lane >> 4) << 3;
    const int lrB = ((lane >> 4) << 3) | (lane & 7);
    const int lcB = lane & 8;

    float acc[2][4][4];
#pragma unroll
    for (int mi = 0; mi < 2; mi++)
#pragma unroll
        for (int ni = 0; ni < 4; ni++)
#pragma unroll
            for (int r = 0; r < 4; r++) acc[mi][ni][r] = 0.f;

#pragma unroll 2
    for (int ks = 0; ks < 14; ks++) {
        const int ko = ks * 16;
        uint32_t ah[2][4], al[2][4];
#pragma unroll
        for (int mi = 0; mi < 2; mi++) {
            ldsm4(ah[mi], &sPh[(wm + mi * 16 + lrA) * PPITCH + ko + lcA]);
            ldsm4(al[mi], &sPl[(wm + mi * 16 + lrA) * PPITCH + ko + lcA]);
        }
#pragma unroll
        for (int ni2 = 0; ni2 < 2; ni2++) {
            uint32_t bh4[4], bl4[4];
            ldsm4(bh4, &sVth[(wn + ni2 * 16 + lrB) * PPITCH + ko + lcB]);
            ldsm4(bl4, &sVtl[(wn + ni2 * 16 + lrB) * PPITCH + ko + lcB]);
#pragma unroll
            for (int mi = 0; mi < 2; mi++) {
                mma16816(acc[mi][2*ni2    ], ah[mi], bh4[0], bh4[1]);
                mma16816(acc[mi][2*ni2    ], ah[mi], bl4[0], bl4[1]);
                mma16816(acc[mi][2*ni2    ], al[mi], bh4[0], bh4[1]);
                mma16816(acc[mi][2*ni2 + 1], ah[mi], bh4[2], bh4[3]);
                mma16816(acc[mi][2*ni2 + 1], ah[mi], bl4[2], bl4[3]);
                mma16816(acc[mi][2*ni2 + 1], al[mi], bh4[2], bh4[3]);
            }
        }
    }

#pragma unroll
    for (int mi = 0; mi < 2; mi++) {
#pragma unroll
        for (int h2 = 0; h2 < 2; h2++) {
            const int r = row0 + wm + mi * 16 + gq + h2 * 8;
            if (r >= SEQ) continue;
#pragma unroll
            for (int ni = 0; ni < 4; ni++) {
                const int col = wn + ni * 8 + 2 * tig;
                const size_t off = (size_t)(b * SEQ + r) * CDIM + h * HD + col;
                uint32_t lo, hi = pack_hi_lo(acc[mi][ni][h2*2+0], acc[mi][ni][h2*2+1], &lo);
                *reinterpret_cast<uint32_t*>(&g_cth[off]) = hi;
                *reinterpret_cast<uint32_t*>(&g_ctl[off]) = lo;
            }
        }
    }
}

/* ------------------------------------------------------------------ */
extern "C" void kernel_launch(void* const* d_in, const int* in_sizes, int n_in,
                              void* d_out, int out_size)
{
    const float* x      = (const float*)d_in[0];
    const float* qkv_w  = (const float*)d_in[1];
    const float* proj_w = (const float*)d_in[2];
    const float* proj_b = (const float*)d_in[3];
    float* out = (float*)d_out;

    const int av_smem   = 384 * PPITCH * (int)sizeof(__nv_bfloat16);
    const int gemm_smem = 2 * STAGEB;
    cudaFuncSetAttribute(av_hmma,   cudaFuncAttributeMaxDynamicSharedMemorySize, av_smem);
    cudaFuncSetAttribute(hmma_gemm, cudaFuncAttributeMaxDynamicSharedMemorySize, gemm_smem);

    /* second stream + events for the independent top-k branch (capture
       fork/join pattern; created once, host-side only) */
    static cudaStream_t s2 = nullptr;
    static cudaEvent_t evFork = nullptr, evJoin = nullptr;
    if (s2 == nullptr) {
        cudaStreamCreateWithFlags(&s2, cudaStreamNonBlocking);
        cudaEventCreateWithFlags(&evFork, cudaEventDisableTiming);
        cudaEventCreateWithFlags(&evJoin, cudaEventDisableTiming);
    }

    const int write_keep = (out_size >= TOK * CDIM + BSZ * KEEP) ? 1 : 0;

    /* fork: exact fp32 top-k chain reads only raw inputs — run it
       concurrently with the split + GEMM pipeline */
    cudaEventRecord(evFork, 0);
    cudaStreamWaitEvent(s2, evFork, 0);
    topk_qc  <<<dim3(BSZ, 12), 256, 0, s2>>>(x, qkv_w);
    topk_u   <<<dim3(BSZ, NH), 256, 0, s2>>>(qkv_w);
    topk_wt  <<<dim3(BSZ, (SEQ + 7) / 8), 256, 0, s2>>>(x);
    topk_emit<<<BSZ, 256, 0, s2>>>(out + (size_t)TOK * CDIM, write_keep);
    cudaEventRecord(evJoin, s2);

    /* main pipeline on capture stream */
    split_all_kernel<<<(NSPLIT + 255)/256, 256>>>(x, qkv_w, proj_w);

    hmma_gemm<<<dim3(3*CDIM/NT, (TOK + MT - 1)/MT), 256, gemm_smem>>>(0, nullptr, nullptr);

    score_hmma<<<dim3(2, 2, BH), 256>>>();

    av_hmma<<<dim3(BH, 2), 256, av_smem>>>();

    hmma_gemm<<<dim3(CDIM/NT, (TOK + MT - 1)/MT), 256, gemm_smem>>>(1, proj_b, out);

    /* join the top-k branch back before capture ends */
    cudaStreamWaitEvent(0, evJoin, 0);
}

// round 13
// speedup vs baseline: 3.3983x; 1.0475x over previous
#include <cuda_runtime.h>
#include <cuda_bf16.h>
#include <math.h>
#include <stdint.h>

#define BSZ   64
#define SEQ   197
#define CDIM  768
#define NH    12
#define HD    64
#define KEEP  160
#define SCALEF 0.125f

#define BH   (BSZ*NH)
#define TOK  (BSZ*SEQ)

#define SEQP   228   /* global V^T pitch (u32 elems) */

/* ---------------- scratch (device globals; no allocs allowed) ------ */
__device__ __nv_bfloat16 g_qh[BH*SEQ*HD], g_ql[BH*SEQ*HD];
__device__ __nv_bfloat16 g_kh[BH*SEQ*HD], g_kl[BH*SEQ*HD];
__device__ uint32_t      g_vt[BH*HD*SEQP];

__device__ __nv_bfloat16 g_xh[TOK*CDIM],  g_xl[TOK*CDIM];
__device__ __nv_bfloat16 g_wqh[3*CDIM*CDIM], g_wql[3*CDIM*CDIM];
__device__ __nv_bfloat16 g_wph[CDIM*CDIM],   g_wpl[CDIM*CDIM];
__device__ __nv_bfloat16 g_cth[TOK*CDIM], g_ctl[TOK*CDIM];

/* top-k staging */
__device__ float g_qc[BSZ*CDIM];
__device__ float g_u [BSZ*NH*CDIM];
__device__ float g_wt[BSZ*SEQ];

/* ---------------- helpers ------------------------------------------ */
__device__ __forceinline__ uint32_t pack_hi_lo(float v0, float v1, uint32_t* lo)
{
    __nv_bfloat16 h0 = __float2bfloat16(v0);
    __nv_bfloat16 h1 = __float2bfloat16(v1);
    __nv_bfloat16 l0 = __float2bfloat16(v0 - __bfloat162float(h0));
    __nv_bfloat16 l1 = __float2bfloat16(v1 - __bfloat162float(h1));
    uint32_t hi = ((uint32_t)__bfloat16_as_ushort(h1) << 16) | __bfloat16_as_ushort(h0);
    *lo         = ((uint32_t)__bfloat16_as_ushort(l1) << 16) | __bfloat16_as_ushort(l0);
    return hi;
}
__device__ __forceinline__ uint32_t pack_v(float v)
{
    __nv_bfloat16 h = __float2bfloat16(v);
    __nv_bfloat16 l = __float2bfloat16(v - __bfloat162float(h));
    return (uint32_t)__bfloat16_as_ushort(h) | ((uint32_t)__bfloat16_as_ushort(l) << 16);
}

#define CP_ASYNC16(dst, src) \
    asm volatile("cp.async.cg.shared.global [%0], [%1], 16;" :: "r"(dst), "l"(src))
#define CP_COMMIT() asm volatile("cp.async.commit_group;" ::: "memory")
#define CP_WAIT(n)  asm volatile("cp.async.wait_group %0;" :: "n"(n) : "memory")

__device__ __forceinline__ void ldsm4(uint32_t* r, const void* p)
{
    uint32_t a = (uint32_t)__cvta_generic_to_shared(p);
    asm volatile("ldmatrix.sync.aligned.m8n8.x4.shared.b16 {%0,%1,%2,%3}, [%4];"
                 : "=r"(r[0]), "=r"(r[1]), "=r"(r[2]), "=r"(r[3]) : "r"(a));
}

/* ---------------- merged split fp32 -> bf16 hi/lo ------------------ */
#define NX  (TOK*CDIM)
#define NWQ (3*CDIM*CDIM)
#define NWP (CDIM*CDIM)
#define NSPLIT (NX + NWQ + NWP)

__global__ void split_all_kernel(const float* __restrict__ x,
                                 const float* __restrict__ wq,
                                 const float* __restrict__ wp)
{
    int i = blockIdx.x * 256 + threadIdx.x;
    if (i >= NSPLIT) return;
    const float* s;
    __nv_bfloat16 *hi, *lo;
    int j;
    if (i < NX)            { s = x;  hi = g_xh;  lo = g_xl;  j = i; }
    else if (i < NX + NWQ) { s = wq; hi = g_wqh; lo = g_wql; j = i - NX; }
    else                   { s = wp; hi = g_wph; lo = g_wpl; j = i - NX - NWQ; }
    float v = s[j];
    __nv_bfloat16 h = __float2bfloat16(v);
    hi[j] = h;
    lo[j] = __float2bfloat16(v - __bfloat162float(h));
}

/* ---------------- HMMA primitives ---------------------------------- */
#define MT 128
#define NT 128
#define KPAN 32
#define SPAD 40
#define TILEB (128*SPAD*2)
#define STAGEB (4*TILEB)

__device__ __forceinline__ void mma16816(float* c, const uint32_t* a,
                                         uint32_t b0, uint32_t b1)
{
    asm volatile(
        "mma.sync.aligned.m16n8k16.row.col.f32.bf16.bf16.f32 "
        "{%0,%1,%2,%3}, {%4,%5,%6,%7}, {%8,%9}, {%0,%1,%2,%3};"
        : "+f"(c[0]), "+f"(c[1]), "+f"(c[2]), "+f"(c[3])
        : "r"(a[0]), "r"(a[1]), "r"(a[2]), "r"(a[3]), "r"(b0), "r"(b1));
}

__device__ __forceinline__ void stage_async(uint32_t sbase,
        const __nv_bfloat16* __restrict__ g, int row0, int rowmax, int kb, int t)
{
#pragma unroll
    for (int i = 0; i < 2; i++) {
        const int idx = t + i * 256;
        const int row = idx >> 2;
        const int c8  = (idx & 3) * 8;
        int gr = row0 + row; if (gr > rowmax) gr = rowmax;
        CP_ASYNC16(sbase + (uint32_t)(row * SPAD + c8) * 2,
                   g + (size_t)gr * CDIM + kb + c8);
    }
}

/* 3-pass split-bf16 MMA over one staged panel via LDSM. */
__device__ __forceinline__ void panel_mma(
        const __nv_bfloat16* sAh, const __nv_bfloat16* sAl,
        const __nv_bfloat16* sBh, const __nv_bfloat16* sBl,
        int pitch, int wm, int wn, int nNi2, int lane, float acc[][8][4])
{
    const int lrA = lane & 15;
    const int lcA = (lane >> 4) << 3;
    const int lrB = ((lane >> 4) << 3) | (lane & 7);
    const int lcB = lane & 8;

#pragma unroll
    for (int ks = 0; ks < 2; ks++) {
        const int ko = ks * 16;
        uint32_t ah[2][4], al[2][4];
#pragma unroll
        for (int mi = 0; mi < 2; mi++) {
            ldsm4(ah[mi], &sAh[(wm + mi * 16 + lrA) * pitch + ko + lcA]);
            ldsm4(al[mi], &sAl[(wm + mi * 16 + lrA) * pitch + ko + lcA]);
        }
#pragma unroll
        for (int ni2 = 0; ni2 < 4; ni2++) {
            if (ni2 >= nNi2) break;
            uint32_t bh4[4], bl4[4];
            ldsm4(bh4, &sBh[(wn + ni2 * 16 + lrB) * pitch + ko + lcB]);
            ldsm4(bl4, &sBl[(wn + ni2 * 16 + lrB) * pitch + ko + lcB]);
#pragma unroll
            for (int mi = 0; mi < 2; mi++) {
                mma16816(acc[mi][2*ni2    ], ah[mi], bh4[0], bh4[1]);
                mma16816(acc[mi][2*ni2    ], ah[mi], bl4[0], bl4[1]);
                mma16816(acc[mi][2*ni2    ], al[mi], bh4[0], bh4[1]);
                mma16816(acc[mi][2*ni2 + 1], ah[mi], bh4[2], bh4[3]);
                mma16816(acc[mi][2*ni2 + 1], ah[mi], bl4[2], bl4[3]);
                mma16816(acc[mi][2*ni2 + 1], al[mi], bh4[2], bh4[3]);
            }
        }
    }
}

/* ---------------- K1/K5: big GEMMs, cp.async + LDSM ---------------- */
__global__ __launch_bounds__(256, 2) void hmma_gemm(int mode,
        const float* __restrict__ bias, float* __restrict__ outp)
{
    extern __shared__ __align__(16) char dynsm[];
    const uint32_t sb = (uint32_t)__cvta_generic_to_shared(dynsm);

    const int t    = threadIdx.x;
    const int wid  = t >> 5, lane = t & 31;
    const int gq   = lane >> 2, tig = lane & 3;
    const int wm   = (wid & 3) * 32;
    const int wn   = (wid >> 2) * 64;
    const int m0   = blockIdx.y * MT;
    const int n0   = blockIdx.x * NT;

    const __nv_bfloat16 *Ah, *Al, *Bh, *Bl;
    int brmax;
    if (mode == 0) { Ah = g_xh;  Al = g_xl;  Bh = g_wqh; Bl = g_wql; brmax = 3*CDIM - 1; }
    else           { Ah = g_cth; Al = g_ctl; Bh = g_wph; Bl = g_wpl; brmax = CDIM - 1;   }

    float acc[2][8][4];
#pragma unroll
    for (int mi = 0; mi < 2; mi++)
#pragma unroll
        for (int ni = 0; ni < 8; ni++)
#pragma unroll
            for (int r = 0; r < 4; r++) acc[mi][ni][r] = 0.f;

    stage_async(sb + 0*TILEB, Ah, m0, TOK - 1, 0, t);
    stage_async(sb + 1*TILEB, Al, m0, TOK - 1, 0, t);
    stage_async(sb + 2*TILEB, Bh, n0, brmax,   0, t);
    stage_async(sb + 3*TILEB, Bl, n0, brmax,   0, t);
    CP_COMMIT();

    const int NP = CDIM / KPAN;
    for (int p = 0; p < NP; p++) {
        if (p + 1 < NP) {
            const uint32_t nb = sb + ((p + 1) & 1) * STAGEB;
            const int kb = (p + 1) * KPAN;
            stage_async(nb + 0*TILEB, Ah, m0, TOK - 1, kb, t);
            stage_async(nb + 1*TILEB, Al, m0, TOK - 1, kb, t);
            stage_async(nb + 2*TILEB, Bh, n0, brmax,   kb, t);
            stage_async(nb + 3*TILEB, Bl, n0, brmax,   kb, t);
            CP_COMMIT();
            CP_WAIT(1);
        } else {
            CP_WAIT(0);
        }
        __syncthreads();

        const char* cbuf = dynsm + (p & 1) * STAGEB;
        panel_mma((const __nv_bfloat16*)(cbuf + 0*TILEB),
                  (const __nv_bfloat16*)(cbuf + 1*TILEB),
                  (const __nv_bfloat16*)(cbuf + 2*TILEB),
                  (const __nv_bfloat16*)(cbuf + 3*TILEB),
                  SPAD, wm, wn, 4, lane, acc);
        __syncthreads();
    }

#pragma unroll
    for (int mi = 0; mi < 2; mi++) {
#pragma unroll
        for (int h2 = 0; h2 < 2; h2++) {
            const int m = m0 + wm + mi * 16 + gq + h2 * 8;
            if (m >= TOK) continue;
#pragma unroll
            for (int ni = 0; ni < 8; ni++) {
                const int col = n0 + wn + ni * 8 + 2 * tig;
                const float v0 = acc[mi][ni][h2 * 2 + 0];
                const float v1 = acc[mi][ni][h2 * 2 + 1];
                if (mode == 1) {
                    float2 o = make_float2(v0 + bias[col], v1 + bias[col + 1]);
                    *reinterpret_cast<float2*>(&outp[(size_t)m * CDIM + col]) = o;
                } else {
                    const int s  = col / CDIM;
                    const int rm = col % CDIM;
                    const int h  = rm / HD, dd = rm % HD;
                    const int bidx = m / SEQ, n = m % SEQ;
                    if (s == 2) {
                        const size_t vo = ((size_t)(bidx * NH + h) * HD + dd) * SEQP + n;
                        g_vt[vo]        = pack_v(v0);
                        g_vt[vo + SEQP] = pack_v(v1);
                    } else {
                        const size_t off = ((size_t)(bidx * NH + h) * SEQ + n) * HD + dd;
                        uint32_t lo, hi = pack_hi_lo(v0, v1, &lo);
                        __nv_bfloat16 *dh = (s == 0) ? g_qh : g_kh;
                        __nv_bfloat16 *dl = (s == 0) ? g_ql : g_kl;
                        *reinterpret_cast<uint32_t*>(&dh[off]) = hi;
                        *reinterpret_cast<uint32_t*>(&dl[off]) = lo;
                    }
                }
            }
        }
    }
}

/* ---------------- fused scores + softmax + PV ----------------------
   block = (bh, 64-row Q tile). smem 210,944 B:
     [0, 59392)          S fp32 [64][232] (alias: P hi/lo bf16 [64][232])
     [59392, 77824)      Q hi/lo [64][72]
     [77824, 151552)     K hi/lo [256][72]
     [151552, 210944)    V^T hi/lo [64][232]                            */
#define FPITCH 232
#define QPITCH 72
#define SP_OFF 0
#define Q_OFF  59392
#define K_OFF  77824
#define V_OFF  151552
#define FSMEM  210944

__global__ __launch_bounds__(256, 1) void fused_attn()
{
    extern __shared__ __align__(16) char fsm[];
    float*         S  = (float*)(fsm + SP_OFF);
    __nv_bfloat16* Ph = (__nv_bfloat16*)(fsm + SP_OFF);
    __nv_bfloat16* Pl = (__nv_bfloat16*)(fsm + SP_OFF + 64*FPITCH*2);
    __nv_bfloat16* Qh = (__nv_bfloat16*)(fsm + Q_OFF);
    __nv_bfloat16* Ql = Qh + 64*QPITCH;
    __nv_bfloat16* Kh = (__nv_bfloat16*)(fsm + K_OFF);
    __nv_bfloat16* Kl = Kh + 256*QPITCH;
    __nv_bfloat16* Vh = (__nv_bfloat16*)(fsm + V_OFF);
    __nv_bfloat16* Vl = Vh + 64*FPITCH;

    const int bh   = blockIdx.x;
    const int b    = bh / NH, h = bh % NH;
    const int q0   = blockIdx.y * 64;
    const int t    = threadIdx.x;
    const int lane = t & 31;
    const int w    = t >> 5;
    const int gq   = lane >> 2, tig = lane & 3;
    const int lrA  = lane & 15;
    const int lcA  = (lane >> 4) << 3;
    const int lrB  = ((lane >> 4) << 3) | (lane & 7);
    const int lcB  = lane & 8;

    const size_t base = (size_t)bh * SEQ * HD;

    /* stage Q (64 rows x 64 cols, pitch QPITCH) */
#pragma unroll
    for (int i = 0; i < 2; i++) {
        const int idx = t + i * 256;
        const int row = idx >> 3;
        const int c8  = (idx & 7) * 8;
        int gr = q0 + row; if (gr > SEQ - 1) gr = SEQ - 1;
        *reinterpret_cast<uint4*>(&Qh[row * QPITCH + c8]) =
            *reinterpret_cast<const uint4*>(&g_qh[base + (size_t)gr * HD + c8]);
        *reinterpret_cast<uint4*>(&Ql[row * QPITCH + c8]) =
            *reinterpret_cast<const uint4*>(&g_ql[base + (size_t)gr * HD + c8]);
    }
    /* stage K (256 rows x 64 cols, pitch QPITCH) */
#pragma unroll
    for (int i = 0; i < 8; i++) {
        const int idx = t + i * 256;
        const int row = idx >> 3;
        const int c8  = (idx & 7) * 8;
        int gr = row; if (gr > SEQ - 1) gr = SEQ - 1;
        *reinterpret_cast<uint4*>(&Kh[row * QPITCH + c8]) =
            *reinterpret_cast<const uint4*>(&g_kh[base + (size_t)gr * HD + c8]);
        *reinterpret_cast<uint4*>(&Kl[row * QPITCH + c8]) =
            *reinterpret_cast<const uint4*>(&g_kl[base + (size_t)gr * HD + c8]);
    }
    /* stage V^T (unpack hi/lo; zero pad to FPITCH) */
    const uint32_t* vt = g_vt + (size_t)bh * HD * SEQP;
#pragma unroll
    for (int dd = 0; dd < 8; dd++) {
        const int d = w * 8 + dd;
#pragma unroll
        for (int i = 0; i < 8; i++) {
            const int n = lane + i * 32;
            if (n < FPITCH) {
                uint32_t p = (n < SEQP) ? vt[d * SEQP + n] : 0u;
                Vh[d * FPITCH + n] = __ushort_as_bfloat16((unsigned short)(p & 0xffffu));
                Vl[d * FPITCH + n] = __ushort_as_bfloat16((unsigned short)(p >> 16));
            }
        }
    }
    __syncthreads();

    /* phase 1: S = Q K^T (3-pass HMMA), warps 2x4, cols 256 computed,
       cols < FPITCH stored */
    {
        const int wm = (w & 1) * 32;
        const int wn = (w >> 1) * 64;
        float sacc[2][8][4];
#pragma unroll
        for (int mi = 0; mi < 2; mi++)
#pragma unroll
            for (int ni = 0; ni < 8; ni++)
#pragma unroll
                for (int r = 0; r < 4; r++) sacc[mi][ni][r] = 0.f;

#pragma unroll
        for (int ks = 0; ks < 4; ks++) {
            const int ko = ks * 16;
            uint32_t ah[2][4], al[2][4];
#pragma unroll
            for (int mi = 0; mi < 2; mi++) {
                ldsm4(ah[mi], &Qh[(wm + mi * 16 + lrA) * QPITCH + ko + lcA]);
                ldsm4(al[mi], &Ql[(wm + mi * 16 + lrA) * QPITCH + ko + lcA]);
            }
#pragma unroll
            for (int ni2 = 0; ni2 < 4; ni2++) {
                uint32_t bh4[4], bl4[4];
                ldsm4(bh4, &Kh[(wn + ni2 * 16 + lrB) * QPITCH + ko + lcB]);
                ldsm4(bl4, &Kl[(wn + ni2 * 16 + lrB) * QPITCH + ko + lcB]);
#pragma unroll
                for (int mi = 0; mi < 2; mi++) {
                    mma16816(sacc[mi][2*ni2    ], ah[mi], bh4[0], bh4[1]);
                    mma16816(sacc[mi][2*ni2    ], ah[mi], bl4[0], bl4[1]);
                    mma16816(sacc[mi][2*ni2    ], al[mi], bh4[0], bh4[1]);
                    mma16816(sacc[mi][2*ni2 + 1], ah[mi], bh4[2], bh4[3]);
                    mma16816(sacc[mi][2*ni2 + 1], ah[mi], bl4[2], bl4[3]);
                    mma16816(sacc[mi][2*ni2 + 1], al[mi], bh4[2], bh4[3]);
                }
            }
        }
#pragma unroll
        for (int mi = 0; mi < 2; mi++)
#pragma unroll
            for (int h2 = 0; h2 < 2; h2++) {
                const int row = wm + mi * 16 + gq + h2 * 8;
#pragma unroll
                for (int ni = 0; ni < 8; ni++) {
                    const int col = wn + ni * 8 + 2 * tig;
                    if (col + 1 < FPITCH) {
                        S[row * FPITCH + col]     = sacc[mi][ni][h2*2+0] * SCALEF;
                        S[row * FPITCH + col + 1] = sacc[mi][ni][h2*2+1] * SCALEF;
                    }
                }
            }
    }
    __syncthreads();

    /* phase 2: softmax. warp w owns rows w*8..w*8+7; read-all -> sync -> write P */
    float pv[8][8];
#pragma unroll
    for (int r8 = 0; r8 < 8; r8++) {
        const int sr = w * 8 + r8;
        float mx = -1e30f;
#pragma unroll
        for (int i = 0; i < 8; i++) {
            const int c = lane + i * 32;
            float v = (c < SEQ) ? S[sr * FPITCH + c] : -1e30f;
            pv[r8][i] = v;
            mx = fmaxf(mx, v);
        }
#pragma unroll
        for (int off = 16; off > 0; off >>= 1)
            mx = fmaxf(mx, __shfl_xor_sync(0xffffffffu, mx, off));
        float s = 0.f;
#pragma unroll
        for (int i = 0; i < 8; i++) {
            const int c = lane + i * 32;
            const float e = (c < SEQ) ? __expf(pv[r8][i] - mx) : 0.f;
            pv[r8][i] = e;
            s += e;
        }
#pragma unroll
        for (int off = 16; off > 0; off >>= 1)
            s += __shfl_xor_sync(0xffffffffu, s, off);
        const float inv = 1.f / s;
#pragma unroll
        for (int i = 0; i < 8; i++) pv[r8][i] *= inv;
    }
    __syncthreads();   /* all S reads complete before P overwrites the region */
#pragma unroll
    for (int r8 = 0; r8 < 8; r8++) {
        const int sr = w * 8 + r8;
#pragma unroll
        for (int i = 0; i < 8; i++) {
            const int c = lane + i * 32;
            if (c < FPITCH) {
                const float p = pv[r8][i];
                __nv_bfloat16 ph = __float2bfloat16(p);
                __nv_bfloat16 pl = __float2bfloat16(p - __bfloat162float(ph));
                Ph[sr * FPITCH + c] = ph;
                Pl[sr * FPITCH + c] = pl;
            }
        }
    }
    __syncthreads();

    /* phase 3: ctx = P @ V, 13 k16 steps (P cols >= 208 are zero/unread) */
    {
        const int wm = (w & 1) * 32;
        const int wn = (w >> 1) * 16;
        float acc[2][2][4];
#pragma unroll
        for (int mi = 0; mi < 2; mi++)
#pragma unroll
            for (int ni = 0; ni < 2; ni++)
#pragma unroll
                for (int r = 0; r < 4; r++) acc[mi][ni][r] = 0.f;

#pragma unroll 1
        for (int ks = 0; ks < 13; ks++) {
            const int ko = ks * 16;
            uint32_t ah[2][4], al[2][4];
#pragma unroll
            for (int mi = 0; mi < 2; mi++) {
                ldsm4(ah[mi], &Ph[(wm + mi * 16 + lrA) * FPITCH + ko + lcA]);
                ldsm4(al[mi], &Pl[(wm + mi * 16 + lrA) * FPITCH + ko + lcA]);
            }
            uint32_t bh4[4], bl4[4];
            ldsm4(bh4, &Vh[(wn + lrB) * FPITCH + ko + lcB]);
            ldsm4(bl4, &Vl[(wn + lrB) * FPITCH + ko + lcB]);
#pragma unroll
            for (int mi = 0; mi < 2; mi++) {
                mma16816(acc[mi][0], ah[mi], bh4[0], bh4[1]);
                mma16816(acc[mi][0], ah[mi], bl4[0], bl4[1]);
                mma16816(acc[mi][0], al[mi], bh4[0], bh4[1]);
                mma16816(acc[mi][1], ah[mi], bh4[2], bh4[3]);
                mma16816(acc[mi][1], ah[mi], bl4[2], bl4[3]);
                mma16816(acc[mi][1], al[mi], bh4[2], bh4[3]);
            }
        }

#pragma unroll
        for (int mi = 0; mi < 2; mi++)
#pragma unroll
            for (int h2 = 0; h2 < 2; h2++) {
                const int r = q0 + wm + mi * 16 + gq + h2 * 8;
                if (r >= SEQ) continue;
#pragma unroll
                for (int ni = 0; ni < 2; ni++) {
                    const int col = wn + ni * 8 + 2 * tig;
                    const size_t off = (size_t)(b * SEQ + r) * CDIM + h * HD + col;
                    uint32_t lo, hi = pack_hi_lo(acc[mi][ni][h2*2+0], acc[mi][ni][h2*2+1], &lo);
                    *reinterpret_cast<uint32_t*>(&g_cth[off]) = hi;
                    *reinterpret_cast<uint32_t*>(&g_ctl[off]) = lo;
                }
            }
    }
}

/* ---------------- top-k stages (exact fp32) ------------------------ */
__global__ __launch_bounds__(256) void topk_qc(const float* __restrict__ x,
                                               const float* __restrict__ w)
{
    __shared__ float xc[CDIM];
    const int b  = blockIdx.x;
    const int jt = blockIdx.y;
    const int t  = threadIdx.x;
    const int lane = t & 31, wrp = t >> 5;

    for (int i = t; i < CDIM; i += 256) xc[i] = x[(size_t)(b * SEQ) * CDIM + i];
    __syncthreads();

#pragma unroll
    for (int jj = 0; jj < 8; jj++) {
        const int j = jt * 64 + wrp * 8 + jj;
        const float* wr = w + (size_t)j * CDIM;
        float s = 0.f;
#pragma unroll
        for (int c4 = 0; c4 < 6; c4++) {
            const int c = (c4 * 32 + lane) * 4;
            const float4 wv = *reinterpret_cast<const float4*>(&wr[c]);
            s += wv.x * xc[c] + wv.y * xc[c+1] + wv.z * xc[c+2] + wv.w * xc[c+3];
        }
#pragma unroll
        for (int off = 16; off > 0; off >>= 1)
            s += __shfl_xor_sync(0xffffffffu, s, off);
        if (lane == 0) g_qc[b * CDIM + j] = s;
    }
}

__global__ __launch_bounds__(256) void topk_u(const float* __restrict__ w)
{
    __shared__ float qh[HD];
    const int b = blockIdx.x, h = blockIdx.y;
    const int t = threadIdx.x;
    if (t < HD) qh[t] = g_qc[b * CDIM + h * HD + t];
    __syncthreads();

    const float* wk = w + (size_t)(CDIM + h * HD) * CDIM;
#pragma unroll
    for (int cc = 0; cc < 3; cc++) {
        const int c = cc * 256 + t;
        float s = 0.f;
#pragma unroll 16
        for (int d = 0; d < HD; d++) s += wk[(size_t)d * CDIM + c] * qh[d];
        g_u[((size_t)b * NH + h) * CDIM + c] = s;
    }
}

__global__ __launch_bounds__(256) void topk_wt(const float* __restrict__ x)
{
    const int b = blockIdx.x;
    const int t = threadIdx.x;
    const int lane = t & 31, wrp = t >> 5;
    const int m = blockIdx.y * 8 + wrp;
    if (m >= SEQ) return;

    const float* xr = x + (size_t)(b * SEQ + m) * CDIM;
    float4 xv[6];
#pragma unroll
    for (int c4 = 0; c4 < 6; c4++)
        xv[c4] = *reinterpret_cast<const float4*>(&xr[(c4 * 32 + lane) * 4]);

    const float* ub = g_u + (size_t)b * NH * CDIM;
    float tot = 0.f;
#pragma unroll
    for (int h = 0; h < NH; h++) {
        const float* ur = ub + h * CDIM;
        float s = 0.f;
#pragma unroll
        for (int c4 = 0; c4 < 6; c4++) {
            const int c = (c4 * 32 + lane) * 4;
            const float4 uv = *reinterpret_cast<const float4*>(&ur[c]);
            s += uv.x * xv[c4].x + uv.y * xv[c4].y + uv.z * xv[c4].z + uv.w * xv[c4].w;
        }
#pragma unroll
        for (int off = 16; off > 0; off >>= 1)
            s += __shfl_xor_sync(0xffffffffu, s, off);
        tot += fabsf(s);
    }
    if (lane == 0) g_wt[b * SEQ + m] = tot;
}

__global__ __launch_bounds__(256) void topk_emit(float* __restrict__ out_keep,
                                                 int write_keep)
{
    __shared__ float wt[SEQ];
    __shared__ unsigned char keep[SEQ];
    const int b = blockIdx.x, t = threadIdx.x;

    if (t < SEQ) wt[t] = g_wt[b * SEQ + t];
    __syncthreads();
    if (t < SEQ) {
        const float wi = wt[t];
        int cnt = 0;
        for (int j = 0; j < SEQ; j++) {
            const float wj = wt[j];
            cnt += (wj > wi) || (wj == wi && j < t);
        }
        keep[t] = (cnt < KEEP) ? 1 : 0;
    }
    __syncthreads();
    if (write_keep && t < SEQ && keep[t]) {
        int pos = 0;
        for (int j = 0; j < t; j++) pos += keep[j];
        out_keep[b * KEEP + pos] = (float)t;
    }
}

/* ------------------------------------------------------------------ */
extern "C" void kernel_launch(void* const* d_in, const int* in_sizes, int n_in,
                              void* d_out, int out_size)
{
    const float* x      = (const float*)d_in[0];
    const float* qkv_w  = (const float*)d_in[1];
    const float* proj_w = (const float*)d_in[2];
    const float* proj_b = (const float*)d_in[3];
    float* out = (float*)d_out;

    const int gemm_smem = 2 * STAGEB;
    cudaFuncSetAttribute(hmma_gemm,  cudaFuncAttributeMaxDynamicSharedMemorySize, gemm_smem);
    cudaFuncSetAttribute(fused_attn, cudaFuncAttributeMaxDynamicSharedMemorySize, FSMEM);

    static cudaStream_t s2 = nullptr;
    static cudaEvent_t evFork = nullptr, evJoin = nullptr;
    if (s2 == nullptr) {
        cudaStreamCreateWithFlags(&s2, cudaStreamNonBlocking);
        cudaEventCreateWithFlags(&evFork, cudaEventDisableTiming);
        cudaEventCreateWithFlags(&evJoin, cudaEventDisableTiming);
    }

    const int write_keep = (out_size >= TOK * CDIM + BSZ * KEEP) ? 1 : 0;

    /* fork: exact fp32 top-k chain (reads only raw inputs) */
    cudaEventRecord(evFork, 0);
    cudaStreamWaitEvent(s2, evFork, 0);
    topk_qc  <<<dim3(BSZ, 12), 256, 0, s2>>>(x, qkv_w);
    topk_u   <<<dim3(BSZ, NH), 256, 0, s2>>>(qkv_w);
    topk_wt  <<<dim3(BSZ, (SEQ + 7) / 8), 256, 0, s2>>>(x);
    topk_emit<<<BSZ, 256, 0, s2>>>(out + (size_t)TOK * CDIM, write_keep);
    cudaEventRecord(evJoin, s2);

    /* main pipeline */
    split_all_kernel<<<(NSPLIT + 255)/256, 256>>>(x, qkv_w, proj_w);

    hmma_gemm<<<dim3(3*CDIM/NT, (TOK + MT - 1)/MT), 256, gemm_smem>>>(0, nullptr, nullptr);

    fused_attn<<<dim3(BH, 4), 256, FSMEM>>>();

    hmma_gemm<<<dim3(CDIM/NT, (TOK + MT - 1)/MT), 256, gemm_smem>>>(1, proj_b, out);

    cudaStreamWaitEvent(0, evJoin, 0);
}

// round 14
// speedup vs baseline: 3.7218x; 1.0952x over previous
#include <cuda_runtime.h>
#include <cuda_bf16.h>
#include <math.h>
#include <stdint.h>

#define BSZ   64
#define SEQ   197
#define CDIM  768
#define NH    12
#define HD    64
#define KEEP  160
#define SCALEF 0.125f

#define BH   (BSZ*NH)
#define TOK  (BSZ*SEQ)

#define SEQP   228   /* global V^T pitch (u32 elems) */

/* ---------------- scratch (device globals; no allocs allowed) ------ */
__device__ __nv_bfloat16 g_qh[BH*SEQ*HD], g_ql[BH*SEQ*HD];
__device__ __nv_bfloat16 g_kh[BH*SEQ*HD], g_kl[BH*SEQ*HD];
__device__ uint32_t      g_vt[BH*HD*SEQP];

__device__ __nv_bfloat16 g_xh[TOK*CDIM],  g_xl[TOK*CDIM];
__device__ __nv_bfloat16 g_wqh[3*CDIM*CDIM], g_wql[3*CDIM*CDIM];
__device__ __nv_bfloat16 g_wph[CDIM*CDIM],   g_wpl[CDIM*CDIM];
__device__ __nv_bfloat16 g_cth[TOK*CDIM], g_ctl[TOK*CDIM];

/* top-k staging */
__device__ float g_qc[BSZ*CDIM];
__device__ float g_u [BSZ*NH*CDIM];
__device__ float g_wt[BSZ*SEQ];

/* ---------------- helpers ------------------------------------------ */
__device__ __forceinline__ uint32_t pack_hi_lo(float v0, float v1, uint32_t* lo)
{
    __nv_bfloat16 h0 = __float2bfloat16(v0);
    __nv_bfloat16 h1 = __float2bfloat16(v1);
    __nv_bfloat16 l0 = __float2bfloat16(v0 - __bfloat162float(h0));
    __nv_bfloat16 l1 = __float2bfloat16(v1 - __bfloat162float(h1));
    uint32_t hi = ((uint32_t)__bfloat16_as_ushort(h1) << 16) | __bfloat16_as_ushort(h0);
    *lo         = ((uint32_t)__bfloat16_as_ushort(l1) << 16) | __bfloat16_as_ushort(l0);
    return hi;
}
__device__ __forceinline__ uint32_t pack_v(float v)
{
    __nv_bfloat16 h = __float2bfloat16(v);
    __nv_bfloat16 l = __float2bfloat16(v - __bfloat162float(h));
    return (uint32_t)__bfloat16_as_ushort(h) | ((uint32_t)__bfloat16_as_ushort(l) << 16);
}

#define CP_ASYNC16(dst, src) \
    asm volatile("cp.async.cg.shared.global [%0], [%1], 16;" :: "r"(dst), "l"(src))
#define CP_COMMIT() asm volatile("cp.async.commit_group;" ::: "memory")
#define CP_WAIT(n)  asm volatile("cp.async.wait_group %0;" :: "n"(n) : "memory")

__device__ __forceinline__ void ldsm4(uint32_t* r, const void* p)
{
    uint32_t a = (uint32_t)__cvta_generic_to_shared(p);
    asm volatile("ldmatrix.sync.aligned.m8n8.x4.shared.b16 {%0,%1,%2,%3}, [%4];"
                 : "=r"(r[0]), "=r"(r[1]), "=r"(r[2]), "=r"(r[3]) : "r"(a));
}

/* ---------------- merged split fp32 -> bf16 hi/lo ------------------ */
#define NX  (TOK*CDIM)
#define NWQ (3*CDIM*CDIM)
#define NWP (CDIM*CDIM)
#define NSPLIT (NX + NWQ + NWP)

__global__ void split_all_kernel(const float* __restrict__ x,
                                 const float* __restrict__ wq,
                                 const float* __restrict__ wp)
{
    int i = blockIdx.x * 256 + threadIdx.x;
    if (i >= NSPLIT) return;
    const float* s;
    __nv_bfloat16 *hi, *lo;
    int j;
    if (i < NX)            { s = x;  hi = g_xh;  lo = g_xl;  j = i; }
    else if (i < NX + NWQ) { s = wq; hi = g_wqh; lo = g_wql; j = i - NX; }
    else                   { s = wp; hi = g_wph; lo = g_wpl; j = i - NX - NWQ; }
    float v = s[j];
    __nv_bfloat16 h = __float2bfloat16(v);
    hi[j] = h;
    lo[j] = __float2bfloat16(v - __bfloat162float(h));
}

/* ---------------- HMMA primitives ---------------------------------- */
#define MT 128
#define NT 128
#define KPAN 32
#define SPAD 40
#define TILEB (128*SPAD*2)
#define STAGEB (4*TILEB)

__device__ __forceinline__ void mma16816(float* c, const uint32_t* a,
                                         uint32_t b0, uint32_t b1)
{
    asm volatile(
        "mma.sync.aligned.m16n8k16.row.col.f32.bf16.bf16.f32 "
        "{%0,%1,%2,%3}, {%4,%5,%6,%7}, {%8,%9}, {%0,%1,%2,%3};"
        : "+f"(c[0]), "+f"(c[1]), "+f"(c[2]), "+f"(c[3])
        : "r"(a[0]), "r"(a[1]), "r"(a[2]), "r"(a[3]), "r"(b0), "r"(b1));
}

__device__ __forceinline__ void stage_async(uint32_t sbase,
        const __nv_bfloat16* __restrict__ g, int row0, int rowmax, int kb, int t)
{
#pragma unroll
    for (int i = 0; i < 2; i++) {
        const int idx = t + i * 256;
        const int row = idx >> 2;
        const int c8  = (idx & 3) * 8;
        int gr = row0 + row; if (gr > rowmax) gr = rowmax;
        CP_ASYNC16(sbase + (uint32_t)(row * SPAD + c8) * 2,
                   g + (size_t)gr * CDIM + kb + c8);
    }
}

/* 3-pass split-bf16 MMA over one staged panel via LDSM. */
__device__ __forceinline__ void panel_mma(
        const __nv_bfloat16* sAh, const __nv_bfloat16* sAl,
        const __nv_bfloat16* sBh, const __nv_bfloat16* sBl,
        int pitch, int wm, int wn, int nNi2, int lane, float acc[][8][4])
{
    const int lrA = lane & 15;
    const int lcA = (lane >> 4) << 3;
    const int lrB = ((lane >> 4) << 3) | (lane & 7);
    const int lcB = lane & 8;

#pragma unroll
    for (int ks = 0; ks < 2; ks++) {
        const int ko = ks * 16;
        uint32_t ah[2][4], al[2][4];
#pragma unroll
        for (int mi = 0; mi < 2; mi++) {
            ldsm4(ah[mi], &sAh[(wm + mi * 16 + lrA) * pitch + ko + lcA]);
            ldsm4(al[mi], &sAl[(wm + mi * 16 + lrA) * pitch + ko + lcA]);
        }
#pragma unroll
        for (int ni2 = 0; ni2 < 4; ni2++) {
            if (ni2 >= nNi2) break;
            uint32_t bh4[4], bl4[4];
            ldsm4(bh4, &sBh[(wn + ni2 * 16 + lrB) * pitch + ko + lcB]);
            ldsm4(bl4, &sBl[(wn + ni2 * 16 + lrB) * pitch + ko + lcB]);
#pragma unroll
            for (int mi = 0; mi < 2; mi++) {
                mma16816(acc[mi][2*ni2    ], ah[mi], bh4[0], bh4[1]);
                mma16816(acc[mi][2*ni2    ], ah[mi], bl4[0], bl4[1]);
                mma16816(acc[mi][2*ni2    ], al[mi], bh4[0], bh4[1]);
                mma16816(acc[mi][2*ni2 + 1], ah[mi], bh4[2], bh4[3]);
                mma16816(acc[mi][2*ni2 + 1], ah[mi], bl4[2], bl4[3]);
                mma16816(acc[mi][2*ni2 + 1], al[mi], bh4[2], bh4[3]);
            }
        }
    }
}

/* ---------------- K1/K5: big GEMMs, cp.async + LDSM ---------------- */
__global__ __launch_bounds__(256, 2) void hmma_gemm(int mode,
        const float* __restrict__ bias, float* __restrict__ outp)
{
    extern __shared__ __align__(16) char dynsm[];
    const uint32_t sb = (uint32_t)__cvta_generic_to_shared(dynsm);

    const int t    = threadIdx.x;
    const int wid  = t >> 5, lane = t & 31;
    const int gq   = lane >> 2, tig = lane & 3;
    const int wm   = (wid & 3) * 32;
    const int wn   = (wid >> 2) * 64;
    const int m0   = blockIdx.y * MT;
    const int n0   = blockIdx.x * NT;

    const __nv_bfloat16 *Ah, *Al, *Bh, *Bl;
    int brmax;
    if (mode == 0) { Ah = g_xh;  Al = g_xl;  Bh = g_wqh; Bl = g_wql; brmax = 3*CDIM - 1; }
    else           { Ah = g_cth; Al = g_ctl; Bh = g_wph; Bl = g_wpl; brmax = CDIM - 1;   }

    float acc[2][8][4];
#pragma unroll
    for (int mi = 0; mi < 2; mi++)
#pragma unroll
        for (int ni = 0; ni < 8; ni++)
#pragma unroll
            for (int r = 0; r < 4; r++) acc[mi][ni][r] = 0.f;

    stage_async(sb + 0*TILEB, Ah, m0, TOK - 1, 0, t);
    stage_async(sb + 1*TILEB, Al, m0, TOK - 1, 0, t);
    stage_async(sb + 2*TILEB, Bh, n0, brmax,   0, t);
    stage_async(sb + 3*TILEB, Bl, n0, brmax,   0, t);
    CP_COMMIT();

    const int NP = CDIM / KPAN;
    for (int p = 0; p < NP; p++) {
        if (p + 1 < NP) {
            const uint32_t nb = sb + ((p + 1) & 1) * STAGEB;
            const int kb = (p + 1) * KPAN;
            stage_async(nb + 0*TILEB, Ah, m0, TOK - 1, kb, t);
            stage_async(nb + 1*TILEB, Al, m0, TOK - 1, kb, t);
            stage_async(nb + 2*TILEB, Bh, n0, brmax,   kb, t);
            stage_async(nb + 3*TILEB, Bl, n0, brmax,   kb, t);
            CP_COMMIT();
            CP_WAIT(1);
        } else {
            CP_WAIT(0);
        }
        __syncthreads();

        const char* cbuf = dynsm + (p & 1) * STAGEB;
        panel_mma((const __nv_bfloat16*)(cbuf + 0*TILEB),
                  (const __nv_bfloat16*)(cbuf + 1*TILEB),
                  (const __nv_bfloat16*)(cbuf + 2*TILEB),
                  (const __nv_bfloat16*)(cbuf + 3*TILEB),
                  SPAD, wm, wn, 4, lane, acc);
        __syncthreads();
    }

#pragma unroll
    for (int mi = 0; mi < 2; mi++) {
#pragma unroll
        for (int h2 = 0; h2 < 2; h2++) {
            const int m = m0 + wm + mi * 16 + gq + h2 * 8;
            if (m >= TOK) continue;
#pragma unroll
            for (int ni = 0; ni < 8; ni++) {
                const int col = n0 + wn + ni * 8 + 2 * tig;
                const float v0 = acc[mi][ni][h2 * 2 + 0];
                const float v1 = acc[mi][ni][h2 * 2 + 1];
                if (mode == 1) {
                    float2 o = make_float2(v0 + bias[col], v1 + bias[col + 1]);
                    *reinterpret_cast<float2*>(&outp[(size_t)m * CDIM + col]) = o;
                } else {
                    const int s  = col / CDIM;
                    const int rm = col % CDIM;
                    const int h  = rm / HD, dd = rm % HD;
                    const int bidx = m / SEQ, n = m % SEQ;
                    if (s == 2) {
                        const size_t vo = ((size_t)(bidx * NH + h) * HD + dd) * SEQP + n;
                        g_vt[vo]        = pack_v(v0);
                        g_vt[vo + SEQP] = pack_v(v1);
                    } else {
                        const size_t off = ((size_t)(bidx * NH + h) * SEQ + n) * HD + dd;
                        uint32_t lo, hi = pack_hi_lo(v0, v1, &lo);
                        __nv_bfloat16 *dh = (s == 0) ? g_qh : g_kh;
                        __nv_bfloat16 *dl = (s == 0) ? g_ql : g_kl;
                        *reinterpret_cast<uint32_t*>(&dh[off]) = hi;
                        *reinterpret_cast<uint32_t*>(&dl[off]) = lo;
                    }
                }
            }
        }
    }
}

/* ---------------- fused scores + softmax + PV (persistent per bh) --
   block = bh. K/V staged ONCE; loop over 4 Q-tiles of 64 rows.
   smem 210,944 B:
     [0, 59392)          S fp32 [64][232] (alias: P hi/lo bf16 [64][232])
     [59392, 77824)      Q hi/lo [64][72]
     [77824, 151552)     K hi/lo [256][72]
     [151552, 210944)    V^T hi/lo [64][232]                            */
#define FPITCH 232
#define QPITCH 72
#define SP_OFF 0
#define Q_OFF  59392
#define K_OFF  77824
#define V_OFF  151552
#define FSMEM  210944

__global__ __launch_bounds__(256, 1) void fused_attn()
{
    extern __shared__ __align__(16) char fsm[];
    float*         S  = (float*)(fsm + SP_OFF);
    __nv_bfloat16* Ph = (__nv_bfloat16*)(fsm + SP_OFF);
    __nv_bfloat16* Pl = (__nv_bfloat16*)(fsm + SP_OFF + 64*FPITCH*2);
    __nv_bfloat16* Qh = (__nv_bfloat16*)(fsm + Q_OFF);
    __nv_bfloat16* Ql = Qh + 64*QPITCH;
    __nv_bfloat16* Kh = (__nv_bfloat16*)(fsm + K_OFF);
    __nv_bfloat16* Kl = Kh + 256*QPITCH;
    __nv_bfloat16* Vh = (__nv_bfloat16*)(fsm + V_OFF);
    __nv_bfloat16* Vl = Vh + 64*FPITCH;

    const int bh   = blockIdx.x;
    const int b    = bh / NH, h = bh % NH;
    const int t    = threadIdx.x;
    const int lane = t & 31;
    const int w    = t >> 5;
    const int gq   = lane >> 2, tig = lane & 3;
    const int lrA  = lane & 15;
    const int lcA  = (lane >> 4) << 3;
    const int lrB  = ((lane >> 4) << 3) | (lane & 7);
    const int lcB  = lane & 8;

    const size_t base = (size_t)bh * SEQ * HD;

    /* stage K (256 rows x 64 cols, pitch QPITCH) — once */
#pragma unroll
    for (int i = 0; i < 8; i++) {
        const int idx = t + i * 256;
        const int row = idx >> 3;
        const int c8  = (idx & 7) * 8;
        int gr = row; if (gr > SEQ - 1) gr = SEQ - 1;
        *reinterpret_cast<uint4*>(&Kh[row * QPITCH + c8]) =
            *reinterpret_cast<const uint4*>(&g_kh[base + (size_t)gr * HD + c8]);
        *reinterpret_cast<uint4*>(&Kl[row * QPITCH + c8]) =
            *reinterpret_cast<const uint4*>(&g_kl[base + (size_t)gr * HD + c8]);
    }
    /* stage V^T (unpack hi/lo; zero pad to FPITCH) — once */
    const uint32_t* vt = g_vt + (size_t)bh * HD * SEQP;
#pragma unroll
    for (int dd = 0; dd < 8; dd++) {
        const int d = w * 8 + dd;
#pragma unroll
        for (int i = 0; i < 8; i++) {
            const int n = lane + i * 32;
            if (n < FPITCH) {
                uint32_t p = (n < SEQP) ? vt[d * SEQP + n] : 0u;
                Vh[d * FPITCH + n] = __ushort_as_bfloat16((unsigned short)(p & 0xffffu));
                Vl[d * FPITCH + n] = __ushort_as_bfloat16((unsigned short)(p >> 16));
            }
        }
    }

    for (int qt = 0; qt < 4; qt++) {
        const int q0 = qt * 64;

        /* stage Q tile (64 rows x 64 cols) */
#pragma unroll
        for (int i = 0; i < 2; i++) {
            const int idx = t + i * 256;
            const int row = idx >> 3;
            const int c8  = (idx & 7) * 8;
            int gr = q0 + row; if (gr > SEQ - 1) gr = SEQ - 1;
            *reinterpret_cast<uint4*>(&Qh[row * QPITCH + c8]) =
                *reinterpret_cast<const uint4*>(&g_qh[base + (size_t)gr * HD + c8]);
            *reinterpret_cast<uint4*>(&Ql[row * QPITCH + c8]) =
                *reinterpret_cast<const uint4*>(&g_ql[base + (size_t)gr * HD + c8]);
        }
        __syncthreads();   /* K/V (first iter) + Q ready; prev-iter P reads done */

        /* phase 1: S = Q K^T (3-pass HMMA), warps 2x4 */
        {
            const int wm = (w & 1) * 32;
            const int wn = (w >> 1) * 64;
            float sacc[2][8][4];
#pragma unroll
            for (int mi = 0; mi < 2; mi++)
#pragma unroll
                for (int ni = 0; ni < 8; ni++)
#pragma unroll
                    for (int r = 0; r < 4; r++) sacc[mi][ni][r] = 0.f;

#pragma unroll
            for (int ks = 0; ks < 4; ks++) {
                const int ko = ks * 16;
                uint32_t ah[2][4], al[2][4];
#pragma unroll
                for (int mi = 0; mi < 2; mi++) {
                    ldsm4(ah[mi], &Qh[(wm + mi * 16 + lrA) * QPITCH + ko + lcA]);
                    ldsm4(al[mi], &Ql[(wm + mi * 16 + lrA) * QPITCH + ko + lcA]);
                }
#pragma unroll
                for (int ni2 = 0; ni2 < 4; ni2++) {
                    uint32_t bh4[4], bl4[4];
                    ldsm4(bh4, &Kh[(wn + ni2 * 16 + lrB) * QPITCH + ko + lcB]);
                    ldsm4(bl4, &Kl[(wn + ni2 * 16 + lrB) * QPITCH + ko + lcB]);
#pragma unroll
                    for (int mi = 0; mi < 2; mi++) {
                        mma16816(sacc[mi][2*ni2    ], ah[mi], bh4[0], bh4[1]);
                        mma16816(sacc[mi][2*ni2    ], ah[mi], bl4[0], bl4[1]);
                        mma16816(sacc[mi][2*ni2    ], al[mi], bh4[0], bh4[1]);
                        mma16816(sacc[mi][2*ni2 + 1], ah[mi], bh4[2], bh4[3]);
                        mma16816(sacc[mi][2*ni2 + 1], ah[mi], bl4[2], bl4[3]);
                        mma16816(sacc[mi][2*ni2 + 1], al[mi], bh4[2], bh4[3]);
                    }
                }
            }
#pragma unroll
            for (int mi = 0; mi < 2; mi++)
#pragma unroll
                for (int h2 = 0; h2 < 2; h2++) {
                    const int row = wm + mi * 16 + gq + h2 * 8;
#pragma unroll
                    for (int ni = 0; ni < 8; ni++) {
                        const int col = wn + ni * 8 + 2 * tig;
                        if (col + 1 < FPITCH) {
                            S[row * FPITCH + col]     = sacc[mi][ni][h2*2+0] * SCALEF;
                            S[row * FPITCH + col + 1] = sacc[mi][ni][h2*2+1] * SCALEF;
                        }
                    }
                }
        }
        __syncthreads();

        /* phase 2: softmax; read-all -> sync -> write P (S/P alias) */
        float pv[8][8];
#pragma unroll
        for (int r8 = 0; r8 < 8; r8++) {
            const int sr = w * 8 + r8;
            float mx = -1e30f;
#pragma unroll
            for (int i = 0; i < 8; i++) {
                const int c = lane + i * 32;
                float v = (c < SEQ) ? S[sr * FPITCH + c] : -1e30f;
                pv[r8][i] = v;
                mx = fmaxf(mx, v);
            }
#pragma unroll
            for (int off = 16; off > 0; off >>= 1)
                mx = fmaxf(mx, __shfl_xor_sync(0xffffffffu, mx, off));
            float s = 0.f;
#pragma unroll
            for (int i = 0; i < 8; i++) {
                const int c = lane + i * 32;
                const float e = (c < SEQ) ? __expf(pv[r8][i] - mx) : 0.f;
                pv[r8][i] = e;
                s += e;
            }
#pragma unroll
            for (int off = 16; off > 0; off >>= 1)
                s += __shfl_xor_sync(0xffffffffu, s, off);
            const float inv = 1.f / s;
#pragma unroll
            for (int i = 0; i < 8; i++) pv[r8][i] *= inv;
        }
        __syncthreads();
#pragma unroll
        for (int r8 = 0; r8 < 8; r8++) {
            const int sr = w * 8 + r8;
#pragma unroll
            for (int i = 0; i < 8; i++) {
                const int c = lane + i * 32;
                if (c < FPITCH) {
                    const float p = pv[r8][i];
                    __nv_bfloat16 ph = __float2bfloat16(p);
                    __nv_bfloat16 pl = __float2bfloat16(p - __bfloat162float(ph));
                    Ph[sr * FPITCH + c] = ph;
                    Pl[sr * FPITCH + c] = pl;
                }
            }
        }
        __syncthreads();

        /* phase 3: ctx = P @ V, 13 k16 steps */
        {
            const int wm = (w & 1) * 32;
            const int wn = (w >> 1) * 16;
            float acc[2][2][4];
#pragma unroll
            for (int mi = 0; mi < 2; mi++)
#pragma unroll
                for (int ni = 0; ni < 2; ni++)
#pragma unroll
                    for (int r = 0; r < 4; r++) acc[mi][ni][r] = 0.f;

#pragma unroll 1
            for (int ks = 0; ks < 13; ks++) {
                const int ko = ks * 16;
                uint32_t ah[2][4], al[2][4];
#pragma unroll
                for (int mi = 0; mi < 2; mi++) {
                    ldsm4(ah[mi], &Ph[(wm + mi * 16 + lrA) * FPITCH + ko + lcA]);
                    ldsm4(al[mi], &Pl[(wm + mi * 16 + lrA) * FPITCH + ko + lcA]);
                }
                uint32_t bh4[4], bl4[4];
                ldsm4(bh4, &Vh[(wn + lrB) * FPITCH + ko + lcB]);
                ldsm4(bl4, &Vl[(wn + lrB) * FPITCH + ko + lcB]);
#pragma unroll
                for (int mi = 0; mi < 2; mi++) {
                    mma16816(acc[mi][0], ah[mi], bh4[0], bh4[1]);
                    mma16816(acc[mi][0], ah[mi], bl4[0], bl4[1]);
                    mma16816(acc[mi][0], al[mi], bh4[0], bh4[1]);
                    mma16816(acc[mi][1], ah[mi], bh4[2], bh4[3]);
                    mma16816(acc[mi][1], ah[mi], bl4[2], bl4[3]);
                    mma16816(acc[mi][1], al[mi], bh4[2], bh4[3]);
                }
            }

#pragma unroll
            for (int mi = 0; mi < 2; mi++)
#pragma unroll
                for (int h2 = 0; h2 < 2; h2++) {
                    const int r = q0 + wm + mi * 16 + gq + h2 * 8;
                    if (r >= SEQ) continue;
#pragma unroll
                    for (int ni = 0; ni < 2; ni++) {
                        const int col = wn + ni * 8 + 2 * tig;
                        const size_t off = (size_t)(b * SEQ + r) * CDIM + h * HD + col;
                        uint32_t lo, hi = pack_hi_lo(acc[mi][ni][h2*2+0], acc[mi][ni][h2*2+1], &lo);
                        *reinterpret_cast<uint32_t*>(&g_cth[off]) = hi;
                        *reinterpret_cast<uint32_t*>(&g_ctl[off]) = lo;
                    }
                }
        }
        __syncthreads();   /* P reads done before next iter's S writes */
    }
}

/* ---------------- top-k stages (exact fp32) ------------------------ */
__global__ __launch_bounds__(256) void topk_qc(const float* __restrict__ x,
                                               const float* __restrict__ w)
{
    __shared__ float xc[CDIM];
    const int b  = blockIdx.x;
    const int jt = blockIdx.y;
    const int t  = threadIdx.x;
    const int lane = t & 31, wrp = t >> 5;

    for (int i = t; i < CDIM; i += 256) xc[i] = x[(size_t)(b * SEQ) * CDIM + i];
    __syncthreads();

#pragma unroll
    for (int jj = 0; jj < 8; jj++) {
        const int j = jt * 64 + wrp * 8 + jj;
        const float* wr = w + (size_t)j * CDIM;
        float s = 0.f;
#pragma unroll
        for (int c4 = 0; c4 < 6; c4++) {
            const int c = (c4 * 32 + lane) * 4;
            const float4 wv = *reinterpret_cast<const float4*>(&wr[c]);
            s += wv.x * xc[c] + wv.y * xc[c+1] + wv.z * xc[c+2] + wv.w * xc[c+3];
        }
#pragma unroll
        for (int off = 16; off > 0; off >>= 1)
            s += __shfl_xor_sync(0xffffffffu, s, off);
        if (lane == 0) g_qc[b * CDIM + j] = s;
    }
}

__global__ __launch_bounds__(256) void topk_u(const float* __restrict__ w)
{
    __shared__ float qh[HD];
    const int b = blockIdx.x, h = blockIdx.y;
    const int t = threadIdx.x;
    if (t < HD) qh[t] = g_qc[b * CDIM + h * HD + t];
    __syncthreads();

    const float* wk = w + (size_t)(CDIM + h * HD) * CDIM;
#pragma unroll
    for (int cc = 0; cc < 3; cc++) {
        const int c = cc * 256 + t;
        float s = 0.f;
#pragma unroll 16
        for (int d = 0; d < HD; d++) s += wk[(size_t)d * CDIM + c] * qh[d];
        g_u[((size_t)b * NH + h) * CDIM + c] = s;
    }
}

__global__ __launch_bounds__(256) void topk_wt(const float* __restrict__ x)
{
    const int b = blockIdx.x;
    const int t = threadIdx.x;
    const int lane = t & 31, wrp = t >> 5;
    const int m = blockIdx.y * 8 + wrp;
    if (m >= SEQ) return;

    const float* xr = x + (size_t)(b * SEQ + m) * CDIM;
    float4 xv[6];
#pragma unroll
    for (int c4 = 0; c4 < 6; c4++)
        xv[c4] = *reinterpret_cast<const float4*>(&xr[(c4 * 32 + lane) * 4]);

    const float* ub = g_u + (size_t)b * NH * CDIM;
    float tot = 0.f;
#pragma unroll
    for (int h = 0; h < NH; h++) {
        const float* ur = ub + h * CDIM;
        float s = 0.f;
#pragma unroll
        for (int c4 = 0; c4 < 6; c4++) {
            const int c = (c4 * 32 + lane) * 4;
            const float4 uv = *reinterpret_cast<const float4*>(&ur[c]);
            s += uv.x * xv[c4].x + uv.y * xv[c4].y + uv.z * xv[c4].z + uv.w * xv[c4].w;
        }
#pragma unroll
        for (int off = 16; off > 0; off >>= 1)
            s += __shfl_xor_sync(0xffffffffu, s, off);
        tot += fabsf(s);
    }
    if (lane == 0) g_wt[b * SEQ + m] = tot;
}

__global__ __launch_bounds__(256) void topk_emit(float* __restrict__ out_keep,
                                                 int write_keep)
{
    __shared__ float wt[SEQ];
    __shared__ unsigned char keep[SEQ];
    const int b = blockIdx.x, t = threadIdx.x;

    if (t < SEQ) wt[t] = g_wt[b * SEQ + t];
    __syncthreads();
    if (t < SEQ) {
        const float wi = wt[t];
        int cnt = 0;
        for (int j = 0; j < SEQ; j++) {
            const float wj = wt[j];
            cnt += (wj > wi) || (wj == wi && j < t);
        }
        keep[t] = (cnt < KEEP) ? 1 : 0;
    }
    __syncthreads();
    if (write_keep && t < SEQ && keep[t]) {
        int pos = 0;
        for (int j = 0; j < t; j++) pos += keep[j];
        out_keep[b * KEEP + pos] = (float)t;
    }
}

/* ------------------------------------------------------------------ */
extern "C" void kernel_launch(void* const* d_in, const int* in_sizes, int n_in,
                              void* d_out, int out_size)
{
    const float* x      = (const float*)d_in[0];
    const float* qkv_w  = (const float*)d_in[1];
    const float* proj_w = (const float*)d_in[2];
    const float* proj_b = (const float*)d_in[3];
    float* out = (float*)d_out;

    const int gemm_smem = 2 * STAGEB;
    cudaFuncSetAttribute(hmma_gemm,  cudaFuncAttributeMaxDynamicSharedMemorySize, gemm_smem);
    cudaFuncSetAttribute(fused_attn, cudaFuncAttributeMaxDynamicSharedMemorySize, FSMEM);

    static cudaStream_t s2 = nullptr;
    static cudaEvent_t evFork = nullptr, evJoin = nullptr;
    if (s2 == nullptr) {
        cudaStreamCreateWithFlags(&s2, cudaStreamNonBlocking);
        cudaEventCreateWithFlags(&evFork, cudaEventDisableTiming);
        cudaEventCreateWithFlags(&evJoin, cudaEventDisableTiming);
    }

    const int write_keep = (out_size >= TOK * CDIM + BSZ * KEEP) ? 1 : 0;

    /* fork: exact fp32 top-k chain (reads only raw inputs) */
    cudaEventRecord(evFork, 0);
    cudaStreamWaitEvent(s2, evFork, 0);
    topk_qc  <<<dim3(BSZ, 12), 256, 0, s2>>>(x, qkv_w);
    topk_u   <<<dim3(BSZ, NH), 256, 0, s2>>>(qkv_w);
    topk_wt  <<<dim3(BSZ, (SEQ + 7) / 8), 256, 0, s2>>>(x);
    topk_emit<<<BSZ, 256, 0, s2>>>(out + (size_t)TOK * CDIM, write_keep);
    cudaEventRecord(evJoin, s2);

    /* main pipeline */
    split_all_kernel<<<(NSPLIT + 255)/256, 256>>>(x, qkv_w, proj_w);

    hmma_gemm<<<dim3(3*CDIM/NT, (TOK + MT - 1)/MT), 256, gemm_smem>>>(0, nullptr, nullptr);

    fused_attn<<<BH, 256, FSMEM>>>();

    hmma_gemm<<<dim3(CDIM/NT, (TOK + MT - 1)/MT), 256, gemm_smem>>>(1, proj_b, out);

    cudaStreamWaitEvent(0, evJoin, 0);
}